// round 1
// baseline (speedup 1.0000x reference)
#include <cuda_runtime.h>
#include <math.h>

#define NMAX 10000
#define EMAX 160000

// ---------------- scratch (static device allocations; no cudaMalloc) ----------------
__device__ float g_hemtx[EMAX * 64];
__device__ float g_xhat[EMAX * 3];
__device__ float g_w[EMAX * 4];        // celu logits, then exp weights
__device__ float g_coeff[EMAX * 256];
__device__ float g_nodemax[NMAX * 4];
__device__ float g_expsum[NMAX * 4];
__device__ int   g_counts[NMAX];
__device__ int   g_off[NMAX + 1];
__device__ int   g_cursor[NMAX];
__device__ int   g_eid[EMAX];
__device__ float g_he[NMAX * 256];
__device__ float g_cnorm[NMAX * 256];
__device__ float g_dv[NMAX * 3];

__device__ __forceinline__ float siluf(float x) { return x / (1.f + __expf(-x)); }
__device__ __forceinline__ float fast_tanh(float x) {
    float y; asm("tanh.approx.f32 %0, %1;" : "=f"(y) : "f"(x)); return y;
}
__device__ __forceinline__ void atomicMaxF(float* a, float v) {
    if (v >= 0.f) atomicMax((int*)a, __float_as_int(v));
    else          atomicMin((unsigned int*)a, (unsigned int)__float_as_int(v));
}

// ---------------- K0: init accumulators ----------------
__global__ void k_init(int N) {
    int i = blockIdx.x * blockDim.x + threadIdx.x;
    if (i < N * 4) {
        g_nodemax[i] = __int_as_float(0xff800000);  // -inf
        g_expsum[i]  = 0.f;
    }
    if (i < N) g_counts[i] = 0;
}

// ---------------- K1: fused edge MLP ----------------
// per edge: hcat -> h_in -> rbf*_x -> mid -> h_e_mtx -> celu att logits
// writes g_hemtx, g_w (logits), g_xhat; atomics: counts, nodemax
__global__ void k_edge(const float* __restrict__ h, const float* __restrict__ x,
                       const int* __restrict__ idxs,
                       const float* __restrict__ rbf_means, const float* __restrict__ rbf_betas,
                       const float* __restrict__ W_in,  const float* __restrict__ b_in,
                       const float* __restrict__ W_out1, const float* __restrict__ b_out1,
                       const float* __restrict__ W_out2, const float* __restrict__ b_out2,
                       const float* __restrict__ W_att,  const float* __restrict__ b_att,
                       int E)
{
    extern __shared__ float sm[];
    float* sWin  = sm;                    // 128*52 (padded cols)
    float* sBin  = sWin  + 128 * 52;      // 52
    float* sMean = sBin  + 52;            // 52
    float* sBeta = sMean + 52;            // 52
    float* sW1   = sBeta + 52;            // 179*64
    float* sB1   = sW1   + 179 * 64;      // 64
    float* sW2   = sB1   + 64;            // 64*64
    float* sB2   = sW2   + 64 * 64;       // 64
    float* sWa   = sB2   + 64;            // 64*4
    float* sBa   = sWa   + 256;           // 4
    float* sHcat = sBa   + 4;             // 32*132
    float* sX    = sHcat + 32 * 132;      // 32*52
    float* sMid  = sX    + 32 * 52;       // 32*64
    float* sHe   = sMid  + 32 * 64;       // 32*64
    float* sNorm = sHe   + 32 * 64;       // 32
    float* sXh   = sNorm + 32;            // 32*3

    int tid = threadIdx.x;
    for (int i = tid; i < 128 * 52; i += 256) { int r = i / 52, c = i % 52; sWin[i] = (c < 50) ? W_in[r * 50 + c] : 0.f; }
    for (int i = tid; i < 52; i += 256) {
        sBin[i]  = (i < 50) ? b_in[i] : 0.f;
        sMean[i] = (i < 50) ? rbf_means[i] : 0.f;
        sBeta[i] = (i < 50) ? rbf_betas[i] : 0.f;
    }
    for (int i = tid; i < 179 * 64; i += 256) sW1[i] = W_out1[i];
    for (int i = tid; i < 64 * 64;  i += 256) sW2[i] = W_out2[i];
    for (int i = tid; i < 256;      i += 256) sWa[i] = W_att[i];
    if (tid < 64) { sB1[tid] = b_out1[tid]; sB2[tid] = b_out2[tid]; }
    if (tid < 4)  sBa[tid] = b_att[tid];
    __syncthreads();

    int ntiles = (E + 31) / 32;
    for (int tile = blockIdx.x; tile < ntiles; tile += gridDim.x) {
        int e0 = tile * 32;
        int ne = min(32, E - e0);

        if (tid < ne) {
            int s = idxs[2 * (e0 + tid)], d = idxs[2 * (e0 + tid) + 1];
            float dx = x[3 * s]     - x[3 * d];
            float dy = x[3 * s + 1] - x[3 * d + 1];
            float dz = x[3 * s + 2] - x[3 * d + 2];
            float nrm = sqrtf(dx * dx + dy * dy + dz * dz + 1e-14f);
            sNorm[tid] = nrm;
            float inv = 1.f / (nrm + 1e-5f);
            sXh[tid * 3]     = dx * inv;
            sXh[tid * 3 + 1] = dy * inv;
            sXh[tid * 3 + 2] = dz * inv;
            atomicAdd(&g_counts[s], 1);
        }
        for (int i = tid; i < ne * 128; i += 256) {
            int el = i >> 7, c = i & 127;
            int node = idxs[2 * (e0 + el) + (c >> 6)];
            sHcat[el * 132 + c] = h[node * 64 + (c & 63)];
        }
        __syncthreads();

        // G1: h_in = hcat @ W_in + b ; _x = rbf * h_in   (13 col-groups of 4)
        for (int i = tid; i < ne * 13; i += 256) {
            int el = i / 13, j0 = (i % 13) * 4;
            float a0 = sBin[j0], a1 = sBin[j0 + 1], a2 = sBin[j0 + 2], a3 = sBin[j0 + 3];
            const float* hc = &sHcat[el * 132];
            #pragma unroll 4
            for (int c = 0; c < 128; c++) {
                float hv = hc[c];
                float4 w = *(const float4*)&sWin[c * 52 + j0];
                a0 += hv * w.x; a1 += hv * w.y; a2 += hv * w.z; a3 += hv * w.w;
            }
            float nrm = sNorm[el];
            float ex = __expf(-nrm);  // ALPHA=1, CUTOFF_LOWER=0
            float t0 = ex - sMean[j0],     r0 = __expf(-sBeta[j0]     * t0 * t0);
            float t1 = ex - sMean[j0 + 1], r1 = __expf(-sBeta[j0 + 1] * t1 * t1);
            float t2 = ex - sMean[j0 + 2], r2 = __expf(-sBeta[j0 + 2] * t2 * t2);
            float t3 = ex - sMean[j0 + 3], r3 = __expf(-sBeta[j0 + 3] * t3 * t3);
            float* xo = &sX[el * 52 + j0];
            xo[0] = r0 * a0;
            if (j0 + 1 < 50) xo[1] = r1 * a1;
            if (j0 + 2 < 50) xo[2] = r2 * a2;
            if (j0 + 3 < 50) xo[3] = r3 * a3;
        }
        __syncthreads();

        // G2: mid = silu([hcat,_x,norm] @ W_out1 + b)
        for (int i = tid; i < ne * 16; i += 256) {
            int el = i >> 4, j0 = (i & 15) * 4;
            float a0 = sB1[j0], a1 = sB1[j0 + 1], a2 = sB1[j0 + 2], a3 = sB1[j0 + 3];
            const float* hc = &sHcat[el * 132];
            #pragma unroll 4
            for (int c = 0; c < 128; c++) {
                float hv = hc[c];
                float4 w = *(const float4*)&sW1[c * 64 + j0];
                a0 += hv * w.x; a1 += hv * w.y; a2 += hv * w.z; a3 += hv * w.w;
            }
            const float* xv = &sX[el * 52];
            #pragma unroll 2
            for (int c = 0; c < 50; c++) {
                float hv = xv[c];
                float4 w = *(const float4*)&sW1[(128 + c) * 64 + j0];
                a0 += hv * w.x; a1 += hv * w.y; a2 += hv * w.z; a3 += hv * w.w;
            }
            {
                float nv = sNorm[el];
                float4 w = *(const float4*)&sW1[178 * 64 + j0];
                a0 += nv * w.x; a1 += nv * w.y; a2 += nv * w.z; a3 += nv * w.w;
            }
            float* mo = &sMid[el * 64 + j0];
            mo[0] = siluf(a0); mo[1] = siluf(a1); mo[2] = siluf(a2); mo[3] = siluf(a3);
        }
        __syncthreads();

        // G3: h_e_mtx = mid @ W_out2 + b
        for (int i = tid; i < ne * 16; i += 256) {
            int el = i >> 4, j0 = (i & 15) * 4;
            float a0 = sB2[j0], a1 = sB2[j0 + 1], a2 = sB2[j0 + 2], a3 = sB2[j0 + 3];
            const float* mv = &sMid[el * 64];
            #pragma unroll 4
            for (int c = 0; c < 64; c++) {
                float hv = mv[c];
                float4 w = *(const float4*)&sW2[c * 64 + j0];
                a0 += hv * w.x; a1 += hv * w.y; a2 += hv * w.z; a3 += hv * w.w;
            }
            float* ho = &sHe[el * 64 + j0];
            ho[0] = a0; ho[1] = a1; ho[2] = a2; ho[3] = a3;
            float4 o = make_float4(a0, a1, a2, a3);
            *(float4*)&g_hemtx[(e0 + el) * 64 + j0] = o;
        }
        __syncthreads();

        // att logits = celu(h_e_mtx @ W_att + b, alpha=2)
        for (int i = tid; i < ne * 4; i += 256) {
            int el = i >> 2, a = i & 3;
            float acc = sBa[a];
            const float* hv = &sHe[el * 64];
            #pragma unroll 8
            for (int c = 0; c < 64; c++) acc += hv[c] * sWa[c * 4 + a];
            float lg = (acc > 0.f) ? acc : 2.f * (__expf(acc * 0.5f) - 1.f);
            int s = idxs[2 * (e0 + el)];
            g_w[(e0 + el) * 4 + a] = lg;
            atomicMaxF(&g_nodemax[s * 4 + a], lg);
        }
        for (int i = tid; i < ne * 3; i += 256) g_xhat[e0 * 3 + i] = sXh[i];
        __syncthreads();
    }
}

// ---------------- K2: exclusive scan of counts -> offsets (single block) ----------------
__global__ void k_scan(int N) {
    __shared__ int ssum[1024];
    int t = threadIdx.x;
    int chunk = (N + 1023) / 1024;   // <=16
    int base = t * chunk;
    int vals[16];
    int loc = 0;
    for (int k = 0; k < chunk; k++) {
        int idx = base + k;
        int v = (idx < N) ? g_counts[idx] : 0;
        vals[k] = loc; loc += v;
    }
    ssum[t] = loc; __syncthreads();
    for (int off = 1; off < 1024; off <<= 1) {
        int v = (t >= off) ? ssum[t - off] : 0;
        __syncthreads();
        ssum[t] += v;
        __syncthreads();
    }
    int excl = ssum[t] - loc;
    for (int k = 0; k < chunk; k++) {
        int idx = base + k;
        if (idx < N) { g_off[idx] = excl + vals[k]; g_cursor[idx] = excl + vals[k]; }
    }
    if (t == 1023) g_off[N] = excl + loc;
}

// ---------------- K3: CSR fill ----------------
__global__ void k_fill(const int* __restrict__ idxs, int E) {
    int e = blockIdx.x * blockDim.x + threadIdx.x;
    if (e < E) {
        int s = idxs[2 * e];
        int p = atomicAdd(&g_cursor[s], 1);
        g_eid[p] = e;
    }
}

// ---------------- K4: exp(logit - max) + expsum ----------------
__global__ void k_exp(const int* __restrict__ idxs, int E) {
    int i = blockIdx.x * blockDim.x + threadIdx.x;
    if (i >= E * 4) return;
    int e = i >> 2, a = i & 3;
    int s = idxs[2 * e];
    float w = __expf(g_w[i] - g_nodemax[s * 4 + a]);
    g_w[i] = w;
    atomicAdd(&g_expsum[s * 4 + a], w);
}

// ---------------- K5: xmix GEMM  coeff = tanh(h_e_att @ W_xmix) ----------------
__global__ void k_xmix(const int* __restrict__ idxs, const float* __restrict__ W_xmix, int E) {
    extern __shared__ float sm[];
    float* sHM  = sm;           // 32*64
    float* sAtt = sHM + 2048;   // 32*4
    float* sA   = sAtt + 128;   // 32*256
    float* sW   = sA + 8192;    // 32*256

    int tid = threadIdx.x;
    int e0 = blockIdx.x * 32;
    int ne = min(32, E - e0);

    for (int i = tid; i < 2048; i += 256) {
        int el = i >> 6;
        sHM[i] = (el < ne) ? g_hemtx[e0 * 64 + i] : 0.f;
    }
    if (tid < 128) {
        int el = tid >> 2, a = tid & 3;
        float v = 0.f;
        if (el < ne) {
            int s = idxs[2 * (e0 + el)];
            v = g_w[(e0 + el) * 4 + a] / g_expsum[s * 4 + a];
        }
        sAtt[tid] = v;
    }
    __syncthreads();
    for (int i = tid; i < 8192; i += 256) {
        int el = i >> 8, k = i & 255;
        sA[i] = sHM[el * 64 + (k >> 2)] * sAtt[el * 4 + (k & 3)];
    }

    int tx = tid & 63, ty = tid >> 6;
    float acc[32];
    #pragma unroll
    for (int i = 0; i < 32; i++) acc[i] = 0.f;

    for (int k0 = 0; k0 < 256; k0 += 32) {
        __syncthreads();
        for (int i = tid; i < 8192; i += 256)
            sW[i] = W_xmix[(k0 + (i >> 8)) * 256 + (i & 255)];
        __syncthreads();
        #pragma unroll 8
        for (int kk = 0; kk < 32; kk++) {
            float4 w = *(const float4*)&sW[kk * 256 + tx * 4];
            #pragma unroll
            for (int r = 0; r < 8; r++) {
                float a = sA[(ty * 8 + r) * 256 + k0 + kk];
                acc[r * 4]     += a * w.x;
                acc[r * 4 + 1] += a * w.y;
                acc[r * 4 + 2] += a * w.z;
                acc[r * 4 + 3] += a * w.w;
            }
        }
    }
    #pragma unroll
    for (int r = 0; r < 8; r++) {
        int el = ty * 8 + r;
        if (el < ne) {
            float4 o;
            o.x = fast_tanh(acc[r * 4]);
            o.y = fast_tanh(acc[r * 4 + 1]);
            o.z = fast_tanh(acc[r * 4 + 2]);
            o.w = fast_tanh(acc[r * 4 + 3]);
            *(float4*)&g_coeff[(e0 + el) * 256 + tx * 4] = o;
        }
    }
}

// ---------------- K6: per-node aggregation (CSR gather) ----------------
__global__ void k_agg(const float* __restrict__ W_vmix, int N) {
    __shared__ float red[256];
    int n = blockIdx.x;
    int c = threadIdx.x;
    int beg = g_off[n], end = g_off[n + 1];
    float invs = 1.f / g_expsum[n * 4 + (c & 3)];
    float accH = 0.f, a0 = 0.f, a1 = 0.f, a2 = 0.f;
    for (int i = beg; i < end; i++) {
        int e = g_eid[i];
        float att = g_w[e * 4 + (c & 3)] * invs;
        accH += g_hemtx[e * 64 + (c >> 2)] * att;
        float cf = g_coeff[e * 256 + c];
        float x0 = g_xhat[e * 3], x1 = g_xhat[e * 3 + 1], x2 = g_xhat[e * 3 + 2];
        a0 += cf * x0; a1 += cf * x1; a2 += cf * x2;
    }
    float cnt = (float)(end - beg);
    float invc = 1.f / (cnt + 1.f);
    float s0 = a0 * invc, s1 = a1 * invc, s2 = a2 * invc;
    g_he[n * 256 + c] = accH;
    g_cnorm[n * 256 + c] = s0 * s0 + s1 * s1 + s2 * s2;

    float wv = W_vmix[c];
    float contrib[3] = { wv * a0, wv * a1, wv * a2 };
    for (int d = 0; d < 3; d++) {
        red[c] = contrib[d];
        __syncthreads();
        for (int off = 128; off > 0; off >>= 1) {
            if (c < off) red[c] += red[c + off];
            __syncthreads();
        }
        if (c == 0) g_dv[n * 3 + d] = red[0] * invc;
        __syncthreads();
    }
}

// ---------------- K7: node MLPs + outputs ----------------
__global__ void k_node(const float* __restrict__ h, const float* __restrict__ x,
                       const float* __restrict__ v,
                       const float* __restrict__ W_post1, const float* __restrict__ b_post1,
                       const float* __restrict__ W_post2, const float* __restrict__ b_post2,
                       const float* __restrict__ W_node1, const float* __restrict__ b_node1,
                       const float* __restrict__ W_node2, const float* __restrict__ b_node2,
                       const float* __restrict__ W_vel1,  const float* __restrict__ b_vel1,
                       const float* __restrict__ W_vel2,
                       float* __restrict__ out_h, float* __restrict__ out_x,
                       float* __restrict__ out_v, int N)
{
    extern __shared__ float sm[];
    float* sCN = sm;             // 32*256
    float* sHE = sCN + 8192;     // 32*256
    float* sH  = sHE + 8192;     // 32*64
    float* sT  = sH  + 2048;     // 32*64
    float* sHC = sT  + 2048;     // 32*64
    float* sHN = sHC + 2048;     // 32*64
    float* sBp1 = sHN + 2048;    // 64
    float* sBp2 = sBp1 + 64;     // 64
    float* sBn1 = sBp2 + 64;     // 64
    float* sBn2 = sBn1 + 64;     // 64
    float* sBv1 = sBn2 + 64;     // 64
    float* sWv2 = sBv1 + 64;     // 64
    float* sWbuf = sWv2 + 64;    // 24576

    int tid = threadIdx.x;
    int n0 = blockIdx.x * 32;
    int nn = min(32, N - n0);

    for (int i = tid; i < nn * 256; i += 256) { sCN[i] = g_cnorm[n0 * 256 + i]; sHE[i] = g_he[n0 * 256 + i]; }
    for (int i = tid; i < nn * 64;  i += 256) sH[i] = h[n0 * 64 + i];
    if (tid < 64) {
        sBp1[tid] = b_post1[tid]; sBp2[tid] = b_post2[tid];
        sBn1[tid] = b_node1[tid]; sBn2[tid] = b_node2[tid];
        sBv1[tid] = b_vel1[tid];  sWv2[tid] = W_vel2[tid];
    }
    __syncthreads();

    // stage 1: t1 = silu(comb_norm @ W_post1 + b)
    for (int i = tid; i < 16384; i += 256) sWbuf[i] = W_post1[i];
    __syncthreads();
    for (int i = tid; i < nn * 16; i += 256) {
        int ln = i >> 4, j0 = (i & 15) * 4;
        float a0 = sBp1[j0], a1 = sBp1[j0 + 1], a2 = sBp1[j0 + 2], a3 = sBp1[j0 + 3];
        const float* cv = &sCN[ln * 256];
        #pragma unroll 4
        for (int c = 0; c < 256; c++) {
            float hv = cv[c];
            float4 w = *(const float4*)&sWbuf[c * 64 + j0];
            a0 += hv * w.x; a1 += hv * w.y; a2 += hv * w.z; a3 += hv * w.w;
        }
        float* o = &sT[ln * 64 + j0];
        o[0] = siluf(a0); o[1] = siluf(a1); o[2] = siluf(a2); o[3] = siluf(a3);
    }
    __syncthreads();

    // stage 2: h_comb = silu(t1 @ W_post2 + b)
    for (int i = tid; i < 4096; i += 256) sWbuf[i] = W_post2[i];
    __syncthreads();
    for (int i = tid; i < nn * 16; i += 256) {
        int ln = i >> 4, j0 = (i & 15) * 4;
        float a0 = sBp2[j0], a1 = sBp2[j0 + 1], a2 = sBp2[j0 + 2], a3 = sBp2[j0 + 3];
        const float* tv = &sT[ln * 64];
        #pragma unroll 4
        for (int c = 0; c < 64; c++) {
            float hv = tv[c];
            float4 w = *(const float4*)&sWbuf[c * 64 + j0];
            a0 += hv * w.x; a1 += hv * w.y; a2 += hv * w.z; a3 += hv * w.w;
        }
        float* o = &sHC[ln * 64 + j0];
        o[0] = siluf(a0); o[1] = siluf(a1); o[2] = siluf(a2); o[3] = siluf(a3);
    }
    __syncthreads();

    // stage 3: t2 = silu([h, h_e, h_comb] @ W_node1 + b)
    for (int i = tid; i < 24576; i += 256) sWbuf[i] = W_node1[i];
    __syncthreads();
    for (int i = tid; i < nn * 16; i += 256) {
        int ln = i >> 4, j0 = (i & 15) * 4;
        float a0 = sBn1[j0], a1 = sBn1[j0 + 1], a2 = sBn1[j0 + 2], a3 = sBn1[j0 + 3];
        const float* hv2 = &sH[ln * 64];
        #pragma unroll 4
        for (int c = 0; c < 64; c++) {
            float hv = hv2[c];
            float4 w = *(const float4*)&sWbuf[c * 64 + j0];
            a0 += hv * w.x; a1 += hv * w.y; a2 += hv * w.z; a3 += hv * w.w;
        }
        const float* he = &sHE[ln * 256];
        #pragma unroll 4
        for (int c = 0; c < 256; c++) {
            float hv = he[c];
            float4 w = *(const float4*)&sWbuf[(64 + c) * 64 + j0];
            a0 += hv * w.x; a1 += hv * w.y; a2 += hv * w.z; a3 += hv * w.w;
        }
        const float* hc = &sHC[ln * 64];
        #pragma unroll 4
        for (int c = 0; c < 64; c++) {
            float hv = hc[c];
            float4 w = *(const float4*)&sWbuf[(320 + c) * 64 + j0];
            a0 += hv * w.x; a1 += hv * w.y; a2 += hv * w.z; a3 += hv * w.w;
        }
        float* o = &sT[ln * 64 + j0];
        o[0] = siluf(a0); o[1] = siluf(a1); o[2] = siluf(a2); o[3] = siluf(a3);
    }
    __syncthreads();

    // stage 4: h_new = h + silu(t2 @ W_node2 + b)
    for (int i = tid; i < 4096; i += 256) sWbuf[i] = W_node2[i];
    __syncthreads();
    for (int i = tid; i < nn * 16; i += 256) {
        int ln = i >> 4, j0 = (i & 15) * 4;
        float a0 = sBn2[j0], a1 = sBn2[j0 + 1], a2 = sBn2[j0 + 2], a3 = sBn2[j0 + 3];
        const float* tv = &sT[ln * 64];
        #pragma unroll 4
        for (int c = 0; c < 64; c++) {
            float hv = tv[c];
            float4 w = *(const float4*)&sWbuf[c * 64 + j0];
            a0 += hv * w.x; a1 += hv * w.y; a2 += hv * w.z; a3 += hv * w.w;
        }
        int n = n0 + ln;
        float h0 = sH[ln * 64 + j0]     + siluf(a0);
        float h1 = sH[ln * 64 + j0 + 1] + siluf(a1);
        float h2 = sH[ln * 64 + j0 + 2] + siluf(a2);
        float h3 = sH[ln * 64 + j0 + 3] + siluf(a3);
        float* o = &sHN[ln * 64 + j0];
        o[0] = h0; o[1] = h1; o[2] = h2; o[3] = h3;
        float4 og = make_float4(h0, h1, h2, h3);
        *(float4*)&out_h[n * 64 + j0] = og;
    }
    __syncthreads();

    // stage 5: t3 = silu(h_new @ W_vel1 + b) * W_vel2  (store contributions)
    for (int i = tid; i < 4096; i += 256) sWbuf[i] = W_vel1[i];
    __syncthreads();
    for (int i = tid; i < nn * 16; i += 256) {
        int ln = i >> 4, j0 = (i & 15) * 4;
        float a0 = sBv1[j0], a1 = sBv1[j0 + 1], a2 = sBv1[j0 + 2], a3 = sBv1[j0 + 3];
        const float* hv2 = &sHN[ln * 64];
        #pragma unroll 4
        for (int c = 0; c < 64; c++) {
            float hv = hv2[c];
            float4 w = *(const float4*)&sWbuf[c * 64 + j0];
            a0 += hv * w.x; a1 += hv * w.y; a2 += hv * w.z; a3 += hv * w.w;
        }
        float* o = &sT[ln * 64 + j0];
        o[0] = siluf(a0) * sWv2[j0];
        o[1] = siluf(a1) * sWv2[j0 + 1];
        o[2] = siluf(a2) * sWv2[j0 + 2];
        o[3] = siluf(a3) * sWv2[j0 + 3];
    }
    __syncthreads();

    if (tid < nn) {
        int ln = tid;
        float s = 0.f;
        #pragma unroll 8
        for (int k = 0; k < 64; k++) s += sT[ln * 64 + k];
        float scale = 2.f / (1.f + __expf(-s));
        int n = n0 + ln;
        #pragma unroll
        for (int d = 0; d < 3; d++) {
            float vn = g_dv[n * 3 + d] + scale * v[n * 3 + d];
            out_v[n * 3 + d] = vn;
            out_x[n * 3 + d] = x[n * 3 + d] + vn;
        }
    }
}

// ---------------- launch ----------------
extern "C" void kernel_launch(void* const* d_in, const int* in_sizes, int n_in,
                              void* d_out, int out_size)
{
    const float* h        = (const float*)d_in[0];
    const float* x        = (const float*)d_in[1];
    const float* v        = (const float*)d_in[2];
    const int*   idxs     = (const int*)  d_in[3];
    const float* rbf_mean = (const float*)d_in[4];
    const float* rbf_beta = (const float*)d_in[5];
    const float* W_in     = (const float*)d_in[6];
    const float* b_in     = (const float*)d_in[7];
    const float* W_out1   = (const float*)d_in[8];
    const float* b_out1   = (const float*)d_in[9];
    const float* W_out2   = (const float*)d_in[10];
    const float* b_out2   = (const float*)d_in[11];
    const float* W_att    = (const float*)d_in[12];
    const float* b_att    = (const float*)d_in[13];
    const float* W_xmix   = (const float*)d_in[14];
    const float* W_post1  = (const float*)d_in[15];
    const float* b_post1  = (const float*)d_in[16];
    const float* W_post2  = (const float*)d_in[17];
    const float* b_post2  = (const float*)d_in[18];
    const float* W_node1  = (const float*)d_in[19];
    const float* b_node1  = (const float*)d_in[20];
    const float* W_node2  = (const float*)d_in[21];
    const float* b_node2  = (const float*)d_in[22];
    const float* W_vmix   = (const float*)d_in[23];
    const float* W_vel1   = (const float*)d_in[24];
    const float* b_vel1   = (const float*)d_in[25];
    const float* W_vel2   = (const float*)d_in[26];

    int N = in_sizes[0] / 64;
    int E = in_sizes[3] / 2;

    float* out  = (float*)d_out;
    float* outh = out;
    float* outx = out + (size_t)N * 64;
    float* outv = out + (size_t)N * 67;

    const int SM_EDGE = 32864 * 4;
    const int SM_XMIX = 18560 * 4;
    const int SM_NODE = (8192 * 2 + 2048 * 4 + 64 * 6 + 24576) * 4;

    cudaFuncSetAttribute(k_edge, cudaFuncAttributeMaxDynamicSharedMemorySize, SM_EDGE);
    cudaFuncSetAttribute(k_xmix, cudaFuncAttributeMaxDynamicSharedMemorySize, SM_XMIX);
    cudaFuncSetAttribute(k_node, cudaFuncAttributeMaxDynamicSharedMemorySize, SM_NODE);

    k_init<<<(N * 4 + 255) / 256, 256>>>(N);
    k_edge<<<592, 256, SM_EDGE>>>(h, x, idxs, rbf_mean, rbf_beta,
                                  W_in, b_in, W_out1, b_out1, W_out2, b_out2,
                                  W_att, b_att, E);
    k_scan<<<1, 1024>>>(N);
    k_fill<<<(E + 255) / 256, 256>>>(idxs, E);
    k_exp<<<(E * 4 + 255) / 256, 256>>>(idxs, E);
    k_xmix<<<(E + 31) / 32, 256, SM_XMIX>>>(idxs, W_xmix, E);
    k_agg<<<N, 256>>>(W_vmix, N);
    k_node<<<(N + 31) / 32, 256, SM_NODE>>>(h, x, v,
                                            W_post1, b_post1, W_post2, b_post2,
                                            W_node1, b_node1, W_node2, b_node2,
                                            W_vel1, b_vel1, W_vel2,
                                            outh, outx, outv, N);
}

// round 4
// speedup vs baseline: 1.6470x; 1.6470x over previous
#include <cuda_runtime.h>
#include <cuda_bf16.h>
#include <stdint.h>
#include <math.h>

#define NMAX 10000
#define EMAX 160000

// ---------------- scratch ----------------
__device__ float g_hemtx[EMAX * 64];
__device__ float g_xhat[EMAX * 3];
__device__ float g_w[EMAX * 4];
__device__ float g_coeff[EMAX * 256];
__device__ float g_nodemax[NMAX * 4];
__device__ float g_expsum[NMAX * 4];
__device__ int   g_counts[NMAX];
__device__ int   g_off[NMAX + 1];
__device__ int   g_cursor[NMAX];
__device__ int   g_eid[EMAX];
__device__ float g_he[NMAX * 256];
__device__ float g_cnorm[NMAX * 256];
__device__ float g_dv[NMAX * 3];
__device__ __nv_bfloat16 g_wh[256 * 256];   // W_xmix^T hi (bf16, [n][k])
__device__ __nv_bfloat16 g_wl[256 * 256];   // W_xmix^T lo

__device__ __forceinline__ float siluf(float x) { return x / (1.f + __expf(-x)); }
__device__ __forceinline__ float fast_tanh(float x) {
    float y; asm("tanh.approx.f32 %0, %1;" : "=f"(y) : "f"(x)); return y;
}
__device__ __forceinline__ void atomicMaxF(float* a, float v) {
    if (v >= 0.f) atomicMax((int*)a, __float_as_int(v));
    else          atomicMin((unsigned int*)a, (unsigned int)__float_as_int(v));
}

__device__ __forceinline__ void mma16816(float* d, const uint32_t* a, const uint32_t* b) {
    asm volatile("mma.sync.aligned.m16n8k16.row.col.f32.bf16.bf16.f32 "
        "{%0,%1,%2,%3}, {%4,%5,%6,%7}, {%8,%9}, {%0,%1,%2,%3};"
        : "+f"(d[0]), "+f"(d[1]), "+f"(d[2]), "+f"(d[3])
        : "r"(a[0]), "r"(a[1]), "r"(a[2]), "r"(a[3]), "r"(b[0]), "r"(b[1]));
}

// ---------------- K0: init ----------------
__global__ void k_init(int N) {
    int i = blockIdx.x * blockDim.x + threadIdx.x;
    if (i < N * 4) {
        g_nodemax[i] = __int_as_float(0xff800000);
        g_expsum[i]  = 0.f;
    }
    if (i < N) g_counts[i] = 0;
}

// ---------------- K_wprep: transpose + bf16-split W_xmix ----------------
__global__ void k_wprep(const float* __restrict__ W_xmix) {
    int i = blockIdx.x * 256 + threadIdx.x;   // 65536
    int n = i >> 8, k = i & 255;
    float w = W_xmix[k * 256 + n];
    __nv_bfloat16 wh = __float2bfloat16(w);
    __nv_bfloat16 wl = __float2bfloat16(w - __bfloat162float(wh));
    g_wh[n * 256 + k] = wh;
    g_wl[n * 256 + k] = wl;
}

// ---------------- K1: fused edge MLP (64-edge tiles, 4x4 register blocking) ----------------
__global__ void k_edge(const float* __restrict__ h, const float* __restrict__ x,
                       const int* __restrict__ idxs,
                       const float* __restrict__ rbf_means, const float* __restrict__ rbf_betas,
                       const float* __restrict__ W_in,  const float* __restrict__ b_in,
                       const float* __restrict__ W_out1, const float* __restrict__ b_out1,
                       const float* __restrict__ W_out2, const float* __restrict__ b_out2,
                       const float* __restrict__ W_att,  const float* __restrict__ b_att,
                       int E)
{
    extern __shared__ float sm[];
    float* sWin  = sm;                    // 128*52
    float* sBin  = sWin  + 128 * 52;      // 52
    float* sMean = sBin  + 52;            // 52
    float* sBeta = sMean + 52;            // 52
    float* sW1   = sBeta + 52;            // 179*64
    float* sB1   = sW1   + 179 * 64;      // 64
    float* sW2   = sB1   + 64;            // 64*64
    float* sB2   = sW2   + 64 * 64;       // 64
    float* sWa   = sB2   + 64;            // 64*4
    float* sBa   = sWa   + 256;           // 4
    float* sHcat = sBa   + 4;             // 64*132
    float* sX    = sHcat + 64 * 132;      // 64*52
    float* sMid  = sX    + 64 * 52;       // 64*64
    float* sHe   = sMid  + 64 * 64;       // 64*64
    float* sNorm = sHe   + 64 * 64;       // 64
    float* sXh   = sNorm + 64;            // 64*3

    int tid = threadIdx.x;
    for (int i = tid; i < 128 * 52; i += 256) { int r = i / 52, c = i % 52; sWin[i] = (c < 50) ? W_in[r * 50 + c] : 0.f; }
    for (int i = tid; i < 52; i += 256) {
        sBin[i]  = (i < 50) ? b_in[i] : 0.f;
        sMean[i] = (i < 50) ? rbf_means[i] : 0.f;
        sBeta[i] = (i < 50) ? rbf_betas[i] : 0.f;
    }
    for (int i = tid; i < 179 * 64; i += 256) sW1[i] = W_out1[i];
    for (int i = tid; i < 64 * 64;  i += 256) sW2[i] = W_out2[i];
    for (int i = tid; i < 256;      i += 256) sWa[i] = W_att[i];
    if (tid < 64) { sB1[tid] = b_out1[tid]; sB2[tid] = b_out2[tid]; }
    if (tid < 4)  sBa[tid] = b_att[tid];
    __syncthreads();

    int ntiles = (E + 63) / 64;
    for (int tile = blockIdx.x; tile < ntiles; tile += gridDim.x) {
        int e0 = tile * 64;
        int ne = min(64, E - e0);

        if (tid < 64) {
            if (tid < ne) {
                int s = idxs[2 * (e0 + tid)], d = idxs[2 * (e0 + tid) + 1];
                float dx = x[3 * s]     - x[3 * d];
                float dy = x[3 * s + 1] - x[3 * d + 1];
                float dz = x[3 * s + 2] - x[3 * d + 2];
                float nrm = sqrtf(dx * dx + dy * dy + dz * dz + 1e-14f);
                sNorm[tid] = nrm;
                float inv = 1.f / (nrm + 1e-5f);
                sXh[tid * 3]     = dx * inv;
                sXh[tid * 3 + 1] = dy * inv;
                sXh[tid * 3 + 2] = dz * inv;
                atomicAdd(&g_counts[s], 1);
            } else {
                sNorm[tid] = 0.f;
                sXh[tid * 3] = 0.f; sXh[tid * 3 + 1] = 0.f; sXh[tid * 3 + 2] = 0.f;
            }
        }
        for (int i = tid; i < 64 * 128; i += 256) {
            int el = i >> 7, c = i & 127;
            float val = 0.f;
            if (el < ne) {
                int node = idxs[2 * (e0 + el) + (c >> 6)];
                val = h[node * 64 + (c & 63)];
            }
            sHcat[el * 132 + c] = val;
        }
        __syncthreads();

        // G1: h_in = hcat @ W_in + b ; _x = rbf * h_in    (16 quads x 13 colgroups)
        if (tid < 208) {
            int q = tid / 13, cg = tid % 13;
            int el0 = q * 4, j0 = cg * 4;
            float acc[4][4];
            #pragma unroll
            for (int r = 0; r < 4; r++) { acc[r][0] = sBin[j0]; acc[r][1] = sBin[j0+1]; acc[r][2] = sBin[j0+2]; acc[r][3] = sBin[j0+3]; }
            const float* hb = &sHcat[el0 * 132];
            #pragma unroll 4
            for (int c = 0; c < 128; c++) {
                float4 w = *(const float4*)&sWin[c * 52 + j0];
                #pragma unroll
                for (int r = 0; r < 4; r++) {
                    float hv = hb[r * 132 + c];
                    acc[r][0] += hv * w.x; acc[r][1] += hv * w.y; acc[r][2] += hv * w.z; acc[r][3] += hv * w.w;
                }
            }
            #pragma unroll
            for (int r = 0; r < 4; r++) {
                float nrm = sNorm[el0 + r];
                float ex = __expf(-nrm);
                float* xo = &sX[(el0 + r) * 52 + j0];
                #pragma unroll
                for (int t = 0; t < 4; t++) {
                    if (j0 + t < 50) {
                        float d = ex - sMean[j0 + t];
                        xo[t] = __expf(-sBeta[j0 + t] * d * d) * acc[r][t];
                    }
                }
            }
        }
        __syncthreads();

        // G2: mid = silu([hcat,_x,norm] @ W_out1 + b)
        {
            int q = tid >> 4, cg = tid & 15;
            int el0 = q * 4, j0 = cg * 4;
            float acc[4][4];
            #pragma unroll
            for (int r = 0; r < 4; r++) { acc[r][0] = sB1[j0]; acc[r][1] = sB1[j0+1]; acc[r][2] = sB1[j0+2]; acc[r][3] = sB1[j0+3]; }
            const float* hb = &sHcat[el0 * 132];
            #pragma unroll 4
            for (int c = 0; c < 128; c++) {
                float4 w = *(const float4*)&sW1[c * 64 + j0];
                #pragma unroll
                for (int r = 0; r < 4; r++) {
                    float hv = hb[r * 132 + c];
                    acc[r][0] += hv * w.x; acc[r][1] += hv * w.y; acc[r][2] += hv * w.z; acc[r][3] += hv * w.w;
                }
            }
            const float* xb = &sX[el0 * 52];
            #pragma unroll 2
            for (int c = 0; c < 50; c++) {
                float4 w = *(const float4*)&sW1[(128 + c) * 64 + j0];
                #pragma unroll
                for (int r = 0; r < 4; r++) {
                    float hv = xb[r * 52 + c];
                    acc[r][0] += hv * w.x; acc[r][1] += hv * w.y; acc[r][2] += hv * w.z; acc[r][3] += hv * w.w;
                }
            }
            {
                float4 w = *(const float4*)&sW1[178 * 64 + j0];
                #pragma unroll
                for (int r = 0; r < 4; r++) {
                    float nv = sNorm[el0 + r];
                    acc[r][0] += nv * w.x; acc[r][1] += nv * w.y; acc[r][2] += nv * w.z; acc[r][3] += nv * w.w;
                }
            }
            #pragma unroll
            for (int r = 0; r < 4; r++) {
                float* mo = &sMid[(el0 + r) * 64 + j0];
                mo[0] = siluf(acc[r][0]); mo[1] = siluf(acc[r][1]); mo[2] = siluf(acc[r][2]); mo[3] = siluf(acc[r][3]);
            }
        }
        __syncthreads();

        // G3: h_e_mtx = mid @ W_out2 + b
        {
            int q = tid >> 4, cg = tid & 15;
            int el0 = q * 4, j0 = cg * 4;
            float acc[4][4];
            #pragma unroll
            for (int r = 0; r < 4; r++) { acc[r][0] = sB2[j0]; acc[r][1] = sB2[j0+1]; acc[r][2] = sB2[j0+2]; acc[r][3] = sB2[j0+3]; }
            const float* mb = &sMid[el0 * 64];
            #pragma unroll 4
            for (int c = 0; c < 64; c++) {
                float4 w = *(const float4*)&sW2[c * 64 + j0];
                #pragma unroll
                for (int r = 0; r < 4; r++) {
                    float hv = mb[r * 64 + c];
                    acc[r][0] += hv * w.x; acc[r][1] += hv * w.y; acc[r][2] += hv * w.z; acc[r][3] += hv * w.w;
                }
            }
            #pragma unroll
            for (int r = 0; r < 4; r++) {
                int el = el0 + r;
                float* ho = &sHe[el * 64 + j0];
                ho[0] = acc[r][0]; ho[1] = acc[r][1]; ho[2] = acc[r][2]; ho[3] = acc[r][3];
                if (el < ne) {
                    *(float4*)&g_hemtx[(e0 + el) * 64 + j0] =
                        make_float4(acc[r][0], acc[r][1], acc[r][2], acc[r][3]);
                }
            }
        }
        __syncthreads();

        // att logits = celu(h_e_mtx @ W_att + b, alpha=2)
        {
            int el = tid >> 2, a = tid & 3;
            if (el < ne) {
                float acc = sBa[a];
                const float* hv = &sHe[el * 64];
                #pragma unroll 8
                for (int c = 0; c < 64; c++) acc += hv[c] * sWa[c * 4 + a];
                float lg = (acc > 0.f) ? acc : 2.f * (__expf(acc * 0.5f) - 1.f);
                int s = idxs[2 * (e0 + el)];
                g_w[(e0 + el) * 4 + a] = lg;
                atomicMaxF(&g_nodemax[s * 4 + a], lg);
            }
        }
        for (int i = tid; i < ne * 3; i += 256) g_xhat[e0 * 3 + i] = sXh[i];
        __syncthreads();
    }
}

// ---------------- K2: exclusive scan ----------------
__global__ void k_scan(int N) {
    __shared__ int ssum[1024];
    int t = threadIdx.x;
    int chunk = (N + 1023) / 1024;
    int base = t * chunk;
    int vals[16];
    int loc = 0;
    for (int k = 0; k < chunk; k++) {
        int idx = base + k;
        int v = (idx < N) ? g_counts[idx] : 0;
        vals[k] = loc; loc += v;
    }
    ssum[t] = loc; __syncthreads();
    for (int off = 1; off < 1024; off <<= 1) {
        int v = (t >= off) ? ssum[t - off] : 0;
        __syncthreads();
        ssum[t] += v;
        __syncthreads();
    }
    int excl = ssum[t] - loc;
    for (int k = 0; k < chunk; k++) {
        int idx = base + k;
        if (idx < N) { g_off[idx] = excl + vals[k]; g_cursor[idx] = excl + vals[k]; }
    }
    if (t == 1023) g_off[N] = excl + loc;
}

// ---------------- K3: CSR fill ----------------
__global__ void k_fill(const int* __restrict__ idxs, int E) {
    int e = blockIdx.x * blockDim.x + threadIdx.x;
    if (e < E) {
        int s = idxs[2 * e];
        int p = atomicAdd(&g_cursor[s], 1);
        g_eid[p] = e;
    }
}

// ---------------- K4: exp + expsum ----------------
__global__ void k_exp(const int* __restrict__ idxs, int E) {
    int i = blockIdx.x * blockDim.x + threadIdx.x;
    if (i >= E * 4) return;
    int e = i >> 2, a = i & 3;
    int s = idxs[2 * e];
    float w = __expf(g_w[i] - g_nodemax[s * 4 + a]);
    g_w[i] = w;
    atomicAdd(&g_expsum[s * 4 + a], w);
}

// ---------------- K5: xmix via mma.sync bf16 (3-term split) ----------------
// Block = 64 edges (M=64), N=256, K=256 staged in 4 chunks of 64.
// A row stride 264 bf16 (132 u32), W^T chunk row stride 72 bf16 (36 u32):
// both give conflict-free per-lane 32-bit fragment loads.
#define XS_AH 0
#define XS_AL (64 * 264)
#define XS_WH (2 * 64 * 264)
#define XS_WL (2 * 64 * 264 + 256 * 72)
#define X_ELEMS (2 * 64 * 264 + 2 * 256 * 72)
#define X_SMEM (X_ELEMS * 2)

__global__ void __launch_bounds__(256, 1)
k_xmix_mma(const int* __restrict__ idxs, int E)
{
    extern __shared__ __nv_bfloat16 smx[];
    int tid = threadIdx.x;
    int lid = tid & 31, wid = tid >> 5;
    int e0 = blockIdx.x * 64;
    int ne = min(64, E - e0);

    uint32_t* pAh = (uint32_t*)(smx + XS_AH);
    uint32_t* pAl = (uint32_t*)(smx + XS_AL);
    uint32_t* pWh = (uint32_t*)(smx + XS_WH);
    uint32_t* pWl = (uint32_t*)(smx + XS_WL);

    // ---- build A hi/lo: A[el][k] = hemtx[el][k>>2] * att[el][k&3] ----
    {
        int el = tid & 63, kq = tid >> 6;   // kq in [0,4): k range [kq*64, kq*64+64)
        float att[4], hm[16];
        if (el < ne) {
            int e = e0 + el;
            int s = idxs[2 * e];
            #pragma unroll
            for (int a = 0; a < 4; a++) att[a] = g_w[e * 4 + a] / g_expsum[s * 4 + a];
            const float4* hp = (const float4*)&g_hemtx[(size_t)e * 64 + kq * 16];
            #pragma unroll
            for (int i = 0; i < 4; i++) {
                float4 v = hp[i];
                hm[i * 4] = v.x; hm[i * 4 + 1] = v.y; hm[i * 4 + 2] = v.z; hm[i * 4 + 3] = v.w;
            }
        } else {
            #pragma unroll
            for (int a = 0; a < 4; a++) att[a] = 0.f;
            #pragma unroll
            for (int i = 0; i < 16; i++) hm[i] = 0.f;
        }
        #pragma unroll
        for (int j = 0; j < 32; j++) {
            int kl = 2 * j;                     // local k within the 64-chunk
            float m = hm[kl >> 2];
            float a0 = m * att[kl & 3];
            float a1 = m * att[(kl + 1) & 3];
            __nv_bfloat16 h0 = __float2bfloat16(a0), h1 = __float2bfloat16(a1);
            __nv_bfloat16 l0 = __float2bfloat16(a0 - __bfloat162float(h0));
            __nv_bfloat16 l1 = __float2bfloat16(a1 - __bfloat162float(h1));
            uint32_t ph = (uint32_t)__bfloat16_as_ushort(h0) | ((uint32_t)__bfloat16_as_ushort(h1) << 16);
            uint32_t pl = (uint32_t)__bfloat16_as_ushort(l0) | ((uint32_t)__bfloat16_as_ushort(l1) << 16);
            int idx32 = el * 132 + ((kq * 64 + kl) >> 1);
            pAh[idx32] = ph;
            pAl[idx32] = pl;
        }
    }

    int g = lid >> 2, tg = lid & 3;
    int mrow = (wid & 1) * 32;        // warp M-tile base (2 x 16-row tiles)
    int ncol = (wid >> 1) * 64;       // warp N-tile base (8 x 8-col tiles)

    float acc[2][8][4];
    #pragma unroll
    for (int mt = 0; mt < 2; mt++)
        #pragma unroll
        for (int nt = 0; nt < 8; nt++)
            #pragma unroll
            for (int q = 0; q < 4; q++) acc[mt][nt][q] = 0.f;

    for (int kc = 0; kc < 4; kc++) {
        __syncthreads();
        // load W^T chunk: rows n = tid, k in [kc*64, kc*64+64)
        {
            int n = tid;
            const uint4* srch = (const uint4*)&g_wh[n * 256 + kc * 64];
            const uint4* srcl = (const uint4*)&g_wl[n * 256 + kc * 64];
            uint4* dsth = (uint4*)(pWh + n * 36);
            uint4* dstl = (uint4*)(pWl + n * 36);
            #pragma unroll
            for (int i = 0; i < 8; i++) { dsth[i] = srch[i]; dstl[i] = srcl[i]; }
        }
        __syncthreads();

        #pragma unroll
        for (int ks = 0; ks < 4; ks++) {
            int kA = kc * 64 + ks * 16;
            uint32_t aH[2][4], aL[2][4];
            #pragma unroll
            for (int mt = 0; mt < 2; mt++) {
                int r0 = mrow + mt * 16 + g;
                int c0h = (kA + tg * 2) >> 1;
                aH[mt][0] = pAh[r0 * 132 + c0h];
                aH[mt][1] = pAh[(r0 + 8) * 132 + c0h];
                aH[mt][2] = pAh[r0 * 132 + c0h + 4];
                aH[mt][3] = pAh[(r0 + 8) * 132 + c0h + 4];
                aL[mt][0] = pAl[r0 * 132 + c0h];
                aL[mt][1] = pAl[(r0 + 8) * 132 + c0h];
                aL[mt][2] = pAl[r0 * 132 + c0h + 4];
                aL[mt][3] = pAl[(r0 + 8) * 132 + c0h + 4];
            }
            uint32_t bH[8][2], bL[8][2];
            #pragma unroll
            for (int nt = 0; nt < 8; nt++) {
                int n = ncol + nt * 8 + g;
                int ckh = (ks * 16 + tg * 2) >> 1;
                bH[nt][0] = pWh[n * 36 + ckh];
                bH[nt][1] = pWh[n * 36 + ckh + 4];
                bL[nt][0] = pWl[n * 36 + ckh];
                bL[nt][1] = pWl[n * 36 + ckh + 4];
            }
            #pragma unroll
            for (int mt = 0; mt < 2; mt++)
                #pragma unroll
                for (int nt = 0; nt < 8; nt++) {
                    mma16816(acc[mt][nt], aH[mt], bH[nt]);
                    mma16816(acc[mt][nt], aL[mt], bH[nt]);
                    mma16816(acc[mt][nt], aH[mt], bL[nt]);
                }
        }
    }

    // ---- epilogue: tanh -> g_coeff ----
    #pragma unroll
    for (int mt = 0; mt < 2; mt++)
        #pragma unroll
        for (int nt = 0; nt < 8; nt++) {
            int rl = mrow + mt * 16 + g;
            int col = ncol + nt * 8 + tg * 2;
            float* a = acc[mt][nt];
            if (rl < ne) {
                float2 o = make_float2(fast_tanh(a[0]), fast_tanh(a[1]));
                *(float2*)&g_coeff[(size_t)(e0 + rl) * 256 + col] = o;
            }
            if (rl + 8 < ne) {
                float2 o = make_float2(fast_tanh(a[2]), fast_tanh(a[3]));
                *(float2*)&g_coeff[(size_t)(e0 + rl + 8) * 256 + col] = o;
            }
        }
}

// ---------------- K6: per-node aggregation ----------------
__global__ void k_agg(const float* __restrict__ W_vmix, int N) {
    __shared__ float red[256];
    int n = blockIdx.x;
    int c = threadIdx.x;
    int beg = g_off[n], end = g_off[n + 1];
    float invs = 1.f / g_expsum[n * 4 + (c & 3)];
    float accH = 0.f, a0 = 0.f, a1 = 0.f, a2 = 0.f;
    for (int i = beg; i < end; i++) {
        int e = g_eid[i];
        float att = g_w[e * 4 + (c & 3)] * invs;
        accH += g_hemtx[(size_t)e * 64 + (c >> 2)] * att;
        float cf = g_coeff[(size_t)e * 256 + c];
        float x0 = g_xhat[e * 3], x1 = g_xhat[e * 3 + 1], x2 = g_xhat[e * 3 + 2];
        a0 += cf * x0; a1 += cf * x1; a2 += cf * x2;
    }
    float cnt = (float)(end - beg);
    float invc = 1.f / (cnt + 1.f);
    float s0 = a0 * invc, s1 = a1 * invc, s2 = a2 * invc;
    g_he[n * 256 + c] = accH;
    g_cnorm[n * 256 + c] = s0 * s0 + s1 * s1 + s2 * s2;

    float wv = W_vmix[c];
    float contrib[3] = { wv * a0, wv * a1, wv * a2 };
    for (int d = 0; d < 3; d++) {
        red[c] = contrib[d];
        __syncthreads();
        for (int off = 128; off > 0; off >>= 1) {
            if (c < off) red[c] += red[c + off];
            __syncthreads();
        }
        if (c == 0) g_dv[n * 3 + d] = red[0] * invc;
        __syncthreads();
    }
}

// ---------------- K7: node MLPs ----------------
__global__ void k_node(const float* __restrict__ h, const float* __restrict__ x,
                       const float* __restrict__ v,
                       const float* __restrict__ W_post1, const float* __restrict__ b_post1,
                       const float* __restrict__ W_post2, const float* __restrict__ b_post2,
                       const float* __restrict__ W_node1, const float* __restrict__ b_node1,
                       const float* __restrict__ W_node2, const float* __restrict__ b_node2,
                       const float* __restrict__ W_vel1,  const float* __restrict__ b_vel1,
                       const float* __restrict__ W_vel2,
                       float* __restrict__ out_h, float* __restrict__ out_x,
                       float* __restrict__ out_v, int N)
{
    extern __shared__ float sm[];
    float* sCN = sm;
    float* sHE = sCN + 8192;
    float* sH  = sHE + 8192;
    float* sT  = sH  + 2048;
    float* sHC = sT  + 2048;
    float* sHN = sHC + 2048;
    float* sBp1 = sHN + 2048;
    float* sBp2 = sBp1 + 64;
    float* sBn1 = sBp2 + 64;
    float* sBn2 = sBn1 + 64;
    float* sBv1 = sBn2 + 64;
    float* sWv2 = sBv1 + 64;
    float* sWbuf = sWv2 + 64;

    int tid = threadIdx.x;
    int n0 = blockIdx.x * 32;
    int nn = min(32, N - n0);

    for (int i = tid; i < nn * 256; i += 256) { sCN[i] = g_cnorm[n0 * 256 + i]; sHE[i] = g_he[n0 * 256 + i]; }
    for (int i = tid; i < nn * 64;  i += 256) sH[i] = h[n0 * 64 + i];
    if (tid < 64) {
        sBp1[tid] = b_post1[tid]; sBp2[tid] = b_post2[tid];
        sBn1[tid] = b_node1[tid]; sBn2[tid] = b_node2[tid];
        sBv1[tid] = b_vel1[tid];  sWv2[tid] = W_vel2[tid];
    }
    __syncthreads();

    for (int i = tid; i < 16384; i += 256) sWbuf[i] = W_post1[i];
    __syncthreads();
    for (int i = tid; i < nn * 16; i += 256) {
        int ln = i >> 4, j0 = (i & 15) * 4;
        float a0 = sBp1[j0], a1 = sBp1[j0 + 1], a2 = sBp1[j0 + 2], a3 = sBp1[j0 + 3];
        const float* cv = &sCN[ln * 256];
        #pragma unroll 4
        for (int c = 0; c < 256; c++) {
            float hv = cv[c];
            float4 w = *(const float4*)&sWbuf[c * 64 + j0];
            a0 += hv * w.x; a1 += hv * w.y; a2 += hv * w.z; a3 += hv * w.w;
        }
        float* o = &sT[ln * 64 + j0];
        o[0] = siluf(a0); o[1] = siluf(a1); o[2] = siluf(a2); o[3] = siluf(a3);
    }
    __syncthreads();

    for (int i = tid; i < 4096; i += 256) sWbuf[i] = W_post2[i];
    __syncthreads();
    for (int i = tid; i < nn * 16; i += 256) {
        int ln = i >> 4, j0 = (i & 15) * 4;
        float a0 = sBp2[j0], a1 = sBp2[j0 + 1], a2 = sBp2[j0 + 2], a3 = sBp2[j0 + 3];
        const float* tv = &sT[ln * 64];
        #pragma unroll 4
        for (int c = 0; c < 64; c++) {
            float hv = tv[c];
            float4 w = *(const float4*)&sWbuf[c * 64 + j0];
            a0 += hv * w.x; a1 += hv * w.y; a2 += hv * w.z; a3 += hv * w.w;
        }
        float* o = &sHC[ln * 64 + j0];
        o[0] = siluf(a0); o[1] = siluf(a1); o[2] = siluf(a2); o[3] = siluf(a3);
    }
    __syncthreads();

    for (int i = tid; i < 24576; i += 256) sWbuf[i] = W_node1[i];
    __syncthreads();
    for (int i = tid; i < nn * 16; i += 256) {
        int ln = i >> 4, j0 = (i & 15) * 4;
        float a0 = sBn1[j0], a1 = sBn1[j0 + 1], a2 = sBn1[j0 + 2], a3 = sBn1[j0 + 3];
        const float* hv2 = &sH[ln * 64];
        #pragma unroll 4
        for (int c = 0; c < 64; c++) {
            float hv = hv2[c];
            float4 w = *(const float4*)&sWbuf[c * 64 + j0];
            a0 += hv * w.x; a1 += hv * w.y; a2 += hv * w.z; a3 += hv * w.w;
        }
        const float* he = &sHE[ln * 256];
        #pragma unroll 4
        for (int c = 0; c < 256; c++) {
            float hv = he[c];
            float4 w = *(const float4*)&sWbuf[(64 + c) * 64 + j0];
            a0 += hv * w.x; a1 += hv * w.y; a2 += hv * w.z; a3 += hv * w.w;
        }
        const float* hc = &sHC[ln * 64];
        #pragma unroll 4
        for (int c = 0; c < 64; c++) {
            float hv = hc[c];
            float4 w = *(const float4*)&sWbuf[(320 + c) * 64 + j0];
            a0 += hv * w.x; a1 += hv * w.y; a2 += hv * w.z; a3 += hv * w.w;
        }
        float* o = &sT[ln * 64 + j0];
        o[0] = siluf(a0); o[1] = siluf(a1); o[2] = siluf(a2); o[3] = siluf(a3);
    }
    __syncthreads();

    for (int i = tid; i < 4096; i += 256) sWbuf[i] = W_node2[i];
    __syncthreads();
    for (int i = tid; i < nn * 16; i += 256) {
        int ln = i >> 4, j0 = (i & 15) * 4;
        float a0 = sBn2[j0], a1 = sBn2[j0 + 1], a2 = sBn2[j0 + 2], a3 = sBn2[j0 + 3];
        const float* tv = &sT[ln * 64];
        #pragma unroll 4
        for (int c = 0; c < 64; c++) {
            float hv = tv[c];
            float4 w = *(const float4*)&sWbuf[c * 64 + j0];
            a0 += hv * w.x; a1 += hv * w.y; a2 += hv * w.z; a3 += hv * w.w;
        }
        int n = n0 + ln;
        float h0 = sH[ln * 64 + j0]     + siluf(a0);
        float h1 = sH[ln * 64 + j0 + 1] + siluf(a1);
        float h2 = sH[ln * 64 + j0 + 2] + siluf(a2);
        float h3 = sH[ln * 64 + j0 + 3] + siluf(a3);
        float* o = &sHN[ln * 64 + j0];
        o[0] = h0; o[1] = h1; o[2] = h2; o[3] = h3;
        *(float4*)&out_h[n * 64 + j0] = make_float4(h0, h1, h2, h3);
    }
    __syncthreads();

    for (int i = tid; i < 4096; i += 256) sWbuf[i] = W_vel1[i];
    __syncthreads();
    for (int i = tid; i < nn * 16; i += 256) {
        int ln = i >> 4, j0 = (i & 15) * 4;
        float a0 = sBv1[j0], a1 = sBv1[j0 + 1], a2 = sBv1[j0 + 2], a3 = sBv1[j0 + 3];
        const float* hv2 = &sHN[ln * 64];
        #pragma unroll 4
        for (int c = 0; c < 64; c++) {
            float hv = hv2[c];
            float4 w = *(const float4*)&sWbuf[c * 64 + j0];
            a0 += hv * w.x; a1 += hv * w.y; a2 += hv * w.z; a3 += hv * w.w;
        }
        float* o = &sT[ln * 64 + j0];
        o[0] = siluf(a0) * sWv2[j0];
        o[1] = siluf(a1) * sWv2[j0 + 1];
        o[2] = siluf(a2) * sWv2[j0 + 2];
        o[3] = siluf(a3) * sWv2[j0 + 3];
    }
    __syncthreads();

    if (tid < nn) {
        int ln = tid;
        float s = 0.f;
        #pragma unroll 8
        for (int k = 0; k < 64; k++) s += sT[ln * 64 + k];
        float scale = 2.f / (1.f + __expf(-s));
        int n = n0 + ln;
        #pragma unroll
        for (int d = 0; d < 3; d++) {
            float vn = g_dv[n * 3 + d] + scale * v[n * 3 + d];
            out_v[n * 3 + d] = vn;
            out_x[n * 3 + d] = x[n * 3 + d] + vn;
        }
    }
}

// ---------------- launch ----------------
extern "C" void kernel_launch(void* const* d_in, const int* in_sizes, int n_in,
                              void* d_out, int out_size)
{
    const float* h        = (const float*)d_in[0];
    const float* x        = (const float*)d_in[1];
    const float* v        = (const float*)d_in[2];
    const int*   idxs     = (const int*)  d_in[3];
    const float* rbf_mean = (const float*)d_in[4];
    const float* rbf_beta = (const float*)d_in[5];
    const float* W_in     = (const float*)d_in[6];
    const float* b_in     = (const float*)d_in[7];
    const float* W_out1   = (const float*)d_in[8];
    const float* b_out1   = (const float*)d_in[9];
    const float* W_out2   = (const float*)d_in[10];
    const float* b_out2   = (const float*)d_in[11];
    const float* W_att    = (const float*)d_in[12];
    const float* b_att    = (const float*)d_in[13];
    const float* W_xmix   = (const float*)d_in[14];
    const float* W_post1  = (const float*)d_in[15];
    const float* b_post1  = (const float*)d_in[16];
    const float* W_post2  = (const float*)d_in[17];
    const float* b_post2  = (const float*)d_in[18];
    const float* W_node1  = (const float*)d_in[19];
    const float* b_node1  = (const float*)d_in[20];
    const float* W_node2  = (const float*)d_in[21];
    const float* b_node2  = (const float*)d_in[22];
    const float* W_vmix   = (const float*)d_in[23];
    const float* W_vel1   = (const float*)d_in[24];
    const float* b_vel1   = (const float*)d_in[25];
    const float* W_vel2   = (const float*)d_in[26];

    int N = in_sizes[0] / 64;
    int E = in_sizes[3] / 2;

    float* out  = (float*)d_out;
    float* outh = out;
    float* outx = out + (size_t)N * 64;
    float* outv = out + (size_t)N * 67;

    const int SM_EDGE = 42976 * 4;
    const int SM_NODE = (8192 * 2 + 2048 * 4 + 64 * 6 + 24576) * 4;

    cudaFuncSetAttribute(k_edge,     cudaFuncAttributeMaxDynamicSharedMemorySize, SM_EDGE);
    cudaFuncSetAttribute(k_xmix_mma, cudaFuncAttributeMaxDynamicSharedMemorySize, X_SMEM);
    cudaFuncSetAttribute(k_node,     cudaFuncAttributeMaxDynamicSharedMemorySize, SM_NODE);

    k_init<<<(N * 4 + 255) / 256, 256>>>(N);
    k_wprep<<<256, 256>>>(W_xmix);
    k_edge<<<148, 256, SM_EDGE>>>(h, x, idxs, rbf_mean, rbf_beta,
                                  W_in, b_in, W_out1, b_out1, W_out2, b_out2,
                                  W_att, b_att, E);
    k_scan<<<1, 1024>>>(N);
    k_fill<<<(E + 255) / 256, 256>>>(idxs, E);
    k_exp<<<(E * 4 + 255) / 256, 256>>>(idxs, E);
    k_xmix_mma<<<(E + 63) / 64, 256, X_SMEM>>>(idxs, E);
    k_agg<<<N, 256>>>(W_vmix, N);
    k_node<<<(N + 31) / 32, 256, SM_NODE>>>(h, x, v,
                                            W_post1, b_post1, W_post2, b_post2,
                                            W_node1, b_node1, W_node2, b_node2,
                                            W_vel1, b_vel1, W_vel2,
                                            outh, outx, outv, N);
}

// round 5
// speedup vs baseline: 1.9480x; 1.1827x over previous
#include <cuda_runtime.h>
#include <cuda_bf16.h>
#include <stdint.h>
#include <math.h>

#define NMAX 10000
#define EMAX 160000

// ---------------- scratch ----------------
__device__ float g_hemtx[EMAX * 64];
__device__ float g_xhat[EMAX * 3];
__device__ float g_w[EMAX * 4];
__device__ float g_coeff[EMAX * 256];
__device__ float g_nodemax[NMAX * 4];
__device__ float g_expsum[NMAX * 4];
__device__ int   g_counts[NMAX];
__device__ int   g_off[NMAX + 1];
__device__ int   g_cursor[NMAX];
__device__ int   g_eid[EMAX];
__device__ float g_he[NMAX * 256];
__device__ float g_cnorm[NMAX * 256];
__device__ float g_dv[NMAX * 3];
__device__ __nv_bfloat16 g_wh[256 * 256];   // W_xmix^T hi
__device__ __nv_bfloat16 g_wl[256 * 256];   // W_xmix^T lo
// edge-MLP weights, packed bf16x2 (u32), [n][k] layout
__device__ uint32_t g_ewi_h[4096],  g_ewi_l[4096];    // W_in^T  64x128
__device__ uint32_t g_ew1a_h[4096], g_ew1a_l[4096];   // W_out1^T rows 0..127 -> 64x128
__device__ uint32_t g_ew1b_h[2048], g_ew1b_l[2048];   // W_out1^T rows 128..178 -> 64x64 (k50=norm col)
__device__ uint32_t g_ew2_h[2048],  g_ew2_l[2048];    // W_out2^T 64x64

__device__ __forceinline__ float siluf(float x) { return x / (1.f + __expf(-x)); }
__device__ __forceinline__ float fast_tanh(float x) {
    float y; asm("tanh.approx.f32 %0, %1;" : "=f"(y) : "f"(x)); return y;
}
__device__ __forceinline__ void atomicMaxF(float* a, float v) {
    if (v >= 0.f) atomicMax((int*)a, __float_as_int(v));
    else          atomicMin((unsigned int*)a, (unsigned int)__float_as_int(v));
}
__device__ __forceinline__ void mma16816(float* d, const uint32_t* a, const uint32_t* b) {
    asm volatile("mma.sync.aligned.m16n8k16.row.col.f32.bf16.bf16.f32 "
        "{%0,%1,%2,%3}, {%4,%5,%6,%7}, {%8,%9}, {%0,%1,%2,%3};"
        : "+f"(d[0]), "+f"(d[1]), "+f"(d[2]), "+f"(d[3])
        : "r"(a[0]), "r"(a[1]), "r"(a[2]), "r"(a[3]), "r"(b[0]), "r"(b[1]));
}
__device__ __forceinline__ void split2(float a, float b, uint32_t& hi, uint32_t& lo) {
    __nv_bfloat16 h0 = __float2bfloat16(a), h1 = __float2bfloat16(b);
    __nv_bfloat16 l0 = __float2bfloat16(a - __bfloat162float(h0));
    __nv_bfloat16 l1 = __float2bfloat16(b - __bfloat162float(h1));
    hi = (uint32_t)__bfloat16_as_ushort(h0) | ((uint32_t)__bfloat16_as_ushort(h1) << 16);
    lo = (uint32_t)__bfloat16_as_ushort(l0) | ((uint32_t)__bfloat16_as_ushort(l1) << 16);
}

// ---------------- K0: init ----------------
__global__ void k_init(int N) {
    int i = blockIdx.x * blockDim.x + threadIdx.x;
    if (i < N * 4) {
        g_nodemax[i] = __int_as_float(0xff800000);
        g_expsum[i]  = 0.f;
    }
    if (i < N) g_counts[i] = 0;
}

// ---------------- K_wprep: W_xmix transpose + split ----------------
__global__ void k_wprep(const float* __restrict__ W_xmix) {
    int i = blockIdx.x * 256 + threadIdx.x;
    int n = i >> 8, k = i & 255;
    float w = W_xmix[k * 256 + n];
    __nv_bfloat16 wh = __float2bfloat16(w);
    __nv_bfloat16 wl = __float2bfloat16(w - __bfloat162float(wh));
    g_wh[n * 256 + k] = wh;
    g_wl[n * 256 + k] = wl;
}

// ---------------- K_eprep: edge-MLP weight transpose + split (12288 u32 pairs) ----------------
__global__ void k_eprep(const float* __restrict__ W_in, const float* __restrict__ W_out1,
                        const float* __restrict__ W_out2) {
    int i = blockIdx.x * 256 + threadIdx.x;
    if (i < 4096) {                       // Wi: n 0..63, kp 0..63 (k=2kp)
        int n = i >> 6, k0 = (i & 63) * 2;
        float w0 = (n < 50) ? W_in[k0 * 50 + n] : 0.f;
        float w1 = (n < 50) ? W_in[(k0 + 1) * 50 + n] : 0.f;
        split2(w0, w1, g_ewi_h[i], g_ewi_l[i]);
    } else if (i < 8192) {                // W1a
        int j = i - 4096;
        int n = j >> 6, k0 = (j & 63) * 2;
        split2(W_out1[k0 * 64 + n], W_out1[(k0 + 1) * 64 + n], g_ew1a_h[j], g_ew1a_l[j]);
    } else if (i < 10240) {               // W1b: k<50 -> row 128+k, k==50 -> row 178, else 0
        int j = i - 8192;
        int n = j >> 5, k0 = (j & 31) * 2;
        float w0 = (k0 < 50) ? W_out1[(128 + k0) * 64 + n] : ((k0 == 50) ? W_out1[178 * 64 + n] : 0.f);
        int k1 = k0 + 1;
        float w1 = (k1 < 50) ? W_out1[(128 + k1) * 64 + n] : ((k1 == 50) ? W_out1[178 * 64 + n] : 0.f);
        split2(w0, w1, g_ew1b_h[j], g_ew1b_l[j]);
    } else if (i < 12288) {               // W2
        int j = i - 10240;
        int n = j >> 5, k0 = (j & 31) * 2;
        split2(W_out2[k0 * 64 + n], W_out2[(k0 + 1) * 64 + n], g_ew2_h[j], g_ew2_l[j]);
    }
}

// ---------------- K1: edge MLP via mma.sync (64-edge persistent tiles) ----------------
// smem u32 offsets
#define O_AH    0
#define O_AL    4352
#define O_XH    8704
#define O_XL    11008
#define O_MH    13312
#define O_ML    15616
#define O_WIH   17920
#define O_WIL   22272
#define O_W1AH  26624
#define O_W1AL  30976
#define O_W1BH  35328
#define O_W1BL  37632
#define O_W2H   39936
#define O_W2L   42240
#define O_HE    44544
#define O_BIN   48768
#define O_BO1   48832
#define O_BO2   48896
#define O_MEAN  48960
#define O_BETA  49024
#define O_WA    49088
#define O_BA    49344
#define O_NORM  49348
#define O_EX    49412
#define O_XHT   49476
#define E_SMEM  (49668 * 4)

__global__ void __launch_bounds__(256, 1)
k_edge_mma(const float* __restrict__ h, const float* __restrict__ x,
           const int* __restrict__ idxs,
           const float* __restrict__ rbf_means, const float* __restrict__ rbf_betas,
           const float* __restrict__ b_in, const float* __restrict__ b_out1,
           const float* __restrict__ b_out2,
           const float* __restrict__ W_att, const float* __restrict__ b_att, int E)
{
    extern __shared__ uint32_t su[];
    float* sf = (float*)su;
    int tid = threadIdx.x, lid = tid & 31, wid = tid >> 5;
    int g = lid >> 2, tg = lid & 3;
    int mrow = (wid & 3) * 16, ncol = (wid >> 2) * 32;

    // stage weights once
    for (int i = tid; i < 4096; i += 256) {
        int n = i >> 6, kk = i & 63;
        su[O_WIH  + n * 68 + kk] = g_ewi_h[i];
        su[O_WIL  + n * 68 + kk] = g_ewi_l[i];
        su[O_W1AH + n * 68 + kk] = g_ew1a_h[i];
        su[O_W1AL + n * 68 + kk] = g_ew1a_l[i];
    }
    for (int i = tid; i < 2048; i += 256) {
        int n = i >> 5, kk = i & 31;
        su[O_W1BH + n * 36 + kk] = g_ew1b_h[i];
        su[O_W1BL + n * 36 + kk] = g_ew1b_l[i];
        su[O_W2H  + n * 36 + kk] = g_ew2_h[i];
        su[O_W2L  + n * 36 + kk] = g_ew2_l[i];
    }
    if (tid < 64) {
        sf[O_BIN + tid]  = (tid < 50) ? b_in[tid] : 0.f;
        sf[O_BO1 + tid]  = b_out1[tid];
        sf[O_BO2 + tid]  = b_out2[tid];
        sf[O_MEAN + tid] = (tid < 50) ? rbf_means[tid] : 0.f;
        sf[O_BETA + tid] = (tid < 50) ? rbf_betas[tid] : 1.f;
    }
    if (tid < 256) sf[O_WA + tid] = W_att[tid];
    if (tid < 4)   sf[O_BA + tid] = b_att[tid];
    __syncthreads();

    int ntiles = (E + 63) / 64;
    for (int tile = blockIdx.x; tile < ntiles; tile += gridDim.x) {
        int e0 = tile * 64, ne = min(64, E - e0);

        // norms / xhat / ex
        if (tid < 64) {
            float nrm = 0.f, xh0 = 0.f, xh1 = 0.f, xh2 = 0.f;
            if (tid < ne) {
                int s = idxs[2 * (e0 + tid)], d = idxs[2 * (e0 + tid) + 1];
                float dx = x[3 * s]     - x[3 * d];
                float dy = x[3 * s + 1] - x[3 * d + 1];
                float dz = x[3 * s + 2] - x[3 * d + 2];
                nrm = sqrtf(dx * dx + dy * dy + dz * dz + 1e-14f);
                float inv = 1.f / (nrm + 1e-5f);
                xh0 = dx * inv; xh1 = dy * inv; xh2 = dz * inv;
                atomicAdd(&g_counts[s], 1);
            }
            sf[O_NORM + tid] = nrm;
            sf[O_EX + tid]   = __expf(-nrm);
            sf[O_XHT + tid * 3] = xh0; sf[O_XHT + tid * 3 + 1] = xh1; sf[O_XHT + tid * 3 + 2] = xh2;
        }
        // build hcat bf16 hi/lo (stride 68 u32)
        {
            int el = tid >> 2, part = tid & 3;
            uint32_t hb[16], lb[16];
            if (el < ne) {
                int node = idxs[2 * (e0 + el) + (part >> 1)];
                const float4* hp = (const float4*)&h[node * 64 + (part & 1) * 32];
                #pragma unroll
                for (int i2 = 0; i2 < 8; i2++) {
                    float4 v = hp[i2];
                    split2(v.x, v.y, hb[i2 * 2],     lb[i2 * 2]);
                    split2(v.z, v.w, hb[i2 * 2 + 1], lb[i2 * 2 + 1]);
                }
            } else {
                #pragma unroll
                for (int i2 = 0; i2 < 16; i2++) { hb[i2] = 0u; lb[i2] = 0u; }
            }
            uint4* dh = (uint4*)&su[O_AH + el * 68 + part * 16];
            uint4* dl = (uint4*)&su[O_AL + el * 68 + part * 16];
            #pragma unroll
            for (int i2 = 0; i2 < 4; i2++) {
                dh[i2] = make_uint4(hb[i2*4], hb[i2*4+1], hb[i2*4+2], hb[i2*4+3]);
                dl[i2] = make_uint4(lb[i2*4], lb[i2*4+1], lb[i2*4+2], lb[i2*4+3]);
            }
        }
        __syncthreads();

        float acc[4][4];

        // ---- G1: h_in = hcat @ Wi  (K=128) ----
        #pragma unroll
        for (int nt = 0; nt < 4; nt++)
            #pragma unroll
            for (int q = 0; q < 4; q++) acc[nt][q] = 0.f;
        #pragma unroll
        for (int ks = 0; ks < 8; ks++) {
            uint32_t aH[4], aL[4];
            int ra = (mrow + g) * 68 + ks * 8 + tg;
            aH[0] = su[O_AH + ra];           aH[1] = su[O_AH + ra + 8 * 68];
            aH[2] = su[O_AH + ra + 4];       aH[3] = su[O_AH + ra + 8 * 68 + 4];
            aL[0] = su[O_AL + ra];           aL[1] = su[O_AL + ra + 8 * 68];
            aL[2] = su[O_AL + ra + 4];       aL[3] = su[O_AL + ra + 8 * 68 + 4];
            #pragma unroll
            for (int nt = 0; nt < 4; nt++) {
                int nb = (ncol + nt * 8 + g) * 68 + ks * 8 + tg;
                uint32_t bH[2] = { su[O_WIH + nb], su[O_WIH + nb + 4] };
                uint32_t bL[2] = { su[O_WIL + nb], su[O_WIL + nb + 4] };
                mma16816(acc[nt], aH, bH);
                mma16816(acc[nt], aL, bH);
                mma16816(acc[nt], aH, bL);
            }
        }
        // epilogue: _x = rbf * (h_in + b_in); col50 = norm; else 0
        #pragma unroll
        for (int nt = 0; nt < 4; nt++) {
            #pragma unroll
            for (int hh = 0; hh < 2; hh++) {
                int row = mrow + g + hh * 8;
                int c0 = ncol + nt * 8 + tg * 2;
                float v0 = acc[nt][hh * 2]     + sf[O_BIN + c0];
                float v1 = acc[nt][hh * 2 + 1] + sf[O_BIN + c0 + 1];
                float ex = sf[O_EX + row];
                float x0, x1;
                if (c0 < 50) { float d = ex - sf[O_MEAN + c0]; x0 = __expf(-sf[O_BETA + c0] * d * d) * v0; }
                else x0 = (c0 == 50) ? sf[O_NORM + row] : 0.f;
                if (c0 + 1 < 50) { float d = ex - sf[O_MEAN + c0 + 1]; x1 = __expf(-sf[O_BETA + c0 + 1] * d * d) * v1; }
                else x1 = 0.f;
                uint32_t hi, lo; split2(x0, x1, hi, lo);
                su[O_XH + row * 36 + (c0 >> 1)] = hi;
                su[O_XL + row * 36 + (c0 >> 1)] = lo;
            }
        }
        __syncthreads();

        // ---- G2: mid = silu(hcat@W1a + _x@W1b + b1) ----
        #pragma unroll
        for (int nt = 0; nt < 4; nt++)
            #pragma unroll
            for (int q = 0; q < 4; q++) acc[nt][q] = 0.f;
        #pragma unroll
        for (int ks = 0; ks < 8; ks++) {
            uint32_t aH[4], aL[4];
            int ra = (mrow + g) * 68 + ks * 8 + tg;
            aH[0] = su[O_AH + ra];           aH[1] = su[O_AH + ra + 8 * 68];
            aH[2] = su[O_AH + ra + 4];       aH[3] = su[O_AH + ra + 8 * 68 + 4];
            aL[0] = su[O_AL + ra];           aL[1] = su[O_AL + ra + 8 * 68];
            aL[2] = su[O_AL + ra + 4];       aL[3] = su[O_AL + ra + 8 * 68 + 4];
            #pragma unroll
            for (int nt = 0; nt < 4; nt++) {
                int nb = (ncol + nt * 8 + g) * 68 + ks * 8 + tg;
                uint32_t bH[2] = { su[O_W1AH + nb], su[O_W1AH + nb + 4] };
                uint32_t bL[2] = { su[O_W1AL + nb], su[O_W1AL + nb + 4] };
                mma16816(acc[nt], aH, bH);
                mma16816(acc[nt], aL, bH);
                mma16816(acc[nt], aH, bL);
            }
        }
        #pragma unroll
        for (int ks = 0; ks < 4; ks++) {
            uint32_t aH[4], aL[4];
            int ra = (mrow + g) * 36 + ks * 8 + tg;
            aH[0] = su[O_XH + ra];           aH[1] = su[O_XH + ra + 8 * 36];
            aH[2] = su[O_XH + ra + 4];       aH[3] = su[O_XH + ra + 8 * 36 + 4];
            aL[0] = su[O_XL + ra];           aL[1] = su[O_XL + ra + 8 * 36];
            aL[2] = su[O_XL + ra + 4];       aL[3] = su[O_XL + ra + 8 * 36 + 4];
            #pragma unroll
            for (int nt = 0; nt < 4; nt++) {
                int nb = (ncol + nt * 8 + g) * 36 + ks * 8 + tg;
                uint32_t bH[2] = { su[O_W1BH + nb], su[O_W1BH + nb + 4] };
                uint32_t bL[2] = { su[O_W1BL + nb], su[O_W1BL + nb + 4] };
                mma16816(acc[nt], aH, bH);
                mma16816(acc[nt], aL, bH);
                mma16816(acc[nt], aH, bL);
            }
        }
        #pragma unroll
        for (int nt = 0; nt < 4; nt++) {
            #pragma unroll
            for (int hh = 0; hh < 2; hh++) {
                int row = mrow + g + hh * 8;
                int c0 = ncol + nt * 8 + tg * 2;
                float m0 = siluf(acc[nt][hh * 2]     + sf[O_BO1 + c0]);
                float m1 = siluf(acc[nt][hh * 2 + 1] + sf[O_BO1 + c0 + 1]);
                uint32_t hi, lo; split2(m0, m1, hi, lo);
                su[O_MH + row * 36 + (c0 >> 1)] = hi;
                su[O_ML + row * 36 + (c0 >> 1)] = lo;
            }
        }
        __syncthreads();

        // ---- G3: h_e = mid @ W2 + b2 ----
        #pragma unroll
        for (int nt = 0; nt < 4; nt++)
            #pragma unroll
            for (int q = 0; q < 4; q++) acc[nt][q] = 0.f;
        #pragma unroll
        for (int ks = 0; ks < 4; ks++) {
            uint32_t aH[4], aL[4];
            int ra = (mrow + g) * 36 + ks * 8 + tg;
            aH[0] = su[O_MH + ra];           aH[1] = su[O_MH + ra + 8 * 36];
            aH[2] = su[O_MH + ra + 4];       aH[3] = su[O_MH + ra + 8 * 36 + 4];
            aL[0] = su[O_ML + ra];           aL[1] = su[O_ML + ra + 8 * 36];
            aL[2] = su[O_ML + ra + 4];       aL[3] = su[O_ML + ra + 8 * 36 + 4];
            #pragma unroll
            for (int nt = 0; nt < 4; nt++) {
                int nb = (ncol + nt * 8 + g) * 36 + ks * 8 + tg;
                uint32_t bH[2] = { su[O_W2H + nb], su[O_W2H + nb + 4] };
                uint32_t bL[2] = { su[O_W2L + nb], su[O_W2L + nb + 4] };
                mma16816(acc[nt], aH, bH);
                mma16816(acc[nt], aL, bH);
                mma16816(acc[nt], aH, bL);
            }
        }
        #pragma unroll
        for (int nt = 0; nt < 4; nt++) {
            #pragma unroll
            for (int hh = 0; hh < 2; hh++) {
                int row = mrow + g + hh * 8;
                int c0 = ncol + nt * 8 + tg * 2;
                float h0 = acc[nt][hh * 2]     + sf[O_BO2 + c0];
                float h1 = acc[nt][hh * 2 + 1] + sf[O_BO2 + c0 + 1];
                sf[O_HE + row * 66 + c0]     = h0;
                sf[O_HE + row * 66 + c0 + 1] = h1;
            }
        }
        __syncthreads();

        // att logits + global h_e_mtx writeback (coalesced) + xhat
        {
            int el = tid >> 2, a = tid & 3;
            if (el < ne) {
                float acc2 = sf[O_BA + a];
                const float* hv = &sf[O_HE + el * 66];
                #pragma unroll 8
                for (int c = 0; c < 64; c++) acc2 += hv[c] * sf[O_WA + c * 4 + a];
                float lg = (acc2 > 0.f) ? acc2 : 2.f * (__expf(acc2 * 0.5f) - 1.f);
                int s = idxs[2 * (e0 + el)];
                g_w[(e0 + el) * 4 + a] = lg;
                atomicMaxF(&g_nodemax[s * 4 + a], lg);
            }
        }
        for (int i = tid; i < ne * 16; i += 256) {
            int el = i >> 4, c = (i & 15) * 4;
            float4 o = make_float4(sf[O_HE + el * 66 + c], sf[O_HE + el * 66 + c + 1],
                                   sf[O_HE + el * 66 + c + 2], sf[O_HE + el * 66 + c + 3]);
            *(float4*)&g_hemtx[(size_t)(e0 + el) * 64 + c] = o;
        }
        for (int i = tid; i < ne * 3; i += 256) g_xhat[e0 * 3 + i] = sf[O_XHT + i];
        __syncthreads();
    }
}

// ---------------- K2: exclusive scan ----------------
__global__ void k_scan(int N) {
    __shared__ int ssum[1024];
    int t = threadIdx.x;
    int chunk = (N + 1023) / 1024;
    int base = t * chunk;
    int vals[16];
    int loc = 0;
    for (int k = 0; k < chunk; k++) {
        int idx = base + k;
        int v = (idx < N) ? g_counts[idx] : 0;
        vals[k] = loc; loc += v;
    }
    ssum[t] = loc; __syncthreads();
    for (int off = 1; off < 1024; off <<= 1) {
        int v = (t >= off) ? ssum[t - off] : 0;
        __syncthreads();
        ssum[t] += v;
        __syncthreads();
    }
    int excl = ssum[t] - loc;
    for (int k = 0; k < chunk; k++) {
        int idx = base + k;
        if (idx < N) { g_off[idx] = excl + vals[k]; g_cursor[idx] = excl + vals[k]; }
    }
    if (t == 1023) g_off[N] = excl + loc;
}

// ---------------- K3: CSR fill ----------------
__global__ void k_fill(const int* __restrict__ idxs, int E) {
    int e = blockIdx.x * blockDim.x + threadIdx.x;
    if (e < E) {
        int s = idxs[2 * e];
        int p = atomicAdd(&g_cursor[s], 1);
        g_eid[p] = e;
    }
}

// ---------------- K4: exp + expsum ----------------
__global__ void k_exp(const int* __restrict__ idxs, int E) {
    int i = blockIdx.x * blockDim.x + threadIdx.x;
    if (i >= E * 4) return;
    int e = i >> 2, a = i & 3;
    int s = idxs[2 * e];
    float w = __expf(g_w[i] - g_nodemax[s * 4 + a]);
    g_w[i] = w;
    atomicAdd(&g_expsum[s * 4 + a], w);
}

// ---------------- K5: xmix via mma.sync bf16 (3-term split) ----------------
#define XS_AH 0
#define XS_AL (64 * 264)
#define XS_WH (2 * 64 * 264)
#define XS_WL (2 * 64 * 264 + 256 * 72)
#define X_ELEMS (2 * 64 * 264 + 2 * 256 * 72)
#define X_SMEM (X_ELEMS * 2)

__global__ void __launch_bounds__(256, 1)
k_xmix_mma(const int* __restrict__ idxs, int E)
{
    extern __shared__ __nv_bfloat16 smx[];
    int tid = threadIdx.x;
    int lid = tid & 31, wid = tid >> 5;
    int e0 = blockIdx.x * 64;
    int ne = min(64, E - e0);

    uint32_t* pAh = (uint32_t*)(smx + XS_AH);
    uint32_t* pAl = (uint32_t*)(smx + XS_AL);
    uint32_t* pWh = (uint32_t*)(smx + XS_WH);
    uint32_t* pWl = (uint32_t*)(smx + XS_WL);

    {
        int el = tid & 63, kq = tid >> 6;
        float att[4], hm[16];
        if (el < ne) {
            int e = e0 + el;
            int s = idxs[2 * e];
            #pragma unroll
            for (int a = 0; a < 4; a++) att[a] = g_w[e * 4 + a] / g_expsum[s * 4 + a];
            const float4* hp = (const float4*)&g_hemtx[(size_t)e * 64 + kq * 16];
            #pragma unroll
            for (int i = 0; i < 4; i++) {
                float4 v = hp[i];
                hm[i * 4] = v.x; hm[i * 4 + 1] = v.y; hm[i * 4 + 2] = v.z; hm[i * 4 + 3] = v.w;
            }
        } else {
            #pragma unroll
            for (int a = 0; a < 4; a++) att[a] = 0.f;
            #pragma unroll
            for (int i = 0; i < 16; i++) hm[i] = 0.f;
        }
        #pragma unroll
        for (int j = 0; j < 32; j++) {
            int kl = 2 * j;
            float m = hm[kl >> 2];
            float a0 = m * att[kl & 3];
            float a1 = m * att[(kl + 1) & 3];
            uint32_t ph, pl;
            split2(a0, a1, ph, pl);
            int idx32 = el * 132 + ((kq * 64 + kl) >> 1);
            pAh[idx32] = ph;
            pAl[idx32] = pl;
        }
    }

    int g = lid >> 2, tg = lid & 3;
    int mrow = (wid & 1) * 32;
    int ncol = (wid >> 1) * 64;

    float acc[2][8][4];
    #pragma unroll
    for (int mt = 0; mt < 2; mt++)
        #pragma unroll
        for (int nt = 0; nt < 8; nt++)
            #pragma unroll
            for (int q = 0; q < 4; q++) acc[mt][nt][q] = 0.f;

    for (int kc = 0; kc < 4; kc++) {
        __syncthreads();
        {
            int n = tid;
            const uint4* srch = (const uint4*)&g_wh[n * 256 + kc * 64];
            const uint4* srcl = (const uint4*)&g_wl[n * 256 + kc * 64];
            uint4* dsth = (uint4*)(pWh + n * 36);
            uint4* dstl = (uint4*)(pWl + n * 36);
            #pragma unroll
            for (int i = 0; i < 8; i++) { dsth[i] = srch[i]; dstl[i] = srcl[i]; }
        }
        __syncthreads();

        #pragma unroll
        for (int ks = 0; ks < 4; ks++) {
            int kA = kc * 64 + ks * 16;
            uint32_t aH[2][4], aL[2][4];
            #pragma unroll
            for (int mt = 0; mt < 2; mt++) {
                int r0 = mrow + mt * 16 + g;
                int c0h = (kA + tg * 2) >> 1;
                aH[mt][0] = pAh[r0 * 132 + c0h];
                aH[mt][1] = pAh[(r0 + 8) * 132 + c0h];
                aH[mt][2] = pAh[r0 * 132 + c0h + 4];
                aH[mt][3] = pAh[(r0 + 8) * 132 + c0h + 4];
                aL[mt][0] = pAl[r0 * 132 + c0h];
                aL[mt][1] = pAl[(r0 + 8) * 132 + c0h];
                aL[mt][2] = pAl[r0 * 132 + c0h + 4];
                aL[mt][3] = pAl[(r0 + 8) * 132 + c0h + 4];
            }
            uint32_t bH[8][2], bL[8][2];
            #pragma unroll
            for (int nt = 0; nt < 8; nt++) {
                int n = ncol + nt * 8 + g;
                int ckh = (ks * 16 + tg * 2) >> 1;
                bH[nt][0] = pWh[n * 36 + ckh];
                bH[nt][1] = pWh[n * 36 + ckh + 4];
                bL[nt][0] = pWl[n * 36 + ckh];
                bL[nt][1] = pWl[n * 36 + ckh + 4];
            }
            #pragma unroll
            for (int mt = 0; mt < 2; mt++)
                #pragma unroll
                for (int nt = 0; nt < 8; nt++) {
                    mma16816(acc[mt][nt], aH[mt], bH[nt]);
                    mma16816(acc[mt][nt], aL[mt], bH[nt]);
                    mma16816(acc[mt][nt], aH[mt], bL[nt]);
                }
        }
    }

    #pragma unroll
    for (int mt = 0; mt < 2; mt++)
        #pragma unroll
        for (int nt = 0; nt < 8; nt++) {
            int rl = mrow + mt * 16 + g;
            int col = ncol + nt * 8 + tg * 2;
            float* a = acc[mt][nt];
            if (rl < ne) {
                float2 o = make_float2(fast_tanh(a[0]), fast_tanh(a[1]));
                *(float2*)&g_coeff[(size_t)(e0 + rl) * 256 + col] = o;
            }
            if (rl + 8 < ne) {
                float2 o = make_float2(fast_tanh(a[2]), fast_tanh(a[3]));
                *(float2*)&g_coeff[(size_t)(e0 + rl + 8) * 256 + col] = o;
            }
        }
}

// ---------------- K6: per-node aggregation ----------------
__global__ void k_agg(const float* __restrict__ W_vmix, int N) {
    __shared__ float red[24];
    int n = blockIdx.x;
    int c = threadIdx.x;
    int lid = c & 31, wid = c >> 5;
    int beg = g_off[n], end = g_off[n + 1];
    float invs = 1.f / g_expsum[n * 4 + (c & 3)];
    float accH = 0.f, a0 = 0.f, a1 = 0.f, a2 = 0.f;
    for (int i = beg; i < end; i++) {
        int e = g_eid[i];
        float att = g_w[e * 4 + (c & 3)] * invs;
        accH += g_hemtx[(size_t)e * 64 + (c >> 2)] * att;
        float cf = g_coeff[(size_t)e * 256 + c];
        float x0 = g_xhat[e * 3], x1 = g_xhat[e * 3 + 1], x2 = g_xhat[e * 3 + 2];
        a0 += cf * x0; a1 += cf * x1; a2 += cf * x2;
    }
    float cnt = (float)(end - beg);
    float invc = 1.f / (cnt + 1.f);
    float s0 = a0 * invc, s1 = a1 * invc, s2 = a2 * invc;
    g_he[n * 256 + c] = accH;
    g_cnorm[n * 256 + c] = s0 * s0 + s1 * s1 + s2 * s2;

    float wv = W_vmix[c];
    float r0 = wv * a0, r1 = wv * a1, r2 = wv * a2;
    #pragma unroll
    for (int o = 16; o > 0; o >>= 1) {
        r0 += __shfl_xor_sync(0xFFFFFFFFu, r0, o);
        r1 += __shfl_xor_sync(0xFFFFFFFFu, r1, o);
        r2 += __shfl_xor_sync(0xFFFFFFFFu, r2, o);
    }
    if (lid == 0) { red[wid * 3] = r0; red[wid * 3 + 1] = r1; red[wid * 3 + 2] = r2; }
    __syncthreads();
    if (c < 3) {
        float s = 0.f;
        #pragma unroll
        for (int w = 0; w < 8; w++) s += red[w * 3 + c];
        g_dv[n * 3 + c] = s * invc;
    }
}

// ---------------- K7: node MLPs ----------------
__global__ void k_node(const float* __restrict__ h, const float* __restrict__ x,
                       const float* __restrict__ v,
                       const float* __restrict__ W_post1, const float* __restrict__ b_post1,
                       const float* __restrict__ W_post2, const float* __restrict__ b_post2,
                       const float* __restrict__ W_node1, const float* __restrict__ b_node1,
                       const float* __restrict__ W_node2, const float* __restrict__ b_node2,
                       const float* __restrict__ W_vel1,  const float* __restrict__ b_vel1,
                       const float* __restrict__ W_vel2,
                       float* __restrict__ out_h, float* __restrict__ out_x,
                       float* __restrict__ out_v, int N)
{
    extern __shared__ float sm[];
    float* sCN = sm;
    float* sHE = sCN + 8192;
    float* sH  = sHE + 8192;
    float* sT  = sH  + 2048;
    float* sHC = sT  + 2048;
    float* sHN = sHC + 2048;
    float* sBp1 = sHN + 2048;
    float* sBp2 = sBp1 + 64;
    float* sBn1 = sBp2 + 64;
    float* sBn2 = sBn1 + 64;
    float* sBv1 = sBn2 + 64;
    float* sWv2 = sBv1 + 64;
    float* sWbuf = sWv2 + 64;

    int tid = threadIdx.x;
    int n0 = blockIdx.x * 32;
    int nn = min(32, N - n0);

    for (int i = tid; i < nn * 256; i += 256) { sCN[i] = g_cnorm[n0 * 256 + i]; sHE[i] = g_he[n0 * 256 + i]; }
    for (int i = tid; i < nn * 64;  i += 256) sH[i] = h[n0 * 64 + i];
    if (tid < 64) {
        sBp1[tid] = b_post1[tid]; sBp2[tid] = b_post2[tid];
        sBn1[tid] = b_node1[tid]; sBn2[tid] = b_node2[tid];
        sBv1[tid] = b_vel1[tid];  sWv2[tid] = W_vel2[tid];
    }
    __syncthreads();

    for (int i = tid; i < 16384; i += 256) sWbuf[i] = W_post1[i];
    __syncthreads();
    for (int i = tid; i < nn * 16; i += 256) {
        int ln = i >> 4, j0 = (i & 15) * 4;
        float a0 = sBp1[j0], a1 = sBp1[j0 + 1], a2 = sBp1[j0 + 2], a3 = sBp1[j0 + 3];
        const float* cv = &sCN[ln * 256];
        #pragma unroll 4
        for (int c = 0; c < 256; c++) {
            float hv = cv[c];
            float4 w = *(const float4*)&sWbuf[c * 64 + j0];
            a0 += hv * w.x; a1 += hv * w.y; a2 += hv * w.z; a3 += hv * w.w;
        }
        float* o = &sT[ln * 64 + j0];
        o[0] = siluf(a0); o[1] = siluf(a1); o[2] = siluf(a2); o[3] = siluf(a3);
    }
    __syncthreads();

    for (int i = tid; i < 4096; i += 256) sWbuf[i] = W_post2[i];
    __syncthreads();
    for (int i = tid; i < nn * 16; i += 256) {
        int ln = i >> 4, j0 = (i & 15) * 4;
        float a0 = sBp2[j0], a1 = sBp2[j0 + 1], a2 = sBp2[j0 + 2], a3 = sBp2[j0 + 3];
        const float* tv = &sT[ln * 64];
        #pragma unroll 4
        for (int c = 0; c < 64; c++) {
            float hv = tv[c];
            float4 w = *(const float4*)&sWbuf[c * 64 + j0];
            a0 += hv * w.x; a1 += hv * w.y; a2 += hv * w.z; a3 += hv * w.w;
        }
        float* o = &sHC[ln * 64 + j0];
        o[0] = siluf(a0); o[1] = siluf(a1); o[2] = siluf(a2); o[3] = siluf(a3);
    }
    __syncthreads();

    for (int i = tid; i < 24576; i += 256) sWbuf[i] = W_node1[i];
    __syncthreads();
    for (int i = tid; i < nn * 16; i += 256) {
        int ln = i >> 4, j0 = (i & 15) * 4;
        float a0 = sBn1[j0], a1 = sBn1[j0 + 1], a2 = sBn1[j0 + 2], a3 = sBn1[j0 + 3];
        const float* hv2 = &sH[ln * 64];
        #pragma unroll 4
        for (int c = 0; c < 64; c++) {
            float hv = hv2[c];
            float4 w = *(const float4*)&sWbuf[c * 64 + j0];
            a0 += hv * w.x; a1 += hv * w.y; a2 += hv * w.z; a3 += hv * w.w;
        }
        const float* he = &sHE[ln * 256];
        #pragma unroll 4
        for (int c = 0; c < 256; c++) {
            float hv = he[c];
            float4 w = *(const float4*)&sWbuf[(64 + c) * 64 + j0];
            a0 += hv * w.x; a1 += hv * w.y; a2 += hv * w.z; a3 += hv * w.w;
        }
        const float* hc = &sHC[ln * 64];
        #pragma unroll 4
        for (int c = 0; c < 64; c++) {
            float hv = hc[c];
            float4 w = *(const float4*)&sWbuf[(320 + c) * 64 + j0];
            a0 += hv * w.x; a1 += hv * w.y; a2 += hv * w.z; a3 += hv * w.w;
        }
        float* o = &sT[ln * 64 + j0];
        o[0] = siluf(a0); o[1] = siluf(a1); o[2] = siluf(a2); o[3] = siluf(a3);
    }
    __syncthreads();

    for (int i = tid; i < 4096; i += 256) sWbuf[i] = W_node2[i];
    __syncthreads();
    for (int i = tid; i < nn * 16; i += 256) {
        int ln = i >> 4, j0 = (i & 15) * 4;
        float a0 = sBn2[j0], a1 = sBn2[j0 + 1], a2 = sBn2[j0 + 2], a3 = sBn2[j0 + 3];
        const float* tv = &sT[ln * 64];
        #pragma unroll 4
        for (int c = 0; c < 64; c++) {
            float hv = tv[c];
            float4 w = *(const float4*)&sWbuf[c * 64 + j0];
            a0 += hv * w.x; a1 += hv * w.y; a2 += hv * w.z; a3 += hv * w.w;
        }
        int n = n0 + ln;
        float h0 = sH[ln * 64 + j0]     + siluf(a0);
        float h1 = sH[ln * 64 + j0 + 1] + siluf(a1);
        float h2 = sH[ln * 64 + j0 + 2] + siluf(a2);
        float h3 = sH[ln * 64 + j0 + 3] + siluf(a3);
        float* o = &sHN[ln * 64 + j0];
        o[0] = h0; o[1] = h1; o[2] = h2; o[3] = h3;
        *(float4*)&out_h[n * 64 + j0] = make_float4(h0, h1, h2, h3);
    }
    __syncthreads();

    for (int i = tid; i < 4096; i += 256) sWbuf[i] = W_vel1[i];
    __syncthreads();
    for (int i = tid; i < nn * 16; i += 256) {
        int ln = i >> 4, j0 = (i & 15) * 4;
        float a0 = sBv1[j0], a1 = sBv1[j0 + 1], a2 = sBv1[j0 + 2], a3 = sBv1[j0 + 3];
        const float* hv2 = &sHN[ln * 64];
        #pragma unroll 4
        for (int c = 0; c < 64; c++) {
            float hv = hv2[c];
            float4 w = *(const float4*)&sWbuf[c * 64 + j0];
            a0 += hv * w.x; a1 += hv * w.y; a2 += hv * w.z; a3 += hv * w.w;
        }
        float* o = &sT[ln * 64 + j0];
        o[0] = siluf(a0) * sWv2[j0];
        o[1] = siluf(a1) * sWv2[j0 + 1];
        o[2] = siluf(a2) * sWv2[j0 + 2];
        o[3] = siluf(a3) * sWv2[j0 + 3];
    }
    __syncthreads();

    if (tid < nn) {
        int ln = tid;
        float s = 0.f;
        #pragma unroll 8
        for (int k = 0; k < 64; k++) s += sT[ln * 64 + k];
        float scale = 2.f / (1.f + __expf(-s));
        int n = n0 + ln;
        #pragma unroll
        for (int d = 0; d < 3; d++) {
            float vn = g_dv[n * 3 + d] + scale * v[n * 3 + d];
            out_v[n * 3 + d] = vn;
            out_x[n * 3 + d] = x[n * 3 + d] + vn;
        }
    }
}

// ---------------- launch ----------------
extern "C" void kernel_launch(void* const* d_in, const int* in_sizes, int n_in,
                              void* d_out, int out_size)
{
    const float* h        = (const float*)d_in[0];
    const float* x        = (const float*)d_in[1];
    const float* v        = (const float*)d_in[2];
    const int*   idxs     = (const int*)  d_in[3];
    const float* rbf_mean = (const float*)d_in[4];
    const float* rbf_beta = (const float*)d_in[5];
    const float* W_in     = (const float*)d_in[6];
    const float* b_in     = (const float*)d_in[7];
    const float* W_out1   = (const float*)d_in[8];
    const float* b_out1   = (const float*)d_in[9];
    const float* W_out2   = (const float*)d_in[10];
    const float* b_out2   = (const float*)d_in[11];
    const float* W_att    = (const float*)d_in[12];
    const float* b_att    = (const float*)d_in[13];
    const float* W_xmix   = (const float*)d_in[14];
    const float* W_post1  = (const float*)d_in[15];
    const float* b_post1  = (const float*)d_in[16];
    const float* W_post2  = (const float*)d_in[17];
    const float* b_post2  = (const float*)d_in[18];
    const float* W_node1  = (const float*)d_in[19];
    const float* b_node1  = (const float*)d_in[20];
    const float* W_node2  = (const float*)d_in[21];
    const float* b_node2  = (const float*)d_in[22];
    const float* W_vmix   = (const float*)d_in[23];
    const float* W_vel1   = (const float*)d_in[24];
    const float* b_vel1   = (const float*)d_in[25];
    const float* W_vel2   = (const float*)d_in[26];

    int N = in_sizes[0] / 64;
    int E = in_sizes[3] / 2;

    float* out  = (float*)d_out;
    float* outh = out;
    float* outx = out + (size_t)N * 64;
    float* outv = out + (size_t)N * 67;

    const int SM_NODE = (8192 * 2 + 2048 * 4 + 64 * 6 + 24576) * 4;

    cudaFuncSetAttribute(k_edge_mma, cudaFuncAttributeMaxDynamicSharedMemorySize, E_SMEM);
    cudaFuncSetAttribute(k_xmix_mma, cudaFuncAttributeMaxDynamicSharedMemorySize, X_SMEM);
    cudaFuncSetAttribute(k_node,     cudaFuncAttributeMaxDynamicSharedMemorySize, SM_NODE);

    k_init<<<(N * 4 + 255) / 256, 256>>>(N);
    k_wprep<<<256, 256>>>(W_xmix);
    k_eprep<<<48, 256>>>(W_in, W_out1, W_out2);
    k_edge_mma<<<148, 256, E_SMEM>>>(h, x, idxs, rbf_mean, rbf_beta,
                                     b_in, b_out1, b_out2, W_att, b_att, E);
    k_scan<<<1, 1024>>>(N);
    k_fill<<<(E + 255) / 256, 256>>>(idxs, E);
    k_exp<<<(E * 4 + 255) / 256, 256>>>(idxs, E);
    k_xmix_mma<<<(E + 63) / 64, 256, X_SMEM>>>(idxs, E);
    k_agg<<<N, 256>>>(W_vmix, N);
    k_node<<<(N + 31) / 32, 256, SM_NODE>>>(h, x, v,
                                            W_post1, b_post1, W_post2, b_post2,
                                            W_node1, b_node1, W_node2, b_node2,
                                            W_vel1, b_vel1, W_vel2,
                                            outh, outx, outv, N);
}

// round 6
// speedup vs baseline: 2.8356x; 1.4556x over previous
#include <cuda_runtime.h>
#include <cuda_fp16.h>
#include <stdint.h>
#include <math.h>

#define NMAX 10000
#define EMAX 160000

// ---------------- scratch ----------------
__device__ float g_hemtx[EMAX * 64];
__device__ float g_xhat[EMAX * 3];
__device__ float g_w[EMAX * 4];
__device__ float g_coeff[EMAX * 256];
__device__ float g_nodemax[NMAX * 4];
__device__ float g_expsum[NMAX * 4];
__device__ int   g_counts[NMAX];
__device__ int   g_off[NMAX + 1];
__device__ int   g_cursor[NMAX];
__device__ int   g_eid[EMAX];
__device__ float g_he[NMAX * 256];
__device__ float g_cnorm[NMAX * 256];
__device__ float g_dv[NMAX * 3];
__device__ __half g_wx[256 * 256];                 // W_xmix^T fp16 [n][k]
__device__ uint32_t g_ewi[4096];                   // W_in^T   64x128 fp16x2
__device__ uint32_t g_ew1a[4096];                  // W_out1^T rows 0..127
__device__ uint32_t g_ew1b[2048];                  // W_out1^T rows 128..178 (+norm col 50)
__device__ uint32_t g_ew2[2048];                   // W_out2^T 64x64

__device__ __forceinline__ float siluf(float x) { return x / (1.f + __expf(-x)); }
__device__ __forceinline__ float fast_tanh(float x) {
    float y; asm("tanh.approx.f32 %0, %1;" : "=f"(y) : "f"(x)); return y;
}
__device__ __forceinline__ void atomicMaxF(float* a, float v) {
    if (v >= 0.f) atomicMax((int*)a, __float_as_int(v));
    else          atomicMin((unsigned int*)a, (unsigned int)__float_as_int(v));
}
__device__ __forceinline__ void mma16816h(float* d, const uint32_t* a, const uint32_t* b) {
    asm volatile("mma.sync.aligned.m16n8k16.row.col.f32.f16.f16.f32 "
        "{%0,%1,%2,%3}, {%4,%5,%6,%7}, {%8,%9}, {%0,%1,%2,%3};"
        : "+f"(d[0]), "+f"(d[1]), "+f"(d[2]), "+f"(d[3])
        : "r"(a[0]), "r"(a[1]), "r"(a[2]), "r"(a[3]), "r"(b[0]), "r"(b[1]));
}
__device__ __forceinline__ uint32_t pack2h(float a, float b) {
    __half2 p = __floats2half2_rn(a, b);
    return *(uint32_t*)&p;
}

// ---------------- K0: init ----------------
__global__ void k_init(int N) {
    int i = blockIdx.x * blockDim.x + threadIdx.x;
    if (i < N * 4) {
        g_nodemax[i] = __int_as_float(0xff800000);
        g_expsum[i]  = 0.f;
    }
    if (i < N) g_counts[i] = 0;
}

// ---------------- K_wprep: W_xmix transpose -> fp16 ----------------
__global__ void k_wprep(const float* __restrict__ W_xmix) {
    int i = blockIdx.x * 256 + threadIdx.x;
    int n = i >> 8, k = i & 255;
    g_wx[n * 256 + k] = __float2half_rn(W_xmix[k * 256 + n]);
}

// ---------------- K_eprep: edge-MLP weight transpose -> fp16x2 ----------------
__global__ void k_eprep(const float* __restrict__ W_in, const float* __restrict__ W_out1,
                        const float* __restrict__ W_out2) {
    int i = blockIdx.x * 256 + threadIdx.x;
    if (i < 4096) {
        int n = i >> 6, k0 = (i & 63) * 2;
        float w0 = (n < 50) ? W_in[k0 * 50 + n] : 0.f;
        float w1 = (n < 50) ? W_in[(k0 + 1) * 50 + n] : 0.f;
        g_ewi[i] = pack2h(w0, w1);
    } else if (i < 8192) {
        int j = i - 4096;
        int n = j >> 6, k0 = (j & 63) * 2;
        g_ew1a[j] = pack2h(W_out1[k0 * 64 + n], W_out1[(k0 + 1) * 64 + n]);
    } else if (i < 10240) {
        int j = i - 8192;
        int n = j >> 5, k0 = (j & 31) * 2;
        float w0 = (k0 < 50) ? W_out1[(128 + k0) * 64 + n] : ((k0 == 50) ? W_out1[178 * 64 + n] : 0.f);
        int k1 = k0 + 1;
        float w1 = (k1 < 50) ? W_out1[(128 + k1) * 64 + n] : ((k1 == 50) ? W_out1[178 * 64 + n] : 0.f);
        g_ew1b[j] = pack2h(w0, w1);
    } else if (i < 12288) {
        int j = i - 10240;
        int n = j >> 5, k0 = (j & 31) * 2;
        g_ew2[j] = pack2h(W_out2[k0 * 64 + n], W_out2[(k0 + 1) * 64 + n]);
    }
}

// ---------------- K1: edge MLP via fp16 mma.sync (64-edge persistent tiles) ----------------
// smem u32 offsets
#define O_A     0
#define O_X     4352
#define O_M     6656
#define O_WI    8960
#define O_W1A   13312
#define O_W1B   17664
#define O_W2    19968
#define O_HE    22272
#define O_BIN   26496
#define O_BO1   26560
#define O_BO2   26624
#define O_MEAN  26688
#define O_BETA  26752
#define O_WA    26816
#define O_BA    27072
#define O_NORM  27076
#define O_EX    27140
#define O_XHT   27204
#define E_SMEM  (27400 * 4)

__global__ void __launch_bounds__(256, 2)
k_edge_mma(const float* __restrict__ h, const float* __restrict__ x,
           const int* __restrict__ idxs,
           const float* __restrict__ rbf_means, const float* __restrict__ rbf_betas,
           const float* __restrict__ b_in, const float* __restrict__ b_out1,
           const float* __restrict__ b_out2,
           const float* __restrict__ W_att, const float* __restrict__ b_att, int E)
{
    extern __shared__ uint32_t su[];
    float* sf = (float*)su;
    int tid = threadIdx.x, lid = tid & 31, wid = tid >> 5;
    int g = lid >> 2, tg = lid & 3;
    int mrow = (wid & 3) * 16, ncol = (wid >> 2) * 32;

    for (int i = tid; i < 4096; i += 256) {
        int n = i >> 6, kk = i & 63;
        su[O_WI  + n * 68 + kk] = g_ewi[i];
        su[O_W1A + n * 68 + kk] = g_ew1a[i];
    }
    for (int i = tid; i < 2048; i += 256) {
        int n = i >> 5, kk = i & 31;
        su[O_W1B + n * 36 + kk] = g_ew1b[i];
        su[O_W2  + n * 36 + kk] = g_ew2[i];
    }
    if (tid < 64) {
        sf[O_BIN + tid]  = (tid < 50) ? b_in[tid] : 0.f;
        sf[O_BO1 + tid]  = b_out1[tid];
        sf[O_BO2 + tid]  = b_out2[tid];
        sf[O_MEAN + tid] = (tid < 50) ? rbf_means[tid] : 0.f;
        sf[O_BETA + tid] = (tid < 50) ? rbf_betas[tid] : 1.f;
    }
    if (tid < 256) sf[O_WA + tid] = W_att[tid];
    if (tid < 4)   sf[O_BA + tid] = b_att[tid];
    __syncthreads();

    int ntiles = (E + 63) / 64;
    for (int tile = blockIdx.x; tile < ntiles; tile += gridDim.x) {
        int e0 = tile * 64, ne = min(64, E - e0);

        if (tid < 64) {
            float nrm = 0.f, xh0 = 0.f, xh1 = 0.f, xh2 = 0.f;
            if (tid < ne) {
                int s = idxs[2 * (e0 + tid)], d = idxs[2 * (e0 + tid) + 1];
                float dx = x[3 * s]     - x[3 * d];
                float dy = x[3 * s + 1] - x[3 * d + 1];
                float dz = x[3 * s + 2] - x[3 * d + 2];
                nrm = sqrtf(dx * dx + dy * dy + dz * dz + 1e-14f);
                float inv = 1.f / (nrm + 1e-5f);
                xh0 = dx * inv; xh1 = dy * inv; xh2 = dz * inv;
                atomicAdd(&g_counts[s], 1);
            }
            sf[O_NORM + tid] = nrm;
            sf[O_EX + tid]   = __expf(-nrm);
            sf[O_XHT + tid * 3] = xh0; sf[O_XHT + tid * 3 + 1] = xh1; sf[O_XHT + tid * 3 + 2] = xh2;
        }
        // build hcat fp16 (stride 68 u32)
        {
            int el = tid >> 2, part = tid & 3;
            uint32_t hb[16];
            if (el < ne) {
                int node = idxs[2 * (e0 + el) + (part >> 1)];
                const float4* hp = (const float4*)&h[node * 64 + (part & 1) * 32];
                #pragma unroll
                for (int i2 = 0; i2 < 8; i2++) {
                    float4 v = hp[i2];
                    hb[i2 * 2]     = pack2h(v.x, v.y);
                    hb[i2 * 2 + 1] = pack2h(v.z, v.w);
                }
            } else {
                #pragma unroll
                for (int i2 = 0; i2 < 16; i2++) hb[i2] = 0u;
            }
            uint4* dh = (uint4*)&su[O_A + el * 68 + part * 16];
            #pragma unroll
            for (int i2 = 0; i2 < 4; i2++)
                dh[i2] = make_uint4(hb[i2*4], hb[i2*4+1], hb[i2*4+2], hb[i2*4+3]);
        }
        __syncthreads();

        float acc[4][4];

        // ---- G1: h_in = hcat @ Wi  (K=128) ----
        #pragma unroll
        for (int nt = 0; nt < 4; nt++)
            #pragma unroll
            for (int q = 0; q < 4; q++) acc[nt][q] = 0.f;
        #pragma unroll
        for (int ks = 0; ks < 8; ks++) {
            uint32_t aH[4];
            int ra = (mrow + g) * 68 + ks * 8 + tg;
            aH[0] = su[O_A + ra];       aH[1] = su[O_A + ra + 8 * 68];
            aH[2] = su[O_A + ra + 4];   aH[3] = su[O_A + ra + 8 * 68 + 4];
            #pragma unroll
            for (int nt = 0; nt < 4; nt++) {
                int nb = (ncol + nt * 8 + g) * 68 + ks * 8 + tg;
                uint32_t bH[2] = { su[O_WI + nb], su[O_WI + nb + 4] };
                mma16816h(acc[nt], aH, bH);
            }
        }
        // epilogue: _x = rbf * (h_in + b_in); col50 = norm; else 0
        #pragma unroll
        for (int nt = 0; nt < 4; nt++) {
            #pragma unroll
            for (int hh = 0; hh < 2; hh++) {
                int row = mrow + g + hh * 8;
                int c0 = ncol + nt * 8 + tg * 2;
                float v0 = acc[nt][hh * 2]     + sf[O_BIN + c0];
                float v1 = acc[nt][hh * 2 + 1] + sf[O_BIN + c0 + 1];
                float ex = sf[O_EX + row];
                float x0, x1;
                if (c0 < 50) { float d = ex - sf[O_MEAN + c0]; x0 = __expf(-sf[O_BETA + c0] * d * d) * v0; }
                else x0 = (c0 == 50) ? sf[O_NORM + row] : 0.f;
                if (c0 + 1 < 50) { float d = ex - sf[O_MEAN + c0 + 1]; x1 = __expf(-sf[O_BETA + c0 + 1] * d * d) * v1; }
                else x1 = 0.f;
                su[O_X + row * 36 + (c0 >> 1)] = pack2h(x0, x1);
            }
        }
        __syncthreads();

        // ---- G2: mid = silu(hcat@W1a + _x@W1b + b1) ----
        #pragma unroll
        for (int nt = 0; nt < 4; nt++)
            #pragma unroll
            for (int q = 0; q < 4; q++) acc[nt][q] = 0.f;
        #pragma unroll
        for (int ks = 0; ks < 8; ks++) {
            uint32_t aH[4];
            int ra = (mrow + g) * 68 + ks * 8 + tg;
            aH[0] = su[O_A + ra];       aH[1] = su[O_A + ra + 8 * 68];
            aH[2] = su[O_A + ra + 4];   aH[3] = su[O_A + ra + 8 * 68 + 4];
            #pragma unroll
            for (int nt = 0; nt < 4; nt++) {
                int nb = (ncol + nt * 8 + g) * 68 + ks * 8 + tg;
                uint32_t bH[2] = { su[O_W1A + nb], su[O_W1A + nb + 4] };
                mma16816h(acc[nt], aH, bH);
            }
        }
        #pragma unroll
        for (int ks = 0; ks < 4; ks++) {
            uint32_t aH[4];
            int ra = (mrow + g) * 36 + ks * 8 + tg;
            aH[0] = su[O_X + ra];       aH[1] = su[O_X + ra + 8 * 36];
            aH[2] = su[O_X + ra + 4];   aH[3] = su[O_X + ra + 8 * 36 + 4];
            #pragma unroll
            for (int nt = 0; nt < 4; nt++) {
                int nb = (ncol + nt * 8 + g) * 36 + ks * 8 + tg;
                uint32_t bH[2] = { su[O_W1B + nb], su[O_W1B + nb + 4] };
                mma16816h(acc[nt], aH, bH);
            }
        }
        #pragma unroll
        for (int nt = 0; nt < 4; nt++) {
            #pragma unroll
            for (int hh = 0; hh < 2; hh++) {
                int row = mrow + g + hh * 8;
                int c0 = ncol + nt * 8 + tg * 2;
                float m0 = siluf(acc[nt][hh * 2]     + sf[O_BO1 + c0]);
                float m1 = siluf(acc[nt][hh * 2 + 1] + sf[O_BO1 + c0 + 1]);
                su[O_M + row * 36 + (c0 >> 1)] = pack2h(m0, m1);
            }
        }
        __syncthreads();

        // ---- G3: h_e = mid @ W2 + b2 ----
        #pragma unroll
        for (int nt = 0; nt < 4; nt++)
            #pragma unroll
            for (int q = 0; q < 4; q++) acc[nt][q] = 0.f;
        #pragma unroll
        for (int ks = 0; ks < 4; ks++) {
            uint32_t aH[4];
            int ra = (mrow + g) * 36 + ks * 8 + tg;
            aH[0] = su[O_M + ra];       aH[1] = su[O_M + ra + 8 * 36];
            aH[2] = su[O_M + ra + 4];   aH[3] = su[O_M + ra + 8 * 36 + 4];
            #pragma unroll
            for (int nt = 0; nt < 4; nt++) {
                int nb = (ncol + nt * 8 + g) * 36 + ks * 8 + tg;
                uint32_t bH[2] = { su[O_W2 + nb], su[O_W2 + nb + 4] };
                mma16816h(acc[nt], aH, bH);
            }
        }
        #pragma unroll
        for (int nt = 0; nt < 4; nt++) {
            #pragma unroll
            for (int hh = 0; hh < 2; hh++) {
                int row = mrow + g + hh * 8;
                int c0 = ncol + nt * 8 + tg * 2;
                sf[O_HE + row * 66 + c0]     = acc[nt][hh * 2]     + sf[O_BO2 + c0];
                sf[O_HE + row * 66 + c0 + 1] = acc[nt][hh * 2 + 1] + sf[O_BO2 + c0 + 1];
            }
        }
        __syncthreads();

        // att logits + writeback
        {
            int el = tid >> 2, a = tid & 3;
            if (el < ne) {
                float acc2 = sf[O_BA + a];
                const float* hv = &sf[O_HE + el * 66];
                #pragma unroll 8
                for (int c = 0; c < 64; c++) acc2 += hv[c] * sf[O_WA + c * 4 + a];
                float lg = (acc2 > 0.f) ? acc2 : 2.f * (__expf(acc2 * 0.5f) - 1.f);
                int s = idxs[2 * (e0 + el)];
                g_w[(e0 + el) * 4 + a] = lg;
                atomicMaxF(&g_nodemax[s * 4 + a], lg);
            }
        }
        for (int i = tid; i < ne * 16; i += 256) {
            int el = i >> 4, c = (i & 15) * 4;
            float4 o = make_float4(sf[O_HE + el * 66 + c], sf[O_HE + el * 66 + c + 1],
                                   sf[O_HE + el * 66 + c + 2], sf[O_HE + el * 66 + c + 3]);
            *(float4*)&g_hemtx[(size_t)(e0 + el) * 64 + c] = o;
        }
        for (int i = tid; i < ne * 3; i += 256) g_xhat[e0 * 3 + i] = sf[O_XHT + i];
        __syncthreads();
    }
}

// ---------------- K2: exclusive scan ----------------
__global__ void k_scan(int N) {
    __shared__ int ssum[1024];
    int t = threadIdx.x;
    int chunk = (N + 1023) / 1024;
    int base = t * chunk;
    int vals[16];
    int loc = 0;
    for (int k = 0; k < chunk; k++) {
        int idx = base + k;
        int v = (idx < N) ? g_counts[idx] : 0;
        vals[k] = loc; loc += v;
    }
    ssum[t] = loc; __syncthreads();
    for (int off = 1; off < 1024; off <<= 1) {
        int v = (t >= off) ? ssum[t - off] : 0;
        __syncthreads();
        ssum[t] += v;
        __syncthreads();
    }
    int excl = ssum[t] - loc;
    for (int k = 0; k < chunk; k++) {
        int idx = base + k;
        if (idx < N) { g_off[idx] = excl + vals[k]; g_cursor[idx] = excl + vals[k]; }
    }
    if (t == 1023) g_off[N] = excl + loc;
}

// ---------------- K3: CSR fill ----------------
__global__ void k_fill(const int* __restrict__ idxs, int E) {
    int e = blockIdx.x * blockDim.x + threadIdx.x;
    if (e < E) {
        int s = idxs[2 * e];
        int p = atomicAdd(&g_cursor[s], 1);
        g_eid[p] = e;
    }
}

// ---------------- K4: exp + expsum ----------------
__global__ void k_exp(const int* __restrict__ idxs, int E) {
    int i = blockIdx.x * blockDim.x + threadIdx.x;
    if (i >= E * 4) return;
    int e = i >> 2, a = i & 3;
    int s = idxs[2 * e];
    float w = __expf(g_w[i] - g_nodemax[s * 4 + a]);
    g_w[i] = w;
    atomicAdd(&g_expsum[s * 4 + a], w);
}

// ---------------- K5: xmix via fp16 mma.sync ----------------
#define XS_A 0
#define XS_W (64 * 264)
#define X_ELEMS (64 * 264 + 256 * 72)
#define X_SMEM (X_ELEMS * 2)

__global__ void __launch_bounds__(256, 2)
k_xmix_mma(const int* __restrict__ idxs, int E)
{
    extern __shared__ __half smx[];
    int tid = threadIdx.x;
    int lid = tid & 31, wid = tid >> 5;
    int e0 = blockIdx.x * 64;
    int ne = min(64, E - e0);

    uint32_t* pA = (uint32_t*)(smx + XS_A);
    uint32_t* pW = (uint32_t*)(smx + XS_W);

    {
        int el = tid & 63, kq = tid >> 6;
        float att[4], hm[16];
        if (el < ne) {
            int e = e0 + el;
            int s = idxs[2 * e];
            #pragma unroll
            for (int a = 0; a < 4; a++) att[a] = g_w[e * 4 + a] / g_expsum[s * 4 + a];
            const float4* hp = (const float4*)&g_hemtx[(size_t)e * 64 + kq * 16];
            #pragma unroll
            for (int i = 0; i < 4; i++) {
                float4 v = hp[i];
                hm[i * 4] = v.x; hm[i * 4 + 1] = v.y; hm[i * 4 + 2] = v.z; hm[i * 4 + 3] = v.w;
            }
        } else {
            #pragma unroll
            for (int a = 0; a < 4; a++) att[a] = 0.f;
            #pragma unroll
            for (int i = 0; i < 16; i++) hm[i] = 0.f;
        }
        #pragma unroll
        for (int j = 0; j < 32; j++) {
            int kl = 2 * j;
            float m = hm[kl >> 2];
            pA[el * 132 + ((kq * 64 + kl) >> 1)] = pack2h(m * att[kl & 3], m * att[(kl + 1) & 3]);
        }
    }

    int g = lid >> 2, tg = lid & 3;
    int mrow = (wid & 1) * 32;
    int ncol = (wid >> 1) * 64;

    float acc[2][8][4];
    #pragma unroll
    for (int mt = 0; mt < 2; mt++)
        #pragma unroll
        for (int nt = 0; nt < 8; nt++)
            #pragma unroll
            for (int q = 0; q < 4; q++) acc[mt][nt][q] = 0.f;

    for (int kc = 0; kc < 4; kc++) {
        __syncthreads();
        {
            int n = tid;
            const uint4* src = (const uint4*)&g_wx[n * 256 + kc * 64];
            uint4* dst = (uint4*)(pW + n * 36);
            #pragma unroll
            for (int i = 0; i < 8; i++) dst[i] = src[i];
        }
        __syncthreads();

        #pragma unroll
        for (int ks = 0; ks < 4; ks++) {
            int kA = kc * 64 + ks * 16;
            uint32_t aH[2][4];
            #pragma unroll
            for (int mt = 0; mt < 2; mt++) {
                int r0 = mrow + mt * 16 + g;
                int c0h = (kA + tg * 2) >> 1;
                aH[mt][0] = pA[r0 * 132 + c0h];
                aH[mt][1] = pA[(r0 + 8) * 132 + c0h];
                aH[mt][2] = pA[r0 * 132 + c0h + 4];
                aH[mt][3] = pA[(r0 + 8) * 132 + c0h + 4];
            }
            uint32_t bH[8][2];
            #pragma unroll
            for (int nt = 0; nt < 8; nt++) {
                int n = ncol + nt * 8 + g;
                int ckh = (ks * 16 + tg * 2) >> 1;
                bH[nt][0] = pW[n * 36 + ckh];
                bH[nt][1] = pW[n * 36 + ckh + 4];
            }
            #pragma unroll
            for (int mt = 0; mt < 2; mt++)
                #pragma unroll
                for (int nt = 0; nt < 8; nt++)
                    mma16816h(acc[mt][nt], aH[mt], bH[nt]);
        }
    }

    #pragma unroll
    for (int mt = 0; mt < 2; mt++)
        #pragma unroll
        for (int nt = 0; nt < 8; nt++) {
            int rl = mrow + mt * 16 + g;
            int col = ncol + nt * 8 + tg * 2;
            float* a = acc[mt][nt];
            if (rl < ne) {
                float2 o = make_float2(fast_tanh(a[0]), fast_tanh(a[1]));
                *(float2*)&g_coeff[(size_t)(e0 + rl) * 256 + col] = o;
            }
            if (rl + 8 < ne) {
                float2 o = make_float2(fast_tanh(a[2]), fast_tanh(a[3]));
                *(float2*)&g_coeff[(size_t)(e0 + rl + 8) * 256 + col] = o;
            }
        }
}

// ---------------- K6: per-node aggregation ----------------
__global__ void k_agg(const float* __restrict__ W_vmix, int N) {
    __shared__ float red[24];
    int n = blockIdx.x;
    int c = threadIdx.x;
    int lid = c & 31, wid = c >> 5;
    int beg = g_off[n], end = g_off[n + 1];
    float invs = 1.f / g_expsum[n * 4 + (c & 3)];
    float accH = 0.f, a0 = 0.f, a1 = 0.f, a2 = 0.f;
    for (int i = beg; i < end; i++) {
        int e = g_eid[i];
        float att = g_w[e * 4 + (c & 3)] * invs;
        accH += g_hemtx[(size_t)e * 64 + (c >> 2)] * att;
        float cf = g_coeff[(size_t)e * 256 + c];
        float x0 = g_xhat[e * 3], x1 = g_xhat[e * 3 + 1], x2 = g_xhat[e * 3 + 2];
        a0 += cf * x0; a1 += cf * x1; a2 += cf * x2;
    }
    float cnt = (float)(end - beg);
    float invc = 1.f / (cnt + 1.f);
    float s0 = a0 * invc, s1 = a1 * invc, s2 = a2 * invc;
    g_he[n * 256 + c] = accH;
    g_cnorm[n * 256 + c] = s0 * s0 + s1 * s1 + s2 * s2;

    float wv = W_vmix[c];
    float r0 = wv * a0, r1 = wv * a1, r2 = wv * a2;
    #pragma unroll
    for (int o = 16; o > 0; o >>= 1) {
        r0 += __shfl_xor_sync(0xFFFFFFFFu, r0, o);
        r1 += __shfl_xor_sync(0xFFFFFFFFu, r1, o);
        r2 += __shfl_xor_sync(0xFFFFFFFFu, r2, o);
    }
    if (lid == 0) { red[wid * 3] = r0; red[wid * 3 + 1] = r1; red[wid * 3 + 2] = r2; }
    __syncthreads();
    if (c < 3) {
        float s = 0.f;
        #pragma unroll
        for (int w = 0; w < 8; w++) s += red[w * 3 + c];
        g_dv[n * 3 + c] = s * invc;
    }
}

// ---------------- K7: node MLPs ----------------
__global__ void k_node(const float* __restrict__ h, const float* __restrict__ x,
                       const float* __restrict__ v,
                       const float* __restrict__ W_post1, const float* __restrict__ b_post1,
                       const float* __restrict__ W_post2, const float* __restrict__ b_post2,
                       const float* __restrict__ W_node1, const float* __restrict__ b_node1,
                       const float* __restrict__ W_node2, const float* __restrict__ b_node2,
                       const float* __restrict__ W_vel1,  const float* __restrict__ b_vel1,
                       const float* __restrict__ W_vel2,
                       float* __restrict__ out_h, float* __restrict__ out_x,
                       float* __restrict__ out_v, int N)
{
    extern __shared__ float sm[];
    float* sCN = sm;
    float* sHE = sCN + 8192;
    float* sH  = sHE + 8192;
    float* sT  = sH  + 2048;
    float* sHC = sT  + 2048;
    float* sHN = sHC + 2048;
    float* sBp1 = sHN + 2048;
    float* sBp2 = sBp1 + 64;
    float* sBn1 = sBp2 + 64;
    float* sBn2 = sBn1 + 64;
    float* sBv1 = sBn2 + 64;
    float* sWv2 = sBv1 + 64;
    float* sWbuf = sWv2 + 64;

    int tid = threadIdx.x;
    int n0 = blockIdx.x * 32;
    int nn = min(32, N - n0);

    for (int i = tid; i < nn * 256; i += 256) { sCN[i] = g_cnorm[n0 * 256 + i]; sHE[i] = g_he[n0 * 256 + i]; }
    for (int i = tid; i < nn * 64;  i += 256) sH[i] = h[n0 * 64 + i];
    if (tid < 64) {
        sBp1[tid] = b_post1[tid]; sBp2[tid] = b_post2[tid];
        sBn1[tid] = b_node1[tid]; sBn2[tid] = b_node2[tid];
        sBv1[tid] = b_vel1[tid];  sWv2[tid] = W_vel2[tid];
    }
    __syncthreads();

    for (int i = tid; i < 16384; i += 256) sWbuf[i] = W_post1[i];
    __syncthreads();
    for (int i = tid; i < nn * 16; i += 256) {
        int ln = i >> 4, j0 = (i & 15) * 4;
        float a0 = sBp1[j0], a1 = sBp1[j0 + 1], a2 = sBp1[j0 + 2], a3 = sBp1[j0 + 3];
        const float* cv = &sCN[ln * 256];
        #pragma unroll 4
        for (int c = 0; c < 256; c++) {
            float hv = cv[c];
            float4 w = *(const float4*)&sWbuf[c * 64 + j0];
            a0 += hv * w.x; a1 += hv * w.y; a2 += hv * w.z; a3 += hv * w.w;
        }
        float* o = &sT[ln * 64 + j0];
        o[0] = siluf(a0); o[1] = siluf(a1); o[2] = siluf(a2); o[3] = siluf(a3);
    }
    __syncthreads();

    for (int i = tid; i < 4096; i += 256) sWbuf[i] = W_post2[i];
    __syncthreads();
    for (int i = tid; i < nn * 16; i += 256) {
        int ln = i >> 4, j0 = (i & 15) * 4;
        float a0 = sBp2[j0], a1 = sBp2[j0 + 1], a2 = sBp2[j0 + 2], a3 = sBp2[j0 + 3];
        const float* tv = &sT[ln * 64];
        #pragma unroll 4
        for (int c = 0; c < 64; c++) {
            float hv = tv[c];
            float4 w = *(const float4*)&sWbuf[c * 64 + j0];
            a0 += hv * w.x; a1 += hv * w.y; a2 += hv * w.z; a3 += hv * w.w;
        }
        float* o = &sHC[ln * 64 + j0];
        o[0] = siluf(a0); o[1] = siluf(a1); o[2] = siluf(a2); o[3] = siluf(a3);
    }
    __syncthreads();

    for (int i = tid; i < 24576; i += 256) sWbuf[i] = W_node1[i];
    __syncthreads();
    for (int i = tid; i < nn * 16; i += 256) {
        int ln = i >> 4, j0 = (i & 15) * 4;
        float a0 = sBn1[j0], a1 = sBn1[j0 + 1], a2 = sBn1[j0 + 2], a3 = sBn1[j0 + 3];
        const float* hv2 = &sH[ln * 64];
        #pragma unroll 4
        for (int c = 0; c < 64; c++) {
            float hv = hv2[c];
            float4 w = *(const float4*)&sWbuf[c * 64 + j0];
            a0 += hv * w.x; a1 += hv * w.y; a2 += hv * w.z; a3 += hv * w.w;
        }
        const float* he = &sHE[ln * 256];
        #pragma unroll 4
        for (int c = 0; c < 256; c++) {
            float hv = he[c];
            float4 w = *(const float4*)&sWbuf[(64 + c) * 64 + j0];
            a0 += hv * w.x; a1 += hv * w.y; a2 += hv * w.z; a3 += hv * w.w;
        }
        const float* hc = &sHC[ln * 64];
        #pragma unroll 4
        for (int c = 0; c < 64; c++) {
            float hv = hc[c];
            float4 w = *(const float4*)&sWbuf[(320 + c) * 64 + j0];
            a0 += hv * w.x; a1 += hv * w.y; a2 += hv * w.z; a3 += hv * w.w;
        }
        float* o = &sT[ln * 64 + j0];
        o[0] = siluf(a0); o[1] = siluf(a1); o[2] = siluf(a2); o[3] = siluf(a3);
    }
    __syncthreads();

    for (int i = tid; i < 4096; i += 256) sWbuf[i] = W_node2[i];
    __syncthreads();
    for (int i = tid; i < nn * 16; i += 256) {
        int ln = i >> 4, j0 = (i & 15) * 4;
        float a0 = sBn2[j0], a1 = sBn2[j0 + 1], a2 = sBn2[j0 + 2], a3 = sBn2[j0 + 3];
        const float* tv = &sT[ln * 64];
        #pragma unroll 4
        for (int c = 0; c < 64; c++) {
            float hv = tv[c];
            float4 w = *(const float4*)&sWbuf[c * 64 + j0];
            a0 += hv * w.x; a1 += hv * w.y; a2 += hv * w.z; a3 += hv * w.w;
        }
        int n = n0 + ln;
        float h0 = sH[ln * 64 + j0]     + siluf(a0);
        float h1 = sH[ln * 64 + j0 + 1] + siluf(a1);
        float h2 = sH[ln * 64 + j0 + 2] + siluf(a2);
        float h3 = sH[ln * 64 + j0 + 3] + siluf(a3);
        float* o = &sHN[ln * 64 + j0];
        o[0] = h0; o[1] = h1; o[2] = h2; o[3] = h3;
        *(float4*)&out_h[n * 64 + j0] = make_float4(h0, h1, h2, h3);
    }
    __syncthreads();

    for (int i = tid; i < 4096; i += 256) sWbuf[i] = W_vel1[i];
    __syncthreads();
    for (int i = tid; i < nn * 16; i += 256) {
        int ln = i >> 4, j0 = (i & 15) * 4;
        float a0 = sBv1[j0], a1 = sBv1[j0 + 1], a2 = sBv1[j0 + 2], a3 = sBv1[j0 + 3];
        const float* hv2 = &sHN[ln * 64];
        #pragma unroll 4
        for (int c = 0; c < 64; c++) {
            float hv = hv2[c];
            float4 w = *(const float4*)&sWbuf[c * 64 + j0];
            a0 += hv * w.x; a1 += hv * w.y; a2 += hv * w.z; a3 += hv * w.w;
        }
        float* o = &sT[ln * 64 + j0];
        o[0] = siluf(a0) * sWv2[j0];
        o[1] = siluf(a1) * sWv2[j0 + 1];
        o[2] = siluf(a2) * sWv2[j0 + 2];
        o[3] = siluf(a3) * sWv2[j0 + 3];
    }
    __syncthreads();

    if (tid < nn) {
        int ln = tid;
        float s = 0.f;
        #pragma unroll 8
        for (int k = 0; k < 64; k++) s += sT[ln * 64 + k];
        float scale = 2.f / (1.f + __expf(-s));
        int n = n0 + ln;
        #pragma unroll
        for (int d = 0; d < 3; d++) {
            float vn = g_dv[n * 3 + d] + scale * v[n * 3 + d];
            out_v[n * 3 + d] = vn;
            out_x[n * 3 + d] = x[n * 3 + d] + vn;
        }
    }
}

// ---------------- launch ----------------
extern "C" void kernel_launch(void* const* d_in, const int* in_sizes, int n_in,
                              void* d_out, int out_size)
{
    const float* h        = (const float*)d_in[0];
    const float* x        = (const float*)d_in[1];
    const float* v        = (const float*)d_in[2];
    const int*   idxs     = (const int*)  d_in[3];
    const float* rbf_mean = (const float*)d_in[4];
    const float* rbf_beta = (const float*)d_in[5];
    const float* W_in     = (const float*)d_in[6];
    const float* b_in     = (const float*)d_in[7];
    const float* W_out1   = (const float*)d_in[8];
    const float* b_out1   = (const float*)d_in[9];
    const float* W_out2   = (const float*)d_in[10];
    const float* b_out2   = (const float*)d_in[11];
    const float* W_att    = (const float*)d_in[12];
    const float* b_att    = (const float*)d_in[13];
    const float* W_xmix   = (const float*)d_in[14];
    const float* W_post1  = (const float*)d_in[15];
    const float* b_post1  = (const float*)d_in[16];
    const float* W_post2  = (const float*)d_in[17];
    const float* b_post2  = (const float*)d_in[18];
    const float* W_node1  = (const float*)d_in[19];
    const float* b_node1  = (const float*)d_in[20];
    const float* W_node2  = (const float*)d_in[21];
    const float* b_node2  = (const float*)d_in[22];
    const float* W_vmix   = (const float*)d_in[23];
    const float* W_vel1   = (const float*)d_in[24];
    const float* b_vel1   = (const float*)d_in[25];
    const float* W_vel2   = (const float*)d_in[26];

    int N = in_sizes[0] / 64;
    int E = in_sizes[3] / 2;

    float* out  = (float*)d_out;
    float* outh = out;
    float* outx = out + (size_t)N * 64;
    float* outv = out + (size_t)N * 67;

    const int SM_NODE = (8192 * 2 + 2048 * 4 + 64 * 6 + 24576) * 4;

    cudaFuncSetAttribute(k_edge_mma, cudaFuncAttributeMaxDynamicSharedMemorySize, E_SMEM);
    cudaFuncSetAttribute(k_xmix_mma, cudaFuncAttributeMaxDynamicSharedMemorySize, X_SMEM);
    cudaFuncSetAttribute(k_node,     cudaFuncAttributeMaxDynamicSharedMemorySize, SM_NODE);

    k_init<<<(N * 4 + 255) / 256, 256>>>(N);
    k_wprep<<<256, 256>>>(W_xmix);
    k_eprep<<<48, 256>>>(W_in, W_out1, W_out2);
    k_edge_mma<<<296, 256, E_SMEM>>>(h, x, idxs, rbf_mean, rbf_beta,
                                     b_in, b_out1, b_out2, W_att, b_att, E);
    k_scan<<<1, 1024>>>(N);
    k_fill<<<(E + 255) / 256, 256>>>(idxs, E);
    k_exp<<<(E * 4 + 255) / 256, 256>>>(idxs, E);
    k_xmix_mma<<<(E + 63) / 64, 256, X_SMEM>>>(idxs, E);
    k_agg<<<N, 256>>>(W_vmix, N);
    k_node<<<(N + 31) / 32, 256, SM_NODE>>>(h, x, v,
                                            W_post1, b_post1, W_post2, b_post2,
                                            W_node1, b_node1, W_node2, b_node2,
                                            W_vel1, b_vel1, W_vel2,
                                            outh, outx, outv, N);
}

// round 7
// speedup vs baseline: 2.8872x; 1.0182x over previous
#include <cuda_runtime.h>
#include <cuda_fp16.h>
#include <stdint.h>
#include <math.h>

#define NMAX 10000
#define EMAX 160000

// ---------------- scratch ----------------
__device__ float g_hemtx[EMAX * 64];
__device__ float g_xhat[EMAX * 3];
__device__ float g_w[EMAX * 4];
__device__ float g_nodemax[NMAX * 4];
__device__ float g_expsum[NMAX * 4];
__device__ int   g_counts[NMAX];
__device__ int   g_off[NMAX + 1];
__device__ int   g_cursor[NMAX];
__device__ int   g_eid[EMAX];
__device__ float g_he[NMAX * 256];
__device__ float g_cnorm[NMAX * 256];
__device__ float g_comb[NMAX * 768];     // boundary-node partial sums [n][d][c]
__device__ int   g_bflag[NMAX];
__device__ float g_dv[NMAX * 3];
__device__ __half g_wx[256 * 256];       // W_xmix^T fp16 [n][k]
__device__ uint32_t g_ewi[4096];
__device__ uint32_t g_ew1a[4096];
__device__ uint32_t g_ew1b[2048];
__device__ uint32_t g_ew2[2048];

__device__ __forceinline__ float siluf(float x) { return x / (1.f + __expf(-x)); }
__device__ __forceinline__ float fast_tanh(float x) {
    float y; asm("tanh.approx.f32 %0, %1;" : "=f"(y) : "f"(x)); return y;
}
__device__ __forceinline__ void atomicMaxF(float* a, float v) {
    if (v >= 0.f) atomicMax((int*)a, __float_as_int(v));
    else          atomicMin((unsigned int*)a, (unsigned int)__float_as_int(v));
}
__device__ __forceinline__ void mma16816h(float* d, const uint32_t* a, const uint32_t* b) {
    asm volatile("mma.sync.aligned.m16n8k16.row.col.f32.f16.f16.f32 "
        "{%0,%1,%2,%3}, {%4,%5,%6,%7}, {%8,%9}, {%0,%1,%2,%3};"
        : "+f"(d[0]), "+f"(d[1]), "+f"(d[2]), "+f"(d[3])
        : "r"(a[0]), "r"(a[1]), "r"(a[2]), "r"(a[3]), "r"(b[0]), "r"(b[1]));
}
__device__ __forceinline__ uint32_t pack2h(float a, float b) {
    __half2 p = __floats2half2_rn(a, b);
    return *(uint32_t*)&p;
}

// ---------------- K0: init ----------------
__global__ void k_init(int N) {
    int i = blockIdx.x * blockDim.x + threadIdx.x;
    if (i < N * 4) {
        g_nodemax[i] = __int_as_float(0xff800000);
        g_expsum[i]  = 0.f;
    }
    if (i < N) { g_counts[i] = 0; g_bflag[i] = 0; }
    if (i < N * 3) g_dv[i] = 0.f;
    if (i < N * 256) { g_he[i] = 0.f; g_cnorm[i] = 0.f; }
    if (i < N * 768) g_comb[i] = 0.f;
}

// ---------------- K_wprep: W_xmix transpose -> fp16 ----------------
__global__ void k_wprep(const float* __restrict__ W_xmix) {
    int i = blockIdx.x * 256 + threadIdx.x;
    int n = i >> 8, k = i & 255;
    g_wx[n * 256 + k] = __float2half_rn(W_xmix[k * 256 + n]);
}

// ---------------- K_eprep ----------------
__global__ void k_eprep(const float* __restrict__ W_in, const float* __restrict__ W_out1,
                        const float* __restrict__ W_out2) {
    int i = blockIdx.x * 256 + threadIdx.x;
    if (i < 4096) {
        int n = i >> 6, k0 = (i & 63) * 2;
        float w0 = (n < 50) ? W_in[k0 * 50 + n] : 0.f;
        float w1 = (n < 50) ? W_in[(k0 + 1) * 50 + n] : 0.f;
        g_ewi[i] = pack2h(w0, w1);
    } else if (i < 8192) {
        int j = i - 4096;
        int n = j >> 6, k0 = (j & 63) * 2;
        g_ew1a[j] = pack2h(W_out1[k0 * 64 + n], W_out1[(k0 + 1) * 64 + n]);
    } else if (i < 10240) {
        int j = i - 8192;
        int n = j >> 5, k0 = (j & 31) * 2;
        float w0 = (k0 < 50) ? W_out1[(128 + k0) * 64 + n] : ((k0 == 50) ? W_out1[178 * 64 + n] : 0.f);
        int k1 = k0 + 1;
        float w1 = (k1 < 50) ? W_out1[(128 + k1) * 64 + n] : ((k1 == 50) ? W_out1[178 * 64 + n] : 0.f);
        g_ew1b[j] = pack2h(w0, w1);
    } else if (i < 12288) {
        int j = i - 10240;
        int n = j >> 5, k0 = (j & 31) * 2;
        g_ew2[j] = pack2h(W_out2[k0 * 64 + n], W_out2[(k0 + 1) * 64 + n]);
    }
}

// ---------------- K1: edge MLP via fp16 mma.sync ----------------
#define O_A     0
#define O_X     4352
#define O_M     6656
#define O_WI    8960
#define O_W1A   13312
#define O_W1B   17664
#define O_W2    19968
#define O_HE    22272
#define O_BIN   26496
#define O_BO1   26560
#define O_BO2   26624
#define O_MEAN  26688
#define O_BETA  26752
#define O_WA    26816
#define O_BA    27072
#define O_NORM  27076
#define O_EX    27140
#define O_XHT   27204
#define E_SMEM  (27400 * 4)

__global__ void __launch_bounds__(256, 2)
k_edge_mma(const float* __restrict__ h, const float* __restrict__ x,
           const int* __restrict__ idxs,
           const float* __restrict__ rbf_means, const float* __restrict__ rbf_betas,
           const float* __restrict__ b_in, const float* __restrict__ b_out1,
           const float* __restrict__ b_out2,
           const float* __restrict__ W_att, const float* __restrict__ b_att, int E)
{
    extern __shared__ uint32_t su[];
    float* sf = (float*)su;
    int tid = threadIdx.x, lid = tid & 31, wid = tid >> 5;
    int g = lid >> 2, tg = lid & 3;
    int mrow = (wid & 3) * 16, ncol = (wid >> 2) * 32;

    for (int i = tid; i < 4096; i += 256) {
        int n = i >> 6, kk = i & 63;
        su[O_WI  + n * 68 + kk] = g_ewi[i];
        su[O_W1A + n * 68 + kk] = g_ew1a[i];
    }
    for (int i = tid; i < 2048; i += 256) {
        int n = i >> 5, kk = i & 31;
        su[O_W1B + n * 36 + kk] = g_ew1b[i];
        su[O_W2  + n * 36 + kk] = g_ew2[i];
    }
    if (tid < 64) {
        sf[O_BIN + tid]  = (tid < 50) ? b_in[tid] : 0.f;
        sf[O_BO1 + tid]  = b_out1[tid];
        sf[O_BO2 + tid]  = b_out2[tid];
        sf[O_MEAN + tid] = (tid < 50) ? rbf_means[tid] : 0.f;
        sf[O_BETA + tid] = (tid < 50) ? rbf_betas[tid] : 1.f;
    }
    if (tid < 256) sf[O_WA + tid] = W_att[tid];
    if (tid < 4)   sf[O_BA + tid] = b_att[tid];
    __syncthreads();

    int ntiles = (E + 63) / 64;
    for (int tile = blockIdx.x; tile < ntiles; tile += gridDim.x) {
        int e0 = tile * 64, ne = min(64, E - e0);

        if (tid < 64) {
            float nrm = 0.f, xh0 = 0.f, xh1 = 0.f, xh2 = 0.f;
            if (tid < ne) {
                int s = idxs[2 * (e0 + tid)], d = idxs[2 * (e0 + tid) + 1];
                float dx = x[3 * s]     - x[3 * d];
                float dy = x[3 * s + 1] - x[3 * d + 1];
                float dz = x[3 * s + 2] - x[3 * d + 2];
                nrm = sqrtf(dx * dx + dy * dy + dz * dz + 1e-14f);
                float inv = 1.f / (nrm + 1e-5f);
                xh0 = dx * inv; xh1 = dy * inv; xh2 = dz * inv;
                atomicAdd(&g_counts[s], 1);
            }
            sf[O_NORM + tid] = nrm;
            sf[O_EX + tid]   = __expf(-nrm);
            sf[O_XHT + tid * 3] = xh0; sf[O_XHT + tid * 3 + 1] = xh1; sf[O_XHT + tid * 3 + 2] = xh2;
        }
        {
            int el = tid >> 2, part = tid & 3;
            uint32_t hb[16];
            if (el < ne) {
                int node = idxs[2 * (e0 + el) + (part >> 1)];
                const float4* hp = (const float4*)&h[node * 64 + (part & 1) * 32];
                #pragma unroll
                for (int i2 = 0; i2 < 8; i2++) {
                    float4 v = hp[i2];
                    hb[i2 * 2]     = pack2h(v.x, v.y);
                    hb[i2 * 2 + 1] = pack2h(v.z, v.w);
                }
            } else {
                #pragma unroll
                for (int i2 = 0; i2 < 16; i2++) hb[i2] = 0u;
            }
            uint4* dh = (uint4*)&su[O_A + el * 68 + part * 16];
            #pragma unroll
            for (int i2 = 0; i2 < 4; i2++)
                dh[i2] = make_uint4(hb[i2*4], hb[i2*4+1], hb[i2*4+2], hb[i2*4+3]);
        }
        __syncthreads();

        float acc[4][4];

        // G1
        #pragma unroll
        for (int nt = 0; nt < 4; nt++)
            #pragma unroll
            for (int q = 0; q < 4; q++) acc[nt][q] = 0.f;
        #pragma unroll
        for (int ks = 0; ks < 8; ks++) {
            uint32_t aH[4];
            int ra = (mrow + g) * 68 + ks * 8 + tg;
            aH[0] = su[O_A + ra];       aH[1] = su[O_A + ra + 8 * 68];
            aH[2] = su[O_A + ra + 4];   aH[3] = su[O_A + ra + 8 * 68 + 4];
            #pragma unroll
            for (int nt = 0; nt < 4; nt++) {
                int nb = (ncol + nt * 8 + g) * 68 + ks * 8 + tg;
                uint32_t bH[2] = { su[O_WI + nb], su[O_WI + nb + 4] };
                mma16816h(acc[nt], aH, bH);
            }
        }
        #pragma unroll
        for (int nt = 0; nt < 4; nt++) {
            #pragma unroll
            for (int hh = 0; hh < 2; hh++) {
                int row = mrow + g + hh * 8;
                int c0 = ncol + nt * 8 + tg * 2;
                float v0 = acc[nt][hh * 2]     + sf[O_BIN + c0];
                float v1 = acc[nt][hh * 2 + 1] + sf[O_BIN + c0 + 1];
                float ex = sf[O_EX + row];
                float x0, x1;
                if (c0 < 50) { float d = ex - sf[O_MEAN + c0]; x0 = __expf(-sf[O_BETA + c0] * d * d) * v0; }
                else x0 = (c0 == 50) ? sf[O_NORM + row] : 0.f;
                if (c0 + 1 < 50) { float d = ex - sf[O_MEAN + c0 + 1]; x1 = __expf(-sf[O_BETA + c0 + 1] * d * d) * v1; }
                else x1 = 0.f;
                su[O_X + row * 36 + (c0 >> 1)] = pack2h(x0, x1);
            }
        }
        __syncthreads();

        // G2
        #pragma unroll
        for (int nt = 0; nt < 4; nt++)
            #pragma unroll
            for (int q = 0; q < 4; q++) acc[nt][q] = 0.f;
        #pragma unroll
        for (int ks = 0; ks < 8; ks++) {
            uint32_t aH[4];
            int ra = (mrow + g) * 68 + ks * 8 + tg;
            aH[0] = su[O_A + ra];       aH[1] = su[O_A + ra + 8 * 68];
            aH[2] = su[O_A + ra + 4];   aH[3] = su[O_A + ra + 8 * 68 + 4];
            #pragma unroll
            for (int nt = 0; nt < 4; nt++) {
                int nb = (ncol + nt * 8 + g) * 68 + ks * 8 + tg;
                uint32_t bH[2] = { su[O_W1A + nb], su[O_W1A + nb + 4] };
                mma16816h(acc[nt], aH, bH);
            }
        }
        #pragma unroll
        for (int ks = 0; ks < 4; ks++) {
            uint32_t aH[4];
            int ra = (mrow + g) * 36 + ks * 8 + tg;
            aH[0] = su[O_X + ra];       aH[1] = su[O_X + ra + 8 * 36];
            aH[2] = su[O_X + ra + 4];   aH[3] = su[O_X + ra + 8 * 36 + 4];
            #pragma unroll
            for (int nt = 0; nt < 4; nt++) {
                int nb = (ncol + nt * 8 + g) * 36 + ks * 8 + tg;
                uint32_t bH[2] = { su[O_W1B + nb], su[O_W1B + nb + 4] };
                mma16816h(acc[nt], aH, bH);
            }
        }
        #pragma unroll
        for (int nt = 0; nt < 4; nt++) {
            #pragma unroll
            for (int hh = 0; hh < 2; hh++) {
                int row = mrow + g + hh * 8;
                int c0 = ncol + nt * 8 + tg * 2;
                float m0 = siluf(acc[nt][hh * 2]     + sf[O_BO1 + c0]);
                float m1 = siluf(acc[nt][hh * 2 + 1] + sf[O_BO1 + c0 + 1]);
                su[O_M + row * 36 + (c0 >> 1)] = pack2h(m0, m1);
            }
        }
        __syncthreads();

        // G3
        #pragma unroll
        for (int nt = 0; nt < 4; nt++)
            #pragma unroll
            for (int q = 0; q < 4; q++) acc[nt][q] = 0.f;
        #pragma unroll
        for (int ks = 0; ks < 4; ks++) {
            uint32_t aH[4];
            int ra = (mrow + g) * 36 + ks * 8 + tg;
            aH[0] = su[O_M + ra];       aH[1] = su[O_M + ra + 8 * 36];
            aH[2] = su[O_M + ra + 4];   aH[3] = su[O_M + ra + 8 * 36 + 4];
            #pragma unroll
            for (int nt = 0; nt < 4; nt++) {
                int nb = (ncol + nt * 8 + g) * 36 + ks * 8 + tg;
                uint32_t bH[2] = { su[O_W2 + nb], su[O_W2 + nb + 4] };
                mma16816h(acc[nt], aH, bH);
            }
        }
        #pragma unroll
        for (int nt = 0; nt < 4; nt++) {
            #pragma unroll
            for (int hh = 0; hh < 2; hh++) {
                int row = mrow + g + hh * 8;
                int c0 = ncol + nt * 8 + tg * 2;
                sf[O_HE + row * 66 + c0]     = acc[nt][hh * 2]     + sf[O_BO2 + c0];
                sf[O_HE + row * 66 + c0 + 1] = acc[nt][hh * 2 + 1] + sf[O_BO2 + c0 + 1];
            }
        }
        __syncthreads();

        {
            int el = tid >> 2, a = tid & 3;
            if (el < ne) {
                float acc2 = sf[O_BA + a];
                const float* hv = &sf[O_HE + el * 66];
                #pragma unroll 8
                for (int c = 0; c < 64; c++) acc2 += hv[c] * sf[O_WA + c * 4 + a];
                float lg = (acc2 > 0.f) ? acc2 : 2.f * (__expf(acc2 * 0.5f) - 1.f);
                int s = idxs[2 * (e0 + el)];
                g_w[(e0 + el) * 4 + a] = lg;
                atomicMaxF(&g_nodemax[s * 4 + a], lg);
            }
        }
        for (int i = tid; i < ne * 16; i += 256) {
            int el = i >> 4, c = (i & 15) * 4;
            float4 o = make_float4(sf[O_HE + el * 66 + c], sf[O_HE + el * 66 + c + 1],
                                   sf[O_HE + el * 66 + c + 2], sf[O_HE + el * 66 + c + 3]);
            *(float4*)&g_hemtx[(size_t)(e0 + el) * 64 + c] = o;
        }
        for (int i = tid; i < ne * 3; i += 256) g_xhat[e0 * 3 + i] = sf[O_XHT + i];
        __syncthreads();
    }
}

// ---------------- K2: exclusive scan ----------------
__global__ void k_scan(int N) {
    __shared__ int ssum[1024];
    int t = threadIdx.x;
    int chunk = (N + 1023) / 1024;
    int base = t * chunk;
    int vals[16];
    int loc = 0;
    for (int k = 0; k < chunk; k++) {
        int idx = base + k;
        int v = (idx < N) ? g_counts[idx] : 0;
        vals[k] = loc; loc += v;
    }
    ssum[t] = loc; __syncthreads();
    for (int off = 1; off < 1024; off <<= 1) {
        int v = (t >= off) ? ssum[t - off] : 0;
        __syncthreads();
        ssum[t] += v;
        __syncthreads();
    }
    int excl = ssum[t] - loc;
    for (int k = 0; k < chunk; k++) {
        int idx = base + k;
        if (idx < N) { g_off[idx] = excl + vals[k]; g_cursor[idx] = excl + vals[k]; }
    }
    if (t == 1023) g_off[N] = excl + loc;
}

// ---------------- K3: CSR fill + exp + expsum ----------------
__global__ void k_fillexp(const int* __restrict__ idxs, int E) {
    int e = blockIdx.x * blockDim.x + threadIdx.x;
    if (e >= E) return;
    int s = idxs[2 * e];
    int p = atomicAdd(&g_cursor[s], 1);
    g_eid[p] = e;
    #pragma unroll
    for (int a = 0; a < 4; a++) {
        float w = __expf(g_w[e * 4 + a] - g_nodemax[s * 4 + a]);
        g_w[e * 4 + a] = w;
        atomicAdd(&g_expsum[s * 4 + a], w);
    }
}

// ---------------- K5: fused xmix GEMM + per-node aggregation ----------------
// smem (u32 units):
#define XG_A    0                 // 64*132 fp16x2; aliased by coeff after MMAs
#define XG_W    8448              // 256*36 fp16x2
#define XG_HM   17664             // 64*67 f32
#define XG_ATT  21952             // 64*4 f32
#define XG_XH   22208             // 64*3 f32
#define XG_NODE 22400             // 64 int
#define XG_WV   22464             // 256 f32
#define XG_RED  22720             // 24 f32
#define XG_SMEM (22744 * 4)

__global__ void __launch_bounds__(256, 2)
k_xagg(const int* __restrict__ idxs, const float* __restrict__ W_vmix, int E)
{
    extern __shared__ uint32_t su[];
    float* sf = (float*)su;
    int tid = threadIdx.x, lid = tid & 31, wid = tid >> 5;
    int p0 = blockIdx.x * 64;
    uint32_t* pA = su + XG_A;
    uint32_t* pW = su + XG_W;
    int* sN = (int*)(su + XG_NODE);

    // ---- prologue: gather per CSR slot ----
    {
        int sl = tid & 63, kq = tid >> 6;
        int e = -1, s = -1;
        float att[4], hm[16];
        int p = p0 + sl;
        if (p < E) {
            e = g_eid[p];
            s = idxs[2 * e];
            #pragma unroll
            for (int a = 0; a < 4; a++) att[a] = g_w[e * 4 + a] / g_expsum[s * 4 + a];
            const float4* hp = (const float4*)&g_hemtx[(size_t)e * 64 + kq * 16];
            #pragma unroll
            for (int i = 0; i < 4; i++) {
                float4 v = hp[i];
                hm[i * 4] = v.x; hm[i * 4 + 1] = v.y; hm[i * 4 + 2] = v.z; hm[i * 4 + 3] = v.w;
            }
        } else {
            #pragma unroll
            for (int a = 0; a < 4; a++) att[a] = 0.f;
            #pragma unroll
            for (int i = 0; i < 16; i++) hm[i] = 0.f;
        }
        if (kq == 0) {
            sN[sl] = s;
            #pragma unroll
            for (int a = 0; a < 4; a++) sf[XG_ATT + sl * 4 + a] = att[a];
            float x0 = 0.f, x1 = 0.f, x2 = 0.f;
            if (e >= 0) { x0 = g_xhat[e * 3]; x1 = g_xhat[e * 3 + 1]; x2 = g_xhat[e * 3 + 2]; }
            sf[XG_XH + sl * 3] = x0; sf[XG_XH + sl * 3 + 1] = x1; sf[XG_XH + sl * 3 + 2] = x2;
        }
        #pragma unroll
        for (int i = 0; i < 16; i++) sf[XG_HM + sl * 67 + kq * 16 + i] = hm[i];
        #pragma unroll
        for (int j = 0; j < 32; j++) {
            int kl = 2 * j;
            float m = hm[kl >> 2];
            pA[sl * 132 + ((kq * 64 + kl) >> 1)] = pack2h(m * att[kl & 3], m * att[(kl + 1) & 3]);
        }
        sf[XG_WV + tid] = W_vmix[tid];
    }

    // ---- MMA phase ----
    int g = lid >> 2, tg = lid & 3;
    int mrow = (wid & 1) * 32;
    int ncol = (wid >> 1) * 64;

    float acc[2][8][4];
    #pragma unroll
    for (int mt = 0; mt < 2; mt++)
        #pragma unroll
        for (int nt = 0; nt < 8; nt++)
            #pragma unroll
            for (int q = 0; q < 4; q++) acc[mt][nt][q] = 0.f;

    for (int kc = 0; kc < 4; kc++) {
        __syncthreads();
        {
            int n = tid;
            const uint4* src = (const uint4*)&g_wx[n * 256 + kc * 64];
            uint4* dst = (uint4*)(pW + n * 36);
            #pragma unroll
            for (int i = 0; i < 8; i++) dst[i] = src[i];
        }
        __syncthreads();

        #pragma unroll
        for (int ks = 0; ks < 4; ks++) {
            int kA = kc * 64 + ks * 16;
            uint32_t aH[2][4];
            #pragma unroll
            for (int mt = 0; mt < 2; mt++) {
                int r0 = mrow + mt * 16 + g;
                int c0h = (kA + tg * 2) >> 1;
                aH[mt][0] = pA[r0 * 132 + c0h];
                aH[mt][1] = pA[(r0 + 8) * 132 + c0h];
                aH[mt][2] = pA[r0 * 132 + c0h + 4];
                aH[mt][3] = pA[(r0 + 8) * 132 + c0h + 4];
            }
            uint32_t bH[8][2];
            #pragma unroll
            for (int nt = 0; nt < 8; nt++) {
                int n = ncol + nt * 8 + g;
                int ckh = (ks * 16 + tg * 2) >> 1;
                bH[nt][0] = pW[n * 36 + ckh];
                bH[nt][1] = pW[n * 36 + ckh + 4];
            }
            #pragma unroll
            for (int mt = 0; mt < 2; mt++)
                #pragma unroll
                for (int nt = 0; nt < 8; nt++)
                    mma16816h(acc[mt][nt], aH[mt], bH[nt]);
        }
    }

    // ---- coeff = tanh(acc) -> smem (aliases A) ----
    __syncthreads();
    #pragma unroll
    for (int mt = 0; mt < 2; mt++)
        #pragma unroll
        for (int nt = 0; nt < 8; nt++) {
            int rl = mrow + mt * 16 + g;
            int col = ncol + nt * 8 + tg * 2;
            float* a = acc[mt][nt];
            pA[rl * 132 + (col >> 1)]       = pack2h(fast_tanh(a[0]), fast_tanh(a[1]));
            pA[(rl + 8) * 132 + (col >> 1)] = pack2h(fast_tanh(a[2]), fast_tanh(a[3]));
        }
    __syncthreads();

    // ---- segmented per-node reduction ----
    {
        int c = tid;
        float wv = sf[XG_WV + c];
        float accH = 0.f, a0 = 0.f, a1 = 0.f, a2 = 0.f;
        int segStart = 0;
        for (int sl = 0; sl < 64; sl++) {
            int n = sN[sl];
            if (n >= 0) {
                float A32 = sf[XG_HM + sl * 67 + (c >> 2)] * sf[XG_ATT + sl * 4 + (c & 3)];
                accH += A32;
                uint32_t cp = pA[sl * 132 + (c >> 1)];
                __half2 h2 = *(__half2*)&cp;
                float cf = (c & 1) ? __high2float(h2) : __low2float(h2);
                a0 += cf * sf[XG_XH + sl * 3];
                a1 += cf * sf[XG_XH + sl * 3 + 1];
                a2 += cf * sf[XG_XH + sl * 3 + 2];
            }
            bool segEnd = (sl == 63) || (sN[sl + 1] != n);
            if (segEnd) {
                if (n >= 0) {
                    int beg = g_off[n], end = g_off[n + 1];
                    bool full = (beg == p0 + segStart) && (end == p0 + sl + 1);
                    if (full) {
                        float invc = 1.f / ((float)(end - beg) + 1.f);
                        g_he[n * 256 + c] = accH;
                        float s0 = a0 * invc, s1 = a1 * invc, s2 = a2 * invc;
                        g_cnorm[n * 256 + c] = s0 * s0 + s1 * s1 + s2 * s2;
                        float r0 = wv * s0, r1 = wv * s1, r2 = wv * s2;
                        #pragma unroll
                        for (int o = 16; o > 0; o >>= 1) {
                            r0 += __shfl_xor_sync(0xFFFFFFFFu, r0, o);
                            r1 += __shfl_xor_sync(0xFFFFFFFFu, r1, o);
                            r2 += __shfl_xor_sync(0xFFFFFFFFu, r2, o);
                        }
                        if (lid == 0) {
                            sf[XG_RED + wid * 3]     = r0;
                            sf[XG_RED + wid * 3 + 1] = r1;
                            sf[XG_RED + wid * 3 + 2] = r2;
                        }
                        __syncthreads();
                        if (c < 3) {
                            float s = 0.f;
                            #pragma unroll
                            for (int w = 0; w < 8; w++) s += sf[XG_RED + w * 3 + c];
                            g_dv[n * 3 + c] = s;
                        }
                        __syncthreads();
                    } else {
                        atomicAdd(&g_he[n * 256 + c], accH);
                        atomicAdd(&g_comb[((size_t)n * 3 + 0) * 256 + c], a0);
                        atomicAdd(&g_comb[((size_t)n * 3 + 1) * 256 + c], a1);
                        atomicAdd(&g_comb[((size_t)n * 3 + 2) * 256 + c], a2);
                        if (c == 0) g_bflag[n] = 1;
                    }
                }
                accH = 0.f; a0 = 0.f; a1 = 0.f; a2 = 0.f;
                segStart = sl + 1;
            }
        }
    }
}

// ---------------- K_fin: finish boundary nodes ----------------
__global__ void k_fin(const float* __restrict__ W_vmix, int N) {
    __shared__ float red[24];
    int n = blockIdx.x;
    if (!g_bflag[n]) return;
    int c = threadIdx.x, lid = c & 31, wid = c >> 5;
    int beg = g_off[n], end = g_off[n + 1];
    float invc = 1.f / ((float)(end - beg) + 1.f);
    float s0 = g_comb[((size_t)n * 3 + 0) * 256 + c] * invc;
    float s1 = g_comb[((size_t)n * 3 + 1) * 256 + c] * invc;
    float s2 = g_comb[((size_t)n * 3 + 2) * 256 + c] * invc;
    g_cnorm[n * 256 + c] = s0 * s0 + s1 * s1 + s2 * s2;
    float wv = W_vmix[c];
    float r0 = wv * s0, r1 = wv * s1, r2 = wv * s2;
    #pragma unroll
    for (int o = 16; o > 0; o >>= 1) {
        r0 += __shfl_xor_sync(0xFFFFFFFFu, r0, o);
        r1 += __shfl_xor_sync(0xFFFFFFFFu, r1, o);
        r2 += __shfl_xor_sync(0xFFFFFFFFu, r2, o);
    }
    if (lid == 0) { red[wid * 3] = r0; red[wid * 3 + 1] = r1; red[wid * 3 + 2] = r2; }
    __syncthreads();
    if (c < 3) {
        float s = 0.f;
        #pragma unroll
        for (int w = 0; w < 8; w++) s += red[w * 3 + c];
        g_dv[n * 3 + c] = s;
    }
}

// ---------------- K7: node MLPs ----------------
__global__ void k_node(const float* __restrict__ h, const float* __restrict__ x,
                       const float* __restrict__ v,
                       const float* __restrict__ W_post1, const float* __restrict__ b_post1,
                       const float* __restrict__ W_post2, const float* __restrict__ b_post2,
                       const float* __restrict__ W_node1, const float* __restrict__ b_node1,
                       const float* __restrict__ W_node2, const float* __restrict__ b_node2,
                       const float* __restrict__ W_vel1,  const float* __restrict__ b_vel1,
                       const float* __restrict__ W_vel2,
                       float* __restrict__ out_h, float* __restrict__ out_x,
                       float* __restrict__ out_v, int N)
{
    extern __shared__ float sm[];
    float* sCN = sm;
    float* sHE = sCN + 8192;
    float* sH  = sHE + 8192;
    float* sT  = sH  + 2048;
    float* sHC = sT  + 2048;
    float* sHN = sHC + 2048;
    float* sBp1 = sHN + 2048;
    float* sBp2 = sBp1 + 64;
    float* sBn1 = sBp2 + 64;
    float* sBn2 = sBn1 + 64;
    float* sBv1 = sBn2 + 64;
    float* sWv2 = sBv1 + 64;
    float* sWbuf = sWv2 + 64;

    int tid = threadIdx.x;
    int n0 = blockIdx.x * 32;
    int nn = min(32, N - n0);

    for (int i = tid; i < nn * 256; i += 256) { sCN[i] = g_cnorm[n0 * 256 + i]; sHE[i] = g_he[n0 * 256 + i]; }
    for (int i = tid; i < nn * 64;  i += 256) sH[i] = h[n0 * 64 + i];
    if (tid < 64) {
        sBp1[tid] = b_post1[tid]; sBp2[tid] = b_post2[tid];
        sBn1[tid] = b_node1[tid]; sBn2[tid] = b_node2[tid];
        sBv1[tid] = b_vel1[tid];  sWv2[tid] = W_vel2[tid];
    }
    __syncthreads();

    for (int i = tid; i < 16384; i += 256) sWbuf[i] = W_post1[i];
    __syncthreads();
    for (int i = tid; i < nn * 16; i += 256) {
        int ln = i >> 4, j0 = (i & 15) * 4;
        float a0 = sBp1[j0], a1 = sBp1[j0 + 1], a2 = sBp1[j0 + 2], a3 = sBp1[j0 + 3];
        const float* cv = &sCN[ln * 256];
        #pragma unroll 4
        for (int c = 0; c < 256; c++) {
            float hv = cv[c];
            float4 w = *(const float4*)&sWbuf[c * 64 + j0];
            a0 += hv * w.x; a1 += hv * w.y; a2 += hv * w.z; a3 += hv * w.w;
        }
        float* o = &sT[ln * 64 + j0];
        o[0] = siluf(a0); o[1] = siluf(a1); o[2] = siluf(a2); o[3] = siluf(a3);
    }
    __syncthreads();

    for (int i = tid; i < 4096; i += 256) sWbuf[i] = W_post2[i];
    __syncthreads();
    for (int i = tid; i < nn * 16; i += 256) {
        int ln = i >> 4, j0 = (i & 15) * 4;
        float a0 = sBp2[j0], a1 = sBp2[j0 + 1], a2 = sBp2[j0 + 2], a3 = sBp2[j0 + 3];
        const float* tv = &sT[ln * 64];
        #pragma unroll 4
        for (int c = 0; c < 64; c++) {
            float hv = tv[c];
            float4 w = *(const float4*)&sWbuf[c * 64 + j0];
            a0 += hv * w.x; a1 += hv * w.y; a2 += hv * w.z; a3 += hv * w.w;
        }
        float* o = &sHC[ln * 64 + j0];
        o[0] = siluf(a0); o[1] = siluf(a1); o[2] = siluf(a2); o[3] = siluf(a3);
    }
    __syncthreads();

    for (int i = tid; i < 24576; i += 256) sWbuf[i] = W_node1[i];
    __syncthreads();
    for (int i = tid; i < nn * 16; i += 256) {
        int ln = i >> 4, j0 = (i & 15) * 4;
        float a0 = sBn1[j0], a1 = sBn1[j0 + 1], a2 = sBn1[j0 + 2], a3 = sBn1[j0 + 3];
        const float* hv2 = &sH[ln * 64];
        #pragma unroll 4
        for (int c = 0; c < 64; c++) {
            float hv = hv2[c];
            float4 w = *(const float4*)&sWbuf[c * 64 + j0];
            a0 += hv * w.x; a1 += hv * w.y; a2 += hv * w.z; a3 += hv * w.w;
        }
        const float* he = &sHE[ln * 256];
        #pragma unroll 4
        for (int c = 0; c < 256; c++) {
            float hv = he[c];
            float4 w = *(const float4*)&sWbuf[(64 + c) * 64 + j0];
            a0 += hv * w.x; a1 += hv * w.y; a2 += hv * w.z; a3 += hv * w.w;
        }
        const float* hc = &sHC[ln * 64];
        #pragma unroll 4
        for (int c = 0; c < 64; c++) {
            float hv = hc[c];
            float4 w = *(const float4*)&sWbuf[(320 + c) * 64 + j0];
            a0 += hv * w.x; a1 += hv * w.y; a2 += hv * w.z; a3 += hv * w.w;
        }
        float* o = &sT[ln * 64 + j0];
        o[0] = siluf(a0); o[1] = siluf(a1); o[2] = siluf(a2); o[3] = siluf(a3);
    }
    __syncthreads();

    for (int i = tid; i < 4096; i += 256) sWbuf[i] = W_node2[i];
    __syncthreads();
    for (int i = tid; i < nn * 16; i += 256) {
        int ln = i >> 4, j0 = (i & 15) * 4;
        float a0 = sBn2[j0], a1 = sBn2[j0 + 1], a2 = sBn2[j0 + 2], a3 = sBn2[j0 + 3];
        const float* tv = &sT[ln * 64];
        #pragma unroll 4
        for (int c = 0; c < 64; c++) {
            float hv = tv[c];
            float4 w = *(const float4*)&sWbuf[c * 64 + j0];
            a0 += hv * w.x; a1 += hv * w.y; a2 += hv * w.z; a3 += hv * w.w;
        }
        int n = n0 + ln;
        float h0 = sH[ln * 64 + j0]     + siluf(a0);
        float h1 = sH[ln * 64 + j0 + 1] + siluf(a1);
        float h2 = sH[ln * 64 + j0 + 2] + siluf(a2);
        float h3 = sH[ln * 64 + j0 + 3] + siluf(a3);
        float* o = &sHN[ln * 64 + j0];
        o[0] = h0; o[1] = h1; o[2] = h2; o[3] = h3;
        *(float4*)&out_h[n * 64 + j0] = make_float4(h0, h1, h2, h3);
    }
    __syncthreads();

    for (int i = tid; i < 4096; i += 256) sWbuf[i] = W_vel1[i];
    __syncthreads();
    for (int i = tid; i < nn * 16; i += 256) {
        int ln = i >> 4, j0 = (i & 15) * 4;
        float a0 = sBv1[j0], a1 = sBv1[j0 + 1], a2 = sBv1[j0 + 2], a3 = sBv1[j0 + 3];
        const float* hv2 = &sHN[ln * 64];
        #pragma unroll 4
        for (int c = 0; c < 64; c++) {
            float hv = hv2[c];
            float4 w = *(const float4*)&sWbuf[c * 64 + j0];
            a0 += hv * w.x; a1 += hv * w.y; a2 += hv * w.z; a3 += hv * w.w;
        }
        float* o = &sT[ln * 64 + j0];
        o[0] = siluf(a0) * sWv2[j0];
        o[1] = siluf(a1) * sWv2[j0 + 1];
        o[2] = siluf(a2) * sWv2[j0 + 2];
        o[3] = siluf(a3) * sWv2[j0 + 3];
    }
    __syncthreads();

    if (tid < nn) {
        int ln = tid;
        float s = 0.f;
        #pragma unroll 8
        for (int k = 0; k < 64; k++) s += sT[ln * 64 + k];
        float scale = 2.f / (1.f + __expf(-s));
        int n = n0 + ln;
        #pragma unroll
        for (int d = 0; d < 3; d++) {
            float vn = g_dv[n * 3 + d] + scale * v[n * 3 + d];
            out_v[n * 3 + d] = vn;
            out_x[n * 3 + d] = x[n * 3 + d] + vn;
        }
    }
}

// ---------------- launch ----------------
extern "C" void kernel_launch(void* const* d_in, const int* in_sizes, int n_in,
                              void* d_out, int out_size)
{
    const float* h        = (const float*)d_in[0];
    const float* x        = (const float*)d_in[1];
    const float* v        = (const float*)d_in[2];
    const int*   idxs     = (const int*)  d_in[3];
    const float* rbf_mean = (const float*)d_in[4];
    const float* rbf_beta = (const float*)d_in[5];
    const float* W_in     = (const float*)d_in[6];
    const float* b_in     = (const float*)d_in[7];
    const float* W_out1   = (const float*)d_in[8];
    const float* b_out1   = (const float*)d_in[9];
    const float* W_out2   = (const float*)d_in[10];
    const float* b_out2   = (const float*)d_in[11];
    const float* W_att    = (const float*)d_in[12];
    const float* b_att    = (const float*)d_in[13];
    const float* W_xmix   = (const float*)d_in[14];
    const float* W_post1  = (const float*)d_in[15];
    const float* b_post1  = (const float*)d_in[16];
    const float* W_post2  = (const float*)d_in[17];
    const float* b_post2  = (const float*)d_in[18];
    const float* W_node1  = (const float*)d_in[19];
    const float* b_node1  = (const float*)d_in[20];
    const float* W_node2  = (const float*)d_in[21];
    const float* b_node2  = (const float*)d_in[22];
    const float* W_vmix   = (const float*)d_in[23];
    const float* W_vel1   = (const float*)d_in[24];
    const float* b_vel1   = (const float*)d_in[25];
    const float* W_vel2   = (const float*)d_in[26];

    int N = in_sizes[0] / 64;
    int E = in_sizes[3] / 2;

    float* out  = (float*)d_out;
    float* outh = out;
    float* outx = out + (size_t)N * 64;
    float* outv = out + (size_t)N * 67;

    const int SM_NODE = (8192 * 2 + 2048 * 4 + 64 * 6 + 24576) * 4;

    cudaFuncSetAttribute(k_edge_mma, cudaFuncAttributeMaxDynamicSharedMemorySize, E_SMEM);
    cudaFuncSetAttribute(k_xagg,     cudaFuncAttributeMaxDynamicSharedMemorySize, XG_SMEM);
    cudaFuncSetAttribute(k_node,     cudaFuncAttributeMaxDynamicSharedMemorySize, SM_NODE);

    k_init<<<(N * 768 + 255) / 256, 256>>>(N);
    k_wprep<<<256, 256>>>(W_xmix);
    k_eprep<<<48, 256>>>(W_in, W_out1, W_out2);
    k_edge_mma<<<296, 256, E_SMEM>>>(h, x, idxs, rbf_mean, rbf_beta,
                                     b_in, b_out1, b_out2, W_att, b_att, E);
    k_scan<<<1, 1024>>>(N);
    k_fillexp<<<(E + 255) / 256, 256>>>(idxs, E);
    k_xagg<<<(E + 63) / 64, 256, XG_SMEM>>>(idxs, W_vmix, E);
    k_fin<<<N, 256>>>(W_vmix, N);
    k_node<<<(N + 31) / 32, 256, SM_NODE>>>(h, x, v,
                                            W_post1, b_post1, W_post2, b_post2,
                                            W_node1, b_node1, W_node2, b_node2,
                                            W_vel1, b_vel1, W_vel2,
                                            outh, outx, outv, N);
}

// round 8
// speedup vs baseline: 2.9064x; 1.0067x over previous
#include <cuda_runtime.h>
#include <cuda_fp16.h>
#include <stdint.h>
#include <math.h>

#define NMAX 10000
#define EMAX 160000

// ---------------- scratch ----------------
__device__ float g_hemtx[EMAX * 64];
__device__ float g_xhat[EMAX * 3];
__device__ float g_w[EMAX * 4];
__device__ float g_nodemax[NMAX * 4];
__device__ float g_expsum[NMAX * 4];
__device__ int   g_counts[NMAX];
__device__ int   g_off[NMAX + 1];
__device__ int   g_cursor[NMAX];
__device__ int   g_eid[EMAX];
__device__ float g_he[NMAX * 256];
__device__ float g_cnorm[NMAX * 256];
__device__ float g_comb[NMAX * 768];
__device__ int   g_bflag[NMAX];
__device__ float g_dv[NMAX * 3];
__device__ __half g_wx[256 * 256];       // W_xmix^T fp16 [n][k]
__device__ uint32_t g_ewi[4096];
__device__ uint32_t g_ew1a[4096];
__device__ uint32_t g_ew1b[2048];
__device__ uint32_t g_ew2[2048];

__device__ __forceinline__ float siluf(float x) { return x / (1.f + __expf(-x)); }
__device__ __forceinline__ float fast_tanh(float x) {
    float y; asm("tanh.approx.f32 %0, %1;" : "=f"(y) : "f"(x)); return y;
}
__device__ __forceinline__ void atomicMaxF(float* a, float v) {
    if (v >= 0.f) atomicMax((int*)a, __float_as_int(v));
    else          atomicMin((unsigned int*)a, (unsigned int)__float_as_int(v));
}
__device__ __forceinline__ void mma16816h(float* d, const uint32_t* a, const uint32_t* b) {
    asm volatile("mma.sync.aligned.m16n8k16.row.col.f32.f16.f16.f32 "
        "{%0,%1,%2,%3}, {%4,%5,%6,%7}, {%8,%9}, {%0,%1,%2,%3};"
        : "+f"(d[0]), "+f"(d[1]), "+f"(d[2]), "+f"(d[3])
        : "r"(a[0]), "r"(a[1]), "r"(a[2]), "r"(a[3]), "r"(b[0]), "r"(b[1]));
}
__device__ __forceinline__ uint32_t pack2h(float a, float b) {
    __half2 p = __floats2half2_rn(a, b);
    return *(uint32_t*)&p;
}
__device__ __forceinline__ uint32_t smem_u32(const void* p) {
    uint32_t a;
    asm("{ .reg .u64 t; cvta.to.shared.u64 t, %1; cvt.u32.u64 %0, t; }" : "=r"(a) : "l"(p));
    return a;
}
#define LDSM4(r0, r1, r2, r3, addr) \
    asm volatile("ldmatrix.sync.aligned.m8n8.x4.shared.b16 {%0,%1,%2,%3}, [%4];" \
        : "=r"(r0), "=r"(r1), "=r"(r2), "=r"(r3) : "r"(addr))

// ---------------- K0: init + weight prep (merged) ----------------
__global__ void k_init(int N,
                       const float* __restrict__ W_xmix,
                       const float* __restrict__ W_in,
                       const float* __restrict__ W_out1,
                       const float* __restrict__ W_out2) {
    int i = blockIdx.x * blockDim.x + threadIdx.x;
    if (i < N * 4) {
        g_nodemax[i] = __int_as_float(0xff800000);
        g_expsum[i]  = 0.f;
    }
    if (i < N) { g_counts[i] = 0; g_bflag[i] = 0; }
    if (i < N * 3) g_dv[i] = 0.f;
    if (i < N * 256) { g_he[i] = 0.f; g_cnorm[i] = 0.f; }
    if (i < N * 768) g_comb[i] = 0.f;
    if (i < 65536) {
        int n = i >> 8, k = i & 255;
        g_wx[n * 256 + k] = __float2half_rn(W_xmix[k * 256 + n]);
    }
    if (i < 4096) {
        int n = i >> 6, k0 = (i & 63) * 2;
        float w0 = (n < 50) ? W_in[k0 * 50 + n] : 0.f;
        float w1 = (n < 50) ? W_in[(k0 + 1) * 50 + n] : 0.f;
        g_ewi[i] = pack2h(w0, w1);
    } else if (i < 8192) {
        int j = i - 4096;
        int n = j >> 6, k0 = (j & 63) * 2;
        g_ew1a[j] = pack2h(W_out1[k0 * 64 + n], W_out1[(k0 + 1) * 64 + n]);
    } else if (i < 10240) {
        int j = i - 8192;
        int n = j >> 5, k0 = (j & 31) * 2;
        float w0 = (k0 < 50) ? W_out1[(128 + k0) * 64 + n] : ((k0 == 50) ? W_out1[178 * 64 + n] : 0.f);
        int k1 = k0 + 1;
        float w1 = (k1 < 50) ? W_out1[(128 + k1) * 64 + n] : ((k1 == 50) ? W_out1[178 * 64 + n] : 0.f);
        g_ew1b[j] = pack2h(w0, w1);
    } else if (i < 12288) {
        int j = i - 10240;
        int n = j >> 5, k0 = (j & 31) * 2;
        g_ew2[j] = pack2h(W_out2[k0 * 64 + n], W_out2[(k0 + 1) * 64 + n]);
    }
}

// ---------------- K1: edge MLP via fp16 mma.sync + ldmatrix ----------------
#define O_A     0
#define O_X     4352
#define O_M     6656
#define O_WI    8960
#define O_W1A   13312
#define O_W1B   17664
#define O_W2    19968
#define O_HE    22272
#define O_BIN   26496
#define O_BO1   26560
#define O_BO2   26624
#define O_MEAN  26688
#define O_BETA  26752
#define O_WA    26816
#define O_BA    27072
#define O_NORM  27076
#define O_EX    27140
#define O_XHT   27204
#define E_SMEM  (27400 * 4)

__global__ void __launch_bounds__(256, 2)
k_edge_mma(const float* __restrict__ h, const float* __restrict__ x,
           const int* __restrict__ idxs,
           const float* __restrict__ rbf_means, const float* __restrict__ rbf_betas,
           const float* __restrict__ b_in, const float* __restrict__ b_out1,
           const float* __restrict__ b_out2,
           const float* __restrict__ W_att, const float* __restrict__ b_att, int E)
{
    extern __shared__ uint32_t su[];
    float* sf = (float*)su;
    int tid = threadIdx.x, lid = tid & 31, wid = tid >> 5;
    int g = lid >> 2, tg = lid & 3;
    int mrow = (wid & 3) * 16, ncol = (wid >> 2) * 32;

    for (int i = tid; i < 4096; i += 256) {
        int n = i >> 6, kk = i & 63;
        su[O_WI  + n * 68 + kk] = g_ewi[i];
        su[O_W1A + n * 68 + kk] = g_ew1a[i];
    }
    for (int i = tid; i < 2048; i += 256) {
        int n = i >> 5, kk = i & 31;
        su[O_W1B + n * 36 + kk] = g_ew1b[i];
        su[O_W2  + n * 36 + kk] = g_ew2[i];
    }
    if (tid < 64) {
        sf[O_BIN + tid]  = (tid < 50) ? b_in[tid] : 0.f;
        sf[O_BO1 + tid]  = b_out1[tid];
        sf[O_BO2 + tid]  = b_out2[tid];
        sf[O_MEAN + tid] = (tid < 50) ? rbf_means[tid] : 0.f;
        sf[O_BETA + tid] = (tid < 50) ? rbf_betas[tid] : 1.f;
    }
    if (tid < 256) sf[O_WA + tid] = W_att[tid];
    if (tid < 4)   sf[O_BA + tid] = b_att[tid];
    __syncthreads();

    // per-lane ldmatrix addresses
    uint32_t sbase = smem_u32(su);
    int mq = lid >> 3, rr = lid & 7;
    int rA = mrow + (mq & 1) * 8 + rr;
    int cA = (mq >> 1) * 4;
    uint32_t adA  = sbase + (O_A  + rA * 68 + cA) * 4;
    uint32_t adX  = sbase + (O_X  + rA * 36 + cA) * 4;
    uint32_t adM  = sbase + (O_M  + rA * 36 + cA) * 4;
    int rB = (mq >> 1) * 8 + rr;
    int cB = (mq & 1) * 4;
    uint32_t adWI0  = sbase + (O_WI  + (ncol + rB) * 68 + cB) * 4;
    uint32_t adWI1  = sbase + (O_WI  + (ncol + 16 + rB) * 68 + cB) * 4;
    uint32_t adW1A0 = sbase + (O_W1A + (ncol + rB) * 68 + cB) * 4;
    uint32_t adW1A1 = sbase + (O_W1A + (ncol + 16 + rB) * 68 + cB) * 4;
    uint32_t adW1B0 = sbase + (O_W1B + (ncol + rB) * 36 + cB) * 4;
    uint32_t adW1B1 = sbase + (O_W1B + (ncol + 16 + rB) * 36 + cB) * 4;
    uint32_t adW20  = sbase + (O_W2  + (ncol + rB) * 36 + cB) * 4;
    uint32_t adW21  = sbase + (O_W2  + (ncol + 16 + rB) * 36 + cB) * 4;

    int ntiles = (E + 63) / 64;
    for (int tile = blockIdx.x; tile < ntiles; tile += gridDim.x) {
        int e0 = tile * 64, ne = min(64, E - e0);

        if (tid < 64) {
            float nrm = 0.f, xh0 = 0.f, xh1 = 0.f, xh2 = 0.f;
            if (tid < ne) {
                int s = idxs[2 * (e0 + tid)], d = idxs[2 * (e0 + tid) + 1];
                float dx = x[3 * s]     - x[3 * d];
                float dy = x[3 * s + 1] - x[3 * d + 1];
                float dz = x[3 * s + 2] - x[3 * d + 2];
                nrm = sqrtf(dx * dx + dy * dy + dz * dz + 1e-14f);
                float inv = 1.f / (nrm + 1e-5f);
                xh0 = dx * inv; xh1 = dy * inv; xh2 = dz * inv;
                atomicAdd(&g_counts[s], 1);
            }
            sf[O_NORM + tid] = nrm;
            sf[O_EX + tid]   = __expf(-nrm);
            sf[O_XHT + tid * 3] = xh0; sf[O_XHT + tid * 3 + 1] = xh1; sf[O_XHT + tid * 3 + 2] = xh2;
        }
        {
            int el = tid >> 2, part = tid & 3;
            uint32_t hb[16];
            if (el < ne) {
                int node = idxs[2 * (e0 + el) + (part >> 1)];
                const float4* hp = (const float4*)&h[node * 64 + (part & 1) * 32];
                #pragma unroll
                for (int i2 = 0; i2 < 8; i2++) {
                    float4 v = hp[i2];
                    hb[i2 * 2]     = pack2h(v.x, v.y);
                    hb[i2 * 2 + 1] = pack2h(v.z, v.w);
                }
            } else {
                #pragma unroll
                for (int i2 = 0; i2 < 16; i2++) hb[i2] = 0u;
            }
            uint4* dh = (uint4*)&su[O_A + el * 68 + part * 16];
            #pragma unroll
            for (int i2 = 0; i2 < 4; i2++)
                dh[i2] = make_uint4(hb[i2*4], hb[i2*4+1], hb[i2*4+2], hb[i2*4+3]);
        }
        __syncthreads();

        float acc[4][4];

        // ---- G1: h_in = hcat @ Wi  (K=128) ----
        #pragma unroll
        for (int nt = 0; nt < 4; nt++)
            #pragma unroll
            for (int q = 0; q < 4; q++) acc[nt][q] = 0.f;
        #pragma unroll
        for (int ks = 0; ks < 8; ks++) {
            uint32_t aH[4];
            LDSM4(aH[0], aH[1], aH[2], aH[3], adA + ks * 32);
            uint32_t b0, b1, b2, b3;
            LDSM4(b0, b1, b2, b3, adWI0 + ks * 32);
            { uint32_t bb[2] = { b0, b1 }; mma16816h(acc[0], aH, bb); }
            { uint32_t bb[2] = { b2, b3 }; mma16816h(acc[1], aH, bb); }
            LDSM4(b0, b1, b2, b3, adWI1 + ks * 32);
            { uint32_t bb[2] = { b0, b1 }; mma16816h(acc[2], aH, bb); }
            { uint32_t bb[2] = { b2, b3 }; mma16816h(acc[3], aH, bb); }
        }
        #pragma unroll
        for (int nt = 0; nt < 4; nt++) {
            #pragma unroll
            for (int hh = 0; hh < 2; hh++) {
                int row = mrow + g + hh * 8;
                int c0 = ncol + nt * 8 + tg * 2;
                float v0 = acc[nt][hh * 2]     + sf[O_BIN + c0];
                float v1 = acc[nt][hh * 2 + 1] + sf[O_BIN + c0 + 1];
                float ex = sf[O_EX + row];
                float x0, x1;
                if (c0 < 50) { float d = ex - sf[O_MEAN + c0]; x0 = __expf(-sf[O_BETA + c0] * d * d) * v0; }
                else x0 = (c0 == 50) ? sf[O_NORM + row] : 0.f;
                if (c0 + 1 < 50) { float d = ex - sf[O_MEAN + c0 + 1]; x1 = __expf(-sf[O_BETA + c0 + 1] * d * d) * v1; }
                else x1 = 0.f;
                su[O_X + row * 36 + (c0 >> 1)] = pack2h(x0, x1);
            }
        }
        __syncthreads();

        // ---- G2: mid = silu(hcat@W1a + _x@W1b + b1) ----
        #pragma unroll
        for (int nt = 0; nt < 4; nt++)
            #pragma unroll
            for (int q = 0; q < 4; q++) acc[nt][q] = 0.f;
        #pragma unroll
        for (int ks = 0; ks < 8; ks++) {
            uint32_t aH[4];
            LDSM4(aH[0], aH[1], aH[2], aH[3], adA + ks * 32);
            uint32_t b0, b1, b2, b3;
            LDSM4(b0, b1, b2, b3, adW1A0 + ks * 32);
            { uint32_t bb[2] = { b0, b1 }; mma16816h(acc[0], aH, bb); }
            { uint32_t bb[2] = { b2, b3 }; mma16816h(acc[1], aH, bb); }
            LDSM4(b0, b1, b2, b3, adW1A1 + ks * 32);
            { uint32_t bb[2] = { b0, b1 }; mma16816h(acc[2], aH, bb); }
            { uint32_t bb[2] = { b2, b3 }; mma16816h(acc[3], aH, bb); }
        }
        #pragma unroll
        for (int ks = 0; ks < 4; ks++) {
            uint32_t aH[4];
            LDSM4(aH[0], aH[1], aH[2], aH[3], adX + ks * 32);
            uint32_t b0, b1, b2, b3;
            LDSM4(b0, b1, b2, b3, adW1B0 + ks * 32);
            { uint32_t bb[2] = { b0, b1 }; mma16816h(acc[0], aH, bb); }
            { uint32_t bb[2] = { b2, b3 }; mma16816h(acc[1], aH, bb); }
            LDSM4(b0, b1, b2, b3, adW1B1 + ks * 32);
            { uint32_t bb[2] = { b0, b1 }; mma16816h(acc[2], aH, bb); }
            { uint32_t bb[2] = { b2, b3 }; mma16816h(acc[3], aH, bb); }
        }
        #pragma unroll
        for (int nt = 0; nt < 4; nt++) {
            #pragma unroll
            for (int hh = 0; hh < 2; hh++) {
                int row = mrow + g + hh * 8;
                int c0 = ncol + nt * 8 + tg * 2;
                float m0 = siluf(acc[nt][hh * 2]     + sf[O_BO1 + c0]);
                float m1 = siluf(acc[nt][hh * 2 + 1] + sf[O_BO1 + c0 + 1]);
                su[O_M + row * 36 + (c0 >> 1)] = pack2h(m0, m1);
            }
        }
        __syncthreads();

        // ---- G3: h_e = mid @ W2 + b2 ----
        #pragma unroll
        for (int nt = 0; nt < 4; nt++)
            #pragma unroll
            for (int q = 0; q < 4; q++) acc[nt][q] = 0.f;
        #pragma unroll
        for (int ks = 0; ks < 4; ks++) {
            uint32_t aH[4];
            LDSM4(aH[0], aH[1], aH[2], aH[3], adM + ks * 32);
            uint32_t b0, b1, b2, b3;
            LDSM4(b0, b1, b2, b3, adW20 + ks * 32);
            { uint32_t bb[2] = { b0, b1 }; mma16816h(acc[0], aH, bb); }
            { uint32_t bb[2] = { b2, b3 }; mma16816h(acc[1], aH, bb); }
            LDSM4(b0, b1, b2, b3, adW21 + ks * 32);
            { uint32_t bb[2] = { b0, b1 }; mma16816h(acc[2], aH, bb); }
            { uint32_t bb[2] = { b2, b3 }; mma16816h(acc[3], aH, bb); }
        }
        #pragma unroll
        for (int nt = 0; nt < 4; nt++) {
            #pragma unroll
            for (int hh = 0; hh < 2; hh++) {
                int row = mrow + g + hh * 8;
                int c0 = ncol + nt * 8 + tg * 2;
                sf[O_HE + row * 66 + c0]     = acc[nt][hh * 2]     + sf[O_BO2 + c0];
                sf[O_HE + row * 66 + c0 + 1] = acc[nt][hh * 2 + 1] + sf[O_BO2 + c0 + 1];
            }
        }
        __syncthreads();

        {
            int el = tid >> 2, a = tid & 3;
            if (el < ne) {
                float acc2 = sf[O_BA + a];
                const float* hv = &sf[O_HE + el * 66];
                #pragma unroll 8
                for (int c = 0; c < 64; c++) acc2 += hv[c] * sf[O_WA + c * 4 + a];
                float lg = (acc2 > 0.f) ? acc2 : 2.f * (__expf(acc2 * 0.5f) - 1.f);
                int s = idxs[2 * (e0 + el)];
                g_w[(e0 + el) * 4 + a] = lg;
                atomicMaxF(&g_nodemax[s * 4 + a], lg);
            }
        }
        for (int i = tid; i < ne * 16; i += 256) {
            int el = i >> 4, c = (i & 15) * 4;
            float4 o = make_float4(sf[O_HE + el * 66 + c], sf[O_HE + el * 66 + c + 1],
                                   sf[O_HE + el * 66 + c + 2], sf[O_HE + el * 66 + c + 3]);
            *(float4*)&g_hemtx[(size_t)(e0 + el) * 64 + c] = o;
        }
        for (int i = tid; i < ne * 3; i += 256) g_xhat[e0 * 3 + i] = sf[O_XHT + i];
        __syncthreads();
    }
}

// ---------------- K2: exclusive scan ----------------
__global__ void k_scan(int N) {
    __shared__ int ssum[1024];
    int t = threadIdx.x;
    int chunk = (N + 1023) / 1024;
    int base = t * chunk;
    int vals[16];
    int loc = 0;
    for (int k = 0; k < chunk; k++) {
        int idx = base + k;
        int v = (idx < N) ? g_counts[idx] : 0;
        vals[k] = loc; loc += v;
    }
    ssum[t] = loc; __syncthreads();
    for (int off = 1; off < 1024; off <<= 1) {
        int v = (t >= off) ? ssum[t - off] : 0;
        __syncthreads();
        ssum[t] += v;
        __syncthreads();
    }
    int excl = ssum[t] - loc;
    for (int k = 0; k < chunk; k++) {
        int idx = base + k;
        if (idx < N) { g_off[idx] = excl + vals[k]; g_cursor[idx] = excl + vals[k]; }
    }
    if (t == 1023) g_off[N] = excl + loc;
}

// ---------------- K3: CSR fill + exp + expsum ----------------
__global__ void k_fillexp(const int* __restrict__ idxs, int E) {
    int e = blockIdx.x * blockDim.x + threadIdx.x;
    if (e >= E) return;
    int s = idxs[2 * e];
    int p = atomicAdd(&g_cursor[s], 1);
    g_eid[p] = e;
    #pragma unroll
    for (int a = 0; a < 4; a++) {
        float w = __expf(g_w[e * 4 + a] - g_nodemax[s * 4 + a]);
        g_w[e * 4 + a] = w;
        atomicAdd(&g_expsum[s * 4 + a], w);
    }
}

// ---------------- K5: fused xmix GEMM + per-node aggregation ----------------
#define XG_A    0
#define XG_W    8448
#define XG_HM   17664
#define XG_ATT  21952
#define XG_XH   22208
#define XG_NODE 22400
#define XG_WV   22464
#define XG_RED  22720
#define XG_SMEM (22744 * 4)

__global__ void __launch_bounds__(256, 2)
k_xagg(const int* __restrict__ idxs, const float* __restrict__ W_vmix, int E)
{
    extern __shared__ uint32_t su[];
    float* sf = (float*)su;
    int tid = threadIdx.x, lid = tid & 31, wid = tid >> 5;
    int p0 = blockIdx.x * 64;
    uint32_t* pA = su + XG_A;
    uint32_t* pW = su + XG_W;
    int* sN = (int*)(su + XG_NODE);

    // ---- prologue: gather per CSR slot ----
    {
        int sl = tid & 63, kq = tid >> 6;
        int e = -1, s = -1;
        float att[4], hm[16];
        int p = p0 + sl;
        if (p < E) {
            e = g_eid[p];
            s = idxs[2 * e];
            #pragma unroll
            for (int a = 0; a < 4; a++) att[a] = g_w[e * 4 + a] / g_expsum[s * 4 + a];
            const float4* hp = (const float4*)&g_hemtx[(size_t)e * 64 + kq * 16];
            #pragma unroll
            for (int i = 0; i < 4; i++) {
                float4 v = hp[i];
                hm[i * 4] = v.x; hm[i * 4 + 1] = v.y; hm[i * 4 + 2] = v.z; hm[i * 4 + 3] = v.w;
            }
        } else {
            #pragma unroll
            for (int a = 0; a < 4; a++) att[a] = 0.f;
            #pragma unroll
            for (int i = 0; i < 16; i++) hm[i] = 0.f;
        }
        if (kq == 0) {
            sN[sl] = s;
            #pragma unroll
            for (int a = 0; a < 4; a++) sf[XG_ATT + sl * 4 + a] = att[a];
            float x0 = 0.f, x1 = 0.f, x2 = 0.f;
            if (e >= 0) { x0 = g_xhat[e * 3]; x1 = g_xhat[e * 3 + 1]; x2 = g_xhat[e * 3 + 2]; }
            sf[XG_XH + sl * 3] = x0; sf[XG_XH + sl * 3 + 1] = x1; sf[XG_XH + sl * 3 + 2] = x2;
        }
        #pragma unroll
        for (int i = 0; i < 16; i++) sf[XG_HM + sl * 67 + kq * 16 + i] = hm[i];
        #pragma unroll
        for (int j = 0; j < 32; j++) {
            int kl = 2 * j;
            float m = hm[kl >> 2];
            pA[sl * 132 + ((kq * 64 + kl) >> 1)] = pack2h(m * att[kl & 3], m * att[(kl + 1) & 3]);
        }
        sf[XG_WV + tid] = W_vmix[tid];
    }

    // ---- MMA phase with ldmatrix ----
    int g = lid >> 2, tg = lid & 3;
    int mrow = (wid & 1) * 32;
    int ncol = (wid >> 1) * 64;

    uint32_t sbase = smem_u32(su);
    int mq = lid >> 3, rr = lid & 7;
    uint32_t adA0 = sbase + (XG_A + (mrow + (mq & 1) * 8 + rr) * 132 + (mq >> 1) * 4) * 4;
    uint32_t adA1 = adA0 + 16 * 132 * 4;
    int rB = (mq >> 1) * 8 + rr;
    int cB = (mq & 1) * 4;
    uint32_t adW0 = sbase + (XG_W + (ncol + rB) * 36 + cB) * 4;
    uint32_t adW1 = adW0 + 16 * 36 * 4;
    uint32_t adW2 = adW0 + 32 * 36 * 4;
    uint32_t adW3 = adW0 + 48 * 36 * 4;

    float acc[2][8][4];
    #pragma unroll
    for (int mt = 0; mt < 2; mt++)
        #pragma unroll
        for (int nt = 0; nt < 8; nt++)
            #pragma unroll
            for (int q = 0; q < 4; q++) acc[mt][nt][q] = 0.f;

    for (int kc = 0; kc < 4; kc++) {
        __syncthreads();
        {
            int n = tid;
            const uint4* src = (const uint4*)&g_wx[n * 256 + kc * 64];
            uint4* dst = (uint4*)(pW + n * 36);
            #pragma unroll
            for (int i = 0; i < 8; i++) dst[i] = src[i];
        }
        __syncthreads();

        #pragma unroll
        for (int ks = 0; ks < 4; ks++) {
            uint32_t aoff = kc * 128 + ks * 32;
            uint32_t aH[2][4];
            LDSM4(aH[0][0], aH[0][1], aH[0][2], aH[0][3], adA0 + aoff);
            LDSM4(aH[1][0], aH[1][1], aH[1][2], aH[1][3], adA1 + aoff);
            uint32_t woff = ks * 32;
            uint32_t b0, b1, b2, b3;
            #define XAGG_PAIR(ADDR, NT) \
                LDSM4(b0, b1, b2, b3, (ADDR) + woff); \
                { uint32_t bb[2] = { b0, b1 }; mma16816h(acc[0][NT], aH[0], bb); mma16816h(acc[1][NT], aH[1], bb); } \
                { uint32_t bb[2] = { b2, b3 }; mma16816h(acc[0][(NT)+1], aH[0], bb); mma16816h(acc[1][(NT)+1], aH[1], bb); }
            XAGG_PAIR(adW0, 0)
            XAGG_PAIR(adW1, 2)
            XAGG_PAIR(adW2, 4)
            XAGG_PAIR(adW3, 6)
            #undef XAGG_PAIR
        }
    }

    // ---- coeff = tanh(acc) -> smem (aliases A) ----
    __syncthreads();
    #pragma unroll
    for (int mt = 0; mt < 2; mt++)
        #pragma unroll
        for (int nt = 0; nt < 8; nt++) {
            int rl = mrow + mt * 16 + g;
            int col = ncol + nt * 8 + tg * 2;
            float* a = acc[mt][nt];
            pA[rl * 132 + (col >> 1)]       = pack2h(fast_tanh(a[0]), fast_tanh(a[1]));
            pA[(rl + 8) * 132 + (col >> 1)] = pack2h(fast_tanh(a[2]), fast_tanh(a[3]));
        }
    __syncthreads();

    // ---- segmented per-node reduction ----
    {
        int c = tid;
        float wv = sf[XG_WV + c];
        float accH = 0.f, a0 = 0.f, a1 = 0.f, a2 = 0.f;
        int segStart = 0;
        for (int sl = 0; sl < 64; sl++) {
            int n = sN[sl];
            if (n >= 0) {
                float A32 = sf[XG_HM + sl * 67 + (c >> 2)] * sf[XG_ATT + sl * 4 + (c & 3)];
                accH += A32;
                uint32_t cp = pA[sl * 132 + (c >> 1)];
                __half2 h2 = *(__half2*)&cp;
                float cf = (c & 1) ? __high2float(h2) : __low2float(h2);
                a0 += cf * sf[XG_XH + sl * 3];
                a1 += cf * sf[XG_XH + sl * 3 + 1];
                a2 += cf * sf[XG_XH + sl * 3 + 2];
            }
            bool segEnd = (sl == 63) || (sN[sl + 1] != n);
            if (segEnd) {
                if (n >= 0) {
                    int beg = g_off[n], end = g_off[n + 1];
                    bool full = (beg == p0 + segStart) && (end == p0 + sl + 1);
                    if (full) {
                        float invc = 1.f / ((float)(end - beg) + 1.f);
                        g_he[n * 256 + c] = accH;
                        float s0 = a0 * invc, s1 = a1 * invc, s2 = a2 * invc;
                        g_cnorm[n * 256 + c] = s0 * s0 + s1 * s1 + s2 * s2;
                        float r0 = wv * s0, r1 = wv * s1, r2 = wv * s2;
                        #pragma unroll
                        for (int o = 16; o > 0; o >>= 1) {
                            r0 += __shfl_xor_sync(0xFFFFFFFFu, r0, o);
                            r1 += __shfl_xor_sync(0xFFFFFFFFu, r1, o);
                            r2 += __shfl_xor_sync(0xFFFFFFFFu, r2, o);
                        }
                        if (lid == 0) {
                            sf[XG_RED + wid * 3]     = r0;
                            sf[XG_RED + wid * 3 + 1] = r1;
                            sf[XG_RED + wid * 3 + 2] = r2;
                        }
                        __syncthreads();
                        if (c < 3) {
                            float s = 0.f;
                            #pragma unroll
                            for (int w = 0; w < 8; w++) s += sf[XG_RED + w * 3 + c];
                            g_dv[n * 3 + c] = s;
                        }
                        __syncthreads();
                    } else {
                        atomicAdd(&g_he[n * 256 + c], accH);
                        atomicAdd(&g_comb[((size_t)n * 3 + 0) * 256 + c], a0);
                        atomicAdd(&g_comb[((size_t)n * 3 + 1) * 256 + c], a1);
                        atomicAdd(&g_comb[((size_t)n * 3 + 2) * 256 + c], a2);
                        if (c == 0) g_bflag[n] = 1;
                    }
                }
                accH = 0.f; a0 = 0.f; a1 = 0.f; a2 = 0.f;
                segStart = sl + 1;
            }
        }
    }
}

// ---------------- K_fin: finish boundary nodes ----------------
__global__ void k_fin(const float* __restrict__ W_vmix, int N) {
    __shared__ float red[24];
    int n = blockIdx.x;
    if (!g_bflag[n]) return;
    int c = threadIdx.x, lid = c & 31, wid = c >> 5;
    int beg = g_off[n], end = g_off[n + 1];
    float invc = 1.f / ((float)(end - beg) + 1.f);
    float s0 = g_comb[((size_t)n * 3 + 0) * 256 + c] * invc;
    float s1 = g_comb[((size_t)n * 3 + 1) * 256 + c] * invc;
    float s2 = g_comb[((size_t)n * 3 + 2) * 256 + c] * invc;
    g_cnorm[n * 256 + c] = s0 * s0 + s1 * s1 + s2 * s2;
    float wv = W_vmix[c];
    float r0 = wv * s0, r1 = wv * s1, r2 = wv * s2;
    #pragma unroll
    for (int o = 16; o > 0; o >>= 1) {
        r0 += __shfl_xor_sync(0xFFFFFFFFu, r0, o);
        r1 += __shfl_xor_sync(0xFFFFFFFFu, r1, o);
        r2 += __shfl_xor_sync(0xFFFFFFFFu, r2, o);
    }
    if (lid == 0) { red[wid * 3] = r0; red[wid * 3 + 1] = r1; red[wid * 3 + 2] = r2; }
    __syncthreads();
    if (c < 3) {
        float s = 0.f;
        #pragma unroll
        for (int w = 0; w < 8; w++) s += red[w * 3 + c];
        g_dv[n * 3 + c] = s;
    }
}

// ---------------- K7: node MLPs ----------------
__global__ void k_node(const float* __restrict__ h, const float* __restrict__ x,
                       const float* __restrict__ v,
                       const float* __restrict__ W_post1, const float* __restrict__ b_post1,
                       const float* __restrict__ W_post2, const float* __restrict__ b_post2,
                       const float* __restrict__ W_node1, const float* __restrict__ b_node1,
                       const float* __restrict__ W_node2, const float* __restrict__ b_node2,
                       const float* __restrict__ W_vel1,  const float* __restrict__ b_vel1,
                       const float* __restrict__ W_vel2,
                       float* __restrict__ out_h, float* __restrict__ out_x,
                       float* __restrict__ out_v, int N)
{
    extern __shared__ float sm[];
    float* sCN = sm;
    float* sHE = sCN + 8192;
    float* sH  = sHE + 8192;
    float* sT  = sH  + 2048;
    float* sHC = sT  + 2048;
    float* sHN = sHC + 2048;
    float* sBp1 = sHN + 2048;
    float* sBp2 = sBp1 + 64;
    float* sBn1 = sBp2 + 64;
    float* sBn2 = sBn1 + 64;
    float* sBv1 = sBn2 + 64;
    float* sWv2 = sBv1 + 64;
    float* sWbuf = sWv2 + 64;

    int tid = threadIdx.x;
    int n0 = blockIdx.x * 32;
    int nn = min(32, N - n0);

    for (int i = tid; i < nn * 256; i += 256) { sCN[i] = g_cnorm[n0 * 256 + i]; sHE[i] = g_he[n0 * 256 + i]; }
    for (int i = tid; i < nn * 64;  i += 256) sH[i] = h[n0 * 64 + i];
    if (tid < 64) {
        sBp1[tid] = b_post1[tid]; sBp2[tid] = b_post2[tid];
        sBn1[tid] = b_node1[tid]; sBn2[tid] = b_node2[tid];
        sBv1[tid] = b_vel1[tid];  sWv2[tid] = W_vel2[tid];
    }
    __syncthreads();

    for (int i = tid; i < 16384; i += 256) sWbuf[i] = W_post1[i];
    __syncthreads();
    for (int i = tid; i < nn * 16; i += 256) {
        int ln = i >> 4, j0 = (i & 15) * 4;
        float a0 = sBp1[j0], a1 = sBp1[j0 + 1], a2 = sBp1[j0 + 2], a3 = sBp1[j0 + 3];
        const float* cv = &sCN[ln * 256];
        #pragma unroll 4
        for (int c = 0; c < 256; c++) {
            float hv = cv[c];
            float4 w = *(const float4*)&sWbuf[c * 64 + j0];
            a0 += hv * w.x; a1 += hv * w.y; a2 += hv * w.z; a3 += hv * w.w;
        }
        float* o = &sT[ln * 64 + j0];
        o[0] = siluf(a0); o[1] = siluf(a1); o[2] = siluf(a2); o[3] = siluf(a3);
    }
    __syncthreads();

    for (int i = tid; i < 4096; i += 256) sWbuf[i] = W_post2[i];
    __syncthreads();
    for (int i = tid; i < nn * 16; i += 256) {
        int ln = i >> 4, j0 = (i & 15) * 4;
        float a0 = sBp2[j0], a1 = sBp2[j0 + 1], a2 = sBp2[j0 + 2], a3 = sBp2[j0 + 3];
        const float* tv = &sT[ln * 64];
        #pragma unroll 4
        for (int c = 0; c < 64; c++) {
            float hv = tv[c];
            float4 w = *(const float4*)&sWbuf[c * 64 + j0];
            a0 += hv * w.x; a1 += hv * w.y; a2 += hv * w.z; a3 += hv * w.w;
        }
        float* o = &sHC[ln * 64 + j0];
        o[0] = siluf(a0); o[1] = siluf(a1); o[2] = siluf(a2); o[3] = siluf(a3);
    }
    __syncthreads();

    for (int i = tid; i < 24576; i += 256) sWbuf[i] = W_node1[i];
    __syncthreads();
    for (int i = tid; i < nn * 16; i += 256) {
        int ln = i >> 4, j0 = (i & 15) * 4;
        float a0 = sBn1[j0], a1 = sBn1[j0 + 1], a2 = sBn1[j0 + 2], a3 = sBn1[j0 + 3];
        const float* hv2 = &sH[ln * 64];
        #pragma unroll 4
        for (int c = 0; c < 64; c++) {
            float hv = hv2[c];
            float4 w = *(const float4*)&sWbuf[c * 64 + j0];
            a0 += hv * w.x; a1 += hv * w.y; a2 += hv * w.z; a3 += hv * w.w;
        }
        const float* he = &sHE[ln * 256];
        #pragma unroll 4
        for (int c = 0; c < 256; c++) {
            float hv = he[c];
            float4 w = *(const float4*)&sWbuf[(64 + c) * 64 + j0];
            a0 += hv * w.x; a1 += hv * w.y; a2 += hv * w.z; a3 += hv * w.w;
        }
        const float* hc = &sHC[ln * 64];
        #pragma unroll 4
        for (int c = 0; c < 64; c++) {
            float hv = hc[c];
            float4 w = *(const float4*)&sWbuf[(320 + c) * 64 + j0];
            a0 += hv * w.x; a1 += hv * w.y; a2 += hv * w.z; a3 += hv * w.w;
        }
        float* o = &sT[ln * 64 + j0];
        o[0] = siluf(a0); o[1] = siluf(a1); o[2] = siluf(a2); o[3] = siluf(a3);
    }
    __syncthreads();

    for (int i = tid; i < 4096; i += 256) sWbuf[i] = W_node2[i];
    __syncthreads();
    for (int i = tid; i < nn * 16; i += 256) {
        int ln = i >> 4, j0 = (i & 15) * 4;
        float a0 = sBn2[j0], a1 = sBn2[j0 + 1], a2 = sBn2[j0 + 2], a3 = sBn2[j0 + 3];
        const float* tv = &sT[ln * 64];
        #pragma unroll 4
        for (int c = 0; c < 64; c++) {
            float hv = tv[c];
            float4 w = *(const float4*)&sWbuf[c * 64 + j0];
            a0 += hv * w.x; a1 += hv * w.y; a2 += hv * w.z; a3 += hv * w.w;
        }
        int n = n0 + ln;
        float h0 = sH[ln * 64 + j0]     + siluf(a0);
        float h1 = sH[ln * 64 + j0 + 1] + siluf(a1);
        float h2 = sH[ln * 64 + j0 + 2] + siluf(a2);
        float h3 = sH[ln * 64 + j0 + 3] + siluf(a3);
        float* o = &sHN[ln * 64 + j0];
        o[0] = h0; o[1] = h1; o[2] = h2; o[3] = h3;
        *(float4*)&out_h[n * 64 + j0] = make_float4(h0, h1, h2, h3);
    }
    __syncthreads();

    for (int i = tid; i < 4096; i += 256) sWbuf[i] = W_vel1[i];
    __syncthreads();
    for (int i = tid; i < nn * 16; i += 256) {
        int ln = i >> 4, j0 = (i & 15) * 4;
        float a0 = sBv1[j0], a1 = sBv1[j0 + 1], a2 = sBv1[j0 + 2], a3 = sBv1[j0 + 3];
        const float* hv2 = &sHN[ln * 64];
        #pragma unroll 4
        for (int c = 0; c < 64; c++) {
            float hv = hv2[c];
            float4 w = *(const float4*)&sWbuf[c * 64 + j0];
            a0 += hv * w.x; a1 += hv * w.y; a2 += hv * w.z; a3 += hv * w.w;
        }
        float* o = &sT[ln * 64 + j0];
        o[0] = siluf(a0) * sWv2[j0];
        o[1] = siluf(a1) * sWv2[j0 + 1];
        o[2] = siluf(a2) * sWv2[j0 + 2];
        o[3] = siluf(a3) * sWv2[j0 + 3];
    }
    __syncthreads();

    if (tid < nn) {
        int ln = tid;
        float s = 0.f;
        #pragma unroll 8
        for (int k = 0; k < 64; k++) s += sT[ln * 64 + k];
        float scale = 2.f / (1.f + __expf(-s));
        int n = n0 + ln;
        #pragma unroll
        for (int d = 0; d < 3; d++) {
            float vn = g_dv[n * 3 + d] + scale * v[n * 3 + d];
            out_v[n * 3 + d] = vn;
            out_x[n * 3 + d] = x[n * 3 + d] + vn;
        }
    }
}

// ---------------- launch ----------------
extern "C" void kernel_launch(void* const* d_in, const int* in_sizes, int n_in,
                              void* d_out, int out_size)
{
    const float* h        = (const float*)d_in[0];
    const float* x        = (const float*)d_in[1];
    const float* v        = (const float*)d_in[2];
    const int*   idxs     = (const int*)  d_in[3];
    const float* rbf_mean = (const float*)d_in[4];
    const float* rbf_beta = (const float*)d_in[5];
    const float* W_in     = (const float*)d_in[6];
    const float* b_in     = (const float*)d_in[7];
    const float* W_out1   = (const float*)d_in[8];
    const float* b_out1   = (const float*)d_in[9];
    const float* W_out2   = (const float*)d_in[10];
    const float* b_out2   = (const float*)d_in[11];
    const float* W_att    = (const float*)d_in[12];
    const float* b_att    = (const float*)d_in[13];
    const float* W_xmix   = (const float*)d_in[14];
    const float* W_post1  = (const float*)d_in[15];
    const float* b_post1  = (const float*)d_in[16];
    const float* W_post2  = (const float*)d_in[17];
    const float* b_post2  = (const float*)d_in[18];
    const float* W_node1  = (const float*)d_in[19];
    const float* b_node1  = (const float*)d_in[20];
    const float* W_node2  = (const float*)d_in[21];
    const float* b_node2  = (const float*)d_in[22];
    const float* W_vmix   = (const float*)d_in[23];
    const float* W_vel1   = (const float*)d_in[24];
    const float* b_vel1   = (const float*)d_in[25];
    const float* W_vel2   = (const float*)d_in[26];

    int N = in_sizes[0] / 64;
    int E = in_sizes[3] / 2;

    float* out  = (float*)d_out;
    float* outh = out;
    float* outx = out + (size_t)N * 64;
    float* outv = out + (size_t)N * 67;

    const int SM_NODE = (8192 * 2 + 2048 * 4 + 64 * 6 + 24576) * 4;

    cudaFuncSetAttribute(k_edge_mma, cudaFuncAttributeMaxDynamicSharedMemorySize, E_SMEM);
    cudaFuncSetAttribute(k_xagg,     cudaFuncAttributeMaxDynamicSharedMemorySize, XG_SMEM);
    cudaFuncSetAttribute(k_node,     cudaFuncAttributeMaxDynamicSharedMemorySize, SM_NODE);

    k_init<<<(N * 768 + 255) / 256, 256>>>(N, W_xmix, W_in, W_out1, W_out2);
    k_edge_mma<<<296, 256, E_SMEM>>>(h, x, idxs, rbf_mean, rbf_beta,
                                     b_in, b_out1, b_out2, W_att, b_att, E);
    k_scan<<<1, 1024>>>(N);
    k_fillexp<<<(E + 255) / 256, 256>>>(idxs, E);
    k_xagg<<<(E + 63) / 64, 256, XG_SMEM>>>(idxs, W_vmix, E);
    k_fin<<<N, 256>>>(W_vmix, N);
    k_node<<<(N + 31) / 32, 256, SM_NODE>>>(h, x, v,
                                            W_post1, b_post1, W_post2, b_post2,
                                            W_node1, b_node1, W_node2, b_node2,
                                            W_vel1, b_vel1, W_vel2,
                                            outh, outx, outv, N);
}

// round 9
// speedup vs baseline: 3.1361x; 1.0790x over previous
#include <cuda_runtime.h>
#include <cuda_fp16.h>
#include <stdint.h>
#include <math.h>

#define NMAX 10000
#define EMAX 160000
#define NBLK ((EMAX + 63) / 64)

// ---------------- scratch ----------------
__device__ float g_hemtx[EMAX * 64];
__device__ float g_xhat[EMAX * 3];
__device__ float g_w[EMAX * 4];
__device__ float g_nodemax[NMAX * 4];
__device__ float g_expsum[NMAX * 4];
__device__ int   g_counts[NMAX];
__device__ int   g_off[NMAX + 1];
__device__ int   g_cursor[NMAX];
__device__ int   g_eid[EMAX];
__device__ float g_he[NMAX * 256];
__device__ float g_cnorm[NMAX * 256];
__device__ float g_dv[NMAX * 3];
__device__ float g_phe[NBLK * 2 * 256];      // per-block boundary partials (no init needed)
__device__ float g_pcomb[NBLK * 2 * 3 * 256];
__device__ __half g_wx[256 * 256];           // W_xmix^T fp16 [n][k]
__device__ uint32_t g_ewi[4096];
__device__ uint32_t g_ew1a[4096];
__device__ uint32_t g_ew1b[2048];
__device__ uint32_t g_ew2[2048];

__device__ __forceinline__ float siluf(float x) { return x / (1.f + __expf(-x)); }
__device__ __forceinline__ float fast_tanh(float x) {
    float y; asm("tanh.approx.f32 %0, %1;" : "=f"(y) : "f"(x)); return y;
}
__device__ __forceinline__ void atomicMaxF(float* a, float v) {
    if (v >= 0.f) atomicMax((int*)a, __float_as_int(v));
    else          atomicMin((unsigned int*)a, (unsigned int)__float_as_int(v));
}
__device__ __forceinline__ void mma16816h(float* d, const uint32_t* a, const uint32_t* b) {
    asm volatile("mma.sync.aligned.m16n8k16.row.col.f32.f16.f16.f32 "
        "{%0,%1,%2,%3}, {%4,%5,%6,%7}, {%8,%9}, {%0,%1,%2,%3};"
        : "+f"(d[0]), "+f"(d[1]), "+f"(d[2]), "+f"(d[3])
        : "r"(a[0]), "r"(a[1]), "r"(a[2]), "r"(a[3]), "r"(b[0]), "r"(b[1]));
}
__device__ __forceinline__ uint32_t pack2h(float a, float b) {
    __half2 p = __floats2half2_rn(a, b);
    return *(uint32_t*)&p;
}
__device__ __forceinline__ uint32_t smem_u32(const void* p) {
    uint32_t a;
    asm("{ .reg .u64 t; cvta.to.shared.u64 t, %1; cvt.u32.u64 %0, t; }" : "=r"(a) : "l"(p));
    return a;
}
#define LDSM4(r0, r1, r2, r3, addr) \
    asm volatile("ldmatrix.sync.aligned.m8n8.x4.shared.b16 {%0,%1,%2,%3}, [%4];" \
        : "=r"(r0), "=r"(r1), "=r"(r2), "=r"(r3) : "r"(addr))

// ---------------- K0: init + weight prep (merged; only small arrays) ----------------
__global__ void k_init(int N,
                       const float* __restrict__ W_xmix,
                       const float* __restrict__ W_in,
                       const float* __restrict__ W_out1,
                       const float* __restrict__ W_out2) {
    int i = blockIdx.x * blockDim.x + threadIdx.x;
    if (i < N * 4) {
        g_nodemax[i] = __int_as_float(0xff800000);
        g_expsum[i]  = 0.f;
    }
    if (i < N) g_counts[i] = 0;
    if (i < 65536) {
        int n = i >> 8, k = i & 255;
        g_wx[n * 256 + k] = __float2half_rn(W_xmix[k * 256 + n]);
    }
    if (i < 4096) {
        int n = i >> 6, k0 = (i & 63) * 2;
        float w0 = (n < 50) ? W_in[k0 * 50 + n] : 0.f;
        float w1 = (n < 50) ? W_in[(k0 + 1) * 50 + n] : 0.f;
        g_ewi[i] = pack2h(w0, w1);
    } else if (i < 8192) {
        int j = i - 4096;
        int n = j >> 6, k0 = (j & 63) * 2;
        g_ew1a[j] = pack2h(W_out1[k0 * 64 + n], W_out1[(k0 + 1) * 64 + n]);
    } else if (i < 10240) {
        int j = i - 8192;
        int n = j >> 5, k0 = (j & 31) * 2;
        float w0 = (k0 < 50) ? W_out1[(128 + k0) * 64 + n] : ((k0 == 50) ? W_out1[178 * 64 + n] : 0.f);
        int k1 = k0 + 1;
        float w1 = (k1 < 50) ? W_out1[(128 + k1) * 64 + n] : ((k1 == 50) ? W_out1[178 * 64 + n] : 0.f);
        g_ew1b[j] = pack2h(w0, w1);
    } else if (i < 12288) {
        int j = i - 10240;
        int n = j >> 5, k0 = (j & 31) * 2;
        g_ew2[j] = pack2h(W_out2[k0 * 64 + n], W_out2[(k0 + 1) * 64 + n]);
    }
}

// ---------------- K1: edge MLP via fp16 mma.sync + ldmatrix ----------------
#define O_A     0
#define O_X     4352
#define O_M     6656
#define O_WI    8960
#define O_W1A   13312
#define O_W1B   17664
#define O_W2    19968
#define O_HE    22272
#define O_BIN   26496
#define O_BO1   26560
#define O_BO2   26624
#define O_MEAN  26688
#define O_BETA  26752
#define O_WA    26816
#define O_BA    27072
#define O_NORM  27076
#define O_EX    27140
#define O_XHT   27204
#define E_SMEM  (27400 * 4)

__global__ void __launch_bounds__(256, 2)
k_edge_mma(const float* __restrict__ h, const float* __restrict__ x,
           const int* __restrict__ idxs,
           const float* __restrict__ rbf_means, const float* __restrict__ rbf_betas,
           const float* __restrict__ b_in, const float* __restrict__ b_out1,
           const float* __restrict__ b_out2,
           const float* __restrict__ W_att, const float* __restrict__ b_att, int E)
{
    extern __shared__ uint32_t su[];
    float* sf = (float*)su;
    int tid = threadIdx.x, lid = tid & 31, wid = tid >> 5;
    int g = lid >> 2, tg = lid & 3;
    int mrow = (wid & 3) * 16, ncol = (wid >> 2) * 32;

    for (int i = tid; i < 4096; i += 256) {
        int n = i >> 6, kk = i & 63;
        su[O_WI  + n * 68 + kk] = g_ewi[i];
        su[O_W1A + n * 68 + kk] = g_ew1a[i];
    }
    for (int i = tid; i < 2048; i += 256) {
        int n = i >> 5, kk = i & 31;
        su[O_W1B + n * 36 + kk] = g_ew1b[i];
        su[O_W2  + n * 36 + kk] = g_ew2[i];
    }
    if (tid < 64) {
        sf[O_BIN + tid]  = (tid < 50) ? b_in[tid] : 0.f;
        sf[O_BO1 + tid]  = b_out1[tid];
        sf[O_BO2 + tid]  = b_out2[tid];
        sf[O_MEAN + tid] = (tid < 50) ? rbf_means[tid] : 0.f;
        sf[O_BETA + tid] = (tid < 50) ? rbf_betas[tid] : 1.f;
    }
    if (tid < 256) sf[O_WA + tid] = W_att[tid];
    if (tid < 4)   sf[O_BA + tid] = b_att[tid];
    __syncthreads();

    uint32_t sbase = smem_u32(su);
    int mq = lid >> 3, rr = lid & 7;
    int rA = mrow + (mq & 1) * 8 + rr;
    int cA = (mq >> 1) * 4;
    uint32_t adA  = sbase + (O_A  + rA * 68 + cA) * 4;
    uint32_t adX  = sbase + (O_X  + rA * 36 + cA) * 4;
    uint32_t adM  = sbase + (O_M  + rA * 36 + cA) * 4;
    int rB = (mq >> 1) * 8 + rr;
    int cB = (mq & 1) * 4;
    uint32_t adWI0  = sbase + (O_WI  + (ncol + rB) * 68 + cB) * 4;
    uint32_t adWI1  = sbase + (O_WI  + (ncol + 16 + rB) * 68 + cB) * 4;
    uint32_t adW1A0 = sbase + (O_W1A + (ncol + rB) * 68 + cB) * 4;
    uint32_t adW1A1 = sbase + (O_W1A + (ncol + 16 + rB) * 68 + cB) * 4;
    uint32_t adW1B0 = sbase + (O_W1B + (ncol + rB) * 36 + cB) * 4;
    uint32_t adW1B1 = sbase + (O_W1B + (ncol + 16 + rB) * 36 + cB) * 4;
    uint32_t adW20  = sbase + (O_W2  + (ncol + rB) * 36 + cB) * 4;
    uint32_t adW21  = sbase + (O_W2  + (ncol + 16 + rB) * 36 + cB) * 4;

    int ntiles = (E + 63) / 64;
    for (int tile = blockIdx.x; tile < ntiles; tile += gridDim.x) {
        int e0 = tile * 64, ne = min(64, E - e0);

        if (tid < 64) {
            float nrm = 0.f, xh0 = 0.f, xh1 = 0.f, xh2 = 0.f;
            if (tid < ne) {
                int s = idxs[2 * (e0 + tid)], d = idxs[2 * (e0 + tid) + 1];
                float dx = x[3 * s]     - x[3 * d];
                float dy = x[3 * s + 1] - x[3 * d + 1];
                float dz = x[3 * s + 2] - x[3 * d + 2];
                nrm = sqrtf(dx * dx + dy * dy + dz * dz + 1e-14f);
                float inv = 1.f / (nrm + 1e-5f);
                xh0 = dx * inv; xh1 = dy * inv; xh2 = dz * inv;
                atomicAdd(&g_counts[s], 1);
            }
            sf[O_NORM + tid] = nrm;
            sf[O_EX + tid]   = __expf(-nrm);
            sf[O_XHT + tid * 3] = xh0; sf[O_XHT + tid * 3 + 1] = xh1; sf[O_XHT + tid * 3 + 2] = xh2;
        }
        {
            int el = tid >> 2, part = tid & 3;
            uint32_t hb[16];
            if (el < ne) {
                int node = idxs[2 * (e0 + el) + (part >> 1)];
                const float4* hp = (const float4*)&h[node * 64 + (part & 1) * 32];
                #pragma unroll
                for (int i2 = 0; i2 < 8; i2++) {
                    float4 v = hp[i2];
                    hb[i2 * 2]     = pack2h(v.x, v.y);
                    hb[i2 * 2 + 1] = pack2h(v.z, v.w);
                }
            } else {
                #pragma unroll
                for (int i2 = 0; i2 < 16; i2++) hb[i2] = 0u;
            }
            uint4* dh = (uint4*)&su[O_A + el * 68 + part * 16];
            #pragma unroll
            for (int i2 = 0; i2 < 4; i2++)
                dh[i2] = make_uint4(hb[i2*4], hb[i2*4+1], hb[i2*4+2], hb[i2*4+3]);
        }
        __syncthreads();

        float acc[4][4];

        // ---- G1 ----
        #pragma unroll
        for (int nt = 0; nt < 4; nt++)
            #pragma unroll
            for (int q = 0; q < 4; q++) acc[nt][q] = 0.f;
        #pragma unroll
        for (int ks = 0; ks < 8; ks++) {
            uint32_t aH[4];
            LDSM4(aH[0], aH[1], aH[2], aH[3], adA + ks * 32);
            uint32_t b0, b1, b2, b3;
            LDSM4(b0, b1, b2, b3, adWI0 + ks * 32);
            { uint32_t bb[2] = { b0, b1 }; mma16816h(acc[0], aH, bb); }
            { uint32_t bb[2] = { b2, b3 }; mma16816h(acc[1], aH, bb); }
            LDSM4(b0, b1, b2, b3, adWI1 + ks * 32);
            { uint32_t bb[2] = { b0, b1 }; mma16816h(acc[2], aH, bb); }
            { uint32_t bb[2] = { b2, b3 }; mma16816h(acc[3], aH, bb); }
        }
        #pragma unroll
        for (int nt = 0; nt < 4; nt++) {
            #pragma unroll
            for (int hh = 0; hh < 2; hh++) {
                int row = mrow + g + hh * 8;
                int c0 = ncol + nt * 8 + tg * 2;
                float v0 = acc[nt][hh * 2]     + sf[O_BIN + c0];
                float v1 = acc[nt][hh * 2 + 1] + sf[O_BIN + c0 + 1];
                float ex = sf[O_EX + row];
                float x0, x1;
                if (c0 < 50) { float d = ex - sf[O_MEAN + c0]; x0 = __expf(-sf[O_BETA + c0] * d * d) * v0; }
                else x0 = (c0 == 50) ? sf[O_NORM + row] : 0.f;
                if (c0 + 1 < 50) { float d = ex - sf[O_MEAN + c0 + 1]; x1 = __expf(-sf[O_BETA + c0 + 1] * d * d) * v1; }
                else x1 = 0.f;
                su[O_X + row * 36 + (c0 >> 1)] = pack2h(x0, x1);
            }
        }
        __syncthreads();

        // ---- G2 ----
        #pragma unroll
        for (int nt = 0; nt < 4; nt++)
            #pragma unroll
            for (int q = 0; q < 4; q++) acc[nt][q] = 0.f;
        #pragma unroll
        for (int ks = 0; ks < 8; ks++) {
            uint32_t aH[4];
            LDSM4(aH[0], aH[1], aH[2], aH[3], adA + ks * 32);
            uint32_t b0, b1, b2, b3;
            LDSM4(b0, b1, b2, b3, adW1A0 + ks * 32);
            { uint32_t bb[2] = { b0, b1 }; mma16816h(acc[0], aH, bb); }
            { uint32_t bb[2] = { b2, b3 }; mma16816h(acc[1], aH, bb); }
            LDSM4(b0, b1, b2, b3, adW1A1 + ks * 32);
            { uint32_t bb[2] = { b0, b1 }; mma16816h(acc[2], aH, bb); }
            { uint32_t bb[2] = { b2, b3 }; mma16816h(acc[3], aH, bb); }
        }
        #pragma unroll
        for (int ks = 0; ks < 4; ks++) {
            uint32_t aH[4];
            LDSM4(aH[0], aH[1], aH[2], aH[3], adX + ks * 32);
            uint32_t b0, b1, b2, b3;
            LDSM4(b0, b1, b2, b3, adW1B0 + ks * 32);
            { uint32_t bb[2] = { b0, b1 }; mma16816h(acc[0], aH, bb); }
            { uint32_t bb[2] = { b2, b3 }; mma16816h(acc[1], aH, bb); }
            LDSM4(b0, b1, b2, b3, adW1B1 + ks * 32);
            { uint32_t bb[2] = { b0, b1 }; mma16816h(acc[2], aH, bb); }
            { uint32_t bb[2] = { b2, b3 }; mma16816h(acc[3], aH, bb); }
        }
        #pragma unroll
        for (int nt = 0; nt < 4; nt++) {
            #pragma unroll
            for (int hh = 0; hh < 2; hh++) {
                int row = mrow + g + hh * 8;
                int c0 = ncol + nt * 8 + tg * 2;
                float m0 = siluf(acc[nt][hh * 2]     + sf[O_BO1 + c0]);
                float m1 = siluf(acc[nt][hh * 2 + 1] + sf[O_BO1 + c0 + 1]);
                su[O_M + row * 36 + (c0 >> 1)] = pack2h(m0, m1);
            }
        }
        __syncthreads();

        // ---- G3 ----
        #pragma unroll
        for (int nt = 0; nt < 4; nt++)
            #pragma unroll
            for (int q = 0; q < 4; q++) acc[nt][q] = 0.f;
        #pragma unroll
        for (int ks = 0; ks < 4; ks++) {
            uint32_t aH[4];
            LDSM4(aH[0], aH[1], aH[2], aH[3], adM + ks * 32);
            uint32_t b0, b1, b2, b3;
            LDSM4(b0, b1, b2, b3, adW20 + ks * 32);
            { uint32_t bb[2] = { b0, b1 }; mma16816h(acc[0], aH, bb); }
            { uint32_t bb[2] = { b2, b3 }; mma16816h(acc[1], aH, bb); }
            LDSM4(b0, b1, b2, b3, adW21 + ks * 32);
            { uint32_t bb[2] = { b0, b1 }; mma16816h(acc[2], aH, bb); }
            { uint32_t bb[2] = { b2, b3 }; mma16816h(acc[3], aH, bb); }
        }
        #pragma unroll
        for (int nt = 0; nt < 4; nt++) {
            #pragma unroll
            for (int hh = 0; hh < 2; hh++) {
                int row = mrow + g + hh * 8;
                int c0 = ncol + nt * 8 + tg * 2;
                sf[O_HE + row * 66 + c0]     = acc[nt][hh * 2]     + sf[O_BO2 + c0];
                sf[O_HE + row * 66 + c0 + 1] = acc[nt][hh * 2 + 1] + sf[O_BO2 + c0 + 1];
            }
        }
        __syncthreads();

        {
            int el = tid >> 2, a = tid & 3;
            if (el < ne) {
                float acc2 = sf[O_BA + a];
                const float* hv = &sf[O_HE + el * 66];
                #pragma unroll 8
                for (int c = 0; c < 64; c++) acc2 += hv[c] * sf[O_WA + c * 4 + a];
                float lg = (acc2 > 0.f) ? acc2 : 2.f * (__expf(acc2 * 0.5f) - 1.f);
                int s = idxs[2 * (e0 + el)];
                g_w[(e0 + el) * 4 + a] = lg;
                atomicMaxF(&g_nodemax[s * 4 + a], lg);
            }
        }
        for (int i = tid; i < ne * 16; i += 256) {
            int el = i >> 4, c = (i & 15) * 4;
            float4 o = make_float4(sf[O_HE + el * 66 + c], sf[O_HE + el * 66 + c + 1],
                                   sf[O_HE + el * 66 + c + 2], sf[O_HE + el * 66 + c + 3]);
            *(float4*)&g_hemtx[(size_t)(e0 + el) * 64 + c] = o;
        }
        for (int i = tid; i < ne * 3; i += 256) g_xhat[e0 * 3 + i] = sf[O_XHT + i];
        __syncthreads();
    }
}

// ---------------- K2: exclusive scan ----------------
__global__ void k_scan(int N) {
    __shared__ int ssum[1024];
    int t = threadIdx.x;
    int chunk = (N + 1023) / 1024;
    int base = t * chunk;
    int vals[16];
    int loc = 0;
    for (int k = 0; k < chunk; k++) {
        int idx = base + k;
        int v = (idx < N) ? g_counts[idx] : 0;
        vals[k] = loc; loc += v;
    }
    ssum[t] = loc; __syncthreads();
    for (int off = 1; off < 1024; off <<= 1) {
        int v = (t >= off) ? ssum[t - off] : 0;
        __syncthreads();
        ssum[t] += v;
        __syncthreads();
    }
    int excl = ssum[t] - loc;
    for (int k = 0; k < chunk; k++) {
        int idx = base + k;
        if (idx < N) { g_off[idx] = excl + vals[k]; g_cursor[idx] = excl + vals[k]; }
    }
    if (t == 1023) g_off[N] = excl + loc;
}

// ---------------- K3: CSR fill + exp + expsum ----------------
__global__ void k_fillexp(const int* __restrict__ idxs, int E) {
    int e = blockIdx.x * blockDim.x + threadIdx.x;
    if (e >= E) return;
    int s = idxs[2 * e];
    int p = atomicAdd(&g_cursor[s], 1);
    g_eid[p] = e;
    #pragma unroll
    for (int a = 0; a < 4; a++) {
        float w = __expf(g_w[e * 4 + a] - g_nodemax[s * 4 + a]);
        g_w[e * 4 + a] = w;
        atomicAdd(&g_expsum[s * 4 + a], w);
    }
}

// ---------------- K5: fused xmix GEMM + per-node aggregation ----------------
#define XG_A    0
#define XG_W    8448
#define XG_HM   17664
#define XG_ATT  21952
#define XG_XH   22208
#define XG_NODE 22400
#define XG_WV   22464
#define XG_RED  22720
#define XG_SMEM (22744 * 4)

__global__ void __launch_bounds__(256, 2)
k_xagg(const int* __restrict__ idxs, const float* __restrict__ W_vmix, int E)
{
    extern __shared__ uint32_t su[];
    float* sf = (float*)su;
    int tid = threadIdx.x, lid = tid & 31, wid = tid >> 5;
    int p0 = blockIdx.x * 64;
    uint32_t* pA = su + XG_A;
    uint32_t* pW = su + XG_W;
    int* sN = (int*)(su + XG_NODE);

    {
        int sl = tid & 63, kq = tid >> 6;
        int e = -1, s = -1;
        float att[4], hm[16];
        int p = p0 + sl;
        if (p < E) {
            e = g_eid[p];
            s = idxs[2 * e];
            #pragma unroll
            for (int a = 0; a < 4; a++) att[a] = g_w[e * 4 + a] / g_expsum[s * 4 + a];
            const float4* hp = (const float4*)&g_hemtx[(size_t)e * 64 + kq * 16];
            #pragma unroll
            for (int i = 0; i < 4; i++) {
                float4 v = hp[i];
                hm[i * 4] = v.x; hm[i * 4 + 1] = v.y; hm[i * 4 + 2] = v.z; hm[i * 4 + 3] = v.w;
            }
        } else {
            #pragma unroll
            for (int a = 0; a < 4; a++) att[a] = 0.f;
            #pragma unroll
            for (int i = 0; i < 16; i++) hm[i] = 0.f;
        }
        if (kq == 0) {
            sN[sl] = s;
            #pragma unroll
            for (int a = 0; a < 4; a++) sf[XG_ATT + sl * 4 + a] = att[a];
            float x0 = 0.f, x1 = 0.f, x2 = 0.f;
            if (e >= 0) { x0 = g_xhat[e * 3]; x1 = g_xhat[e * 3 + 1]; x2 = g_xhat[e * 3 + 2]; }
            sf[XG_XH + sl * 3] = x0; sf[XG_XH + sl * 3 + 1] = x1; sf[XG_XH + sl * 3 + 2] = x2;
        }
        #pragma unroll
        for (int i = 0; i < 16; i++) sf[XG_HM + sl * 67 + kq * 16 + i] = hm[i];
        #pragma unroll
        for (int j = 0; j < 32; j++) {
            int kl = 2 * j;
            float m = hm[kl >> 2];
            pA[sl * 132 + ((kq * 64 + kl) >> 1)] = pack2h(m * att[kl & 3], m * att[(kl + 1) & 3]);
        }
        sf[XG_WV + tid] = W_vmix[tid];
    }

    int g = lid >> 2, tg = lid & 3;
    int mrow = (wid & 1) * 32;
    int ncol = (wid >> 1) * 64;

    uint32_t sbase = smem_u32(su);
    int mq = lid >> 3, rr = lid & 7;
    uint32_t adA0 = sbase + (XG_A + (mrow + (mq & 1) * 8 + rr) * 132 + (mq >> 1) * 4) * 4;
    uint32_t adA1 = adA0 + 16 * 132 * 4;
    int rB = (mq >> 1) * 8 + rr;
    int cB = (mq & 1) * 4;
    uint32_t adW0 = sbase + (XG_W + (ncol + rB) * 36 + cB) * 4;
    uint32_t adW1 = adW0 + 16 * 36 * 4;
    uint32_t adW2 = adW0 + 32 * 36 * 4;
    uint32_t adW3 = adW0 + 48 * 36 * 4;

    float acc[2][8][4];
    #pragma unroll
    for (int mt = 0; mt < 2; mt++)
        #pragma unroll
        for (int nt = 0; nt < 8; nt++)
            #pragma unroll
            for (int q = 0; q < 4; q++) acc[mt][nt][q] = 0.f;

    for (int kc = 0; kc < 4; kc++) {
        __syncthreads();
        {
            int n = tid;
            const uint4* src = (const uint4*)&g_wx[n * 256 + kc * 64];
            uint4* dst = (uint4*)(pW + n * 36);
            #pragma unroll
            for (int i = 0; i < 8; i++) dst[i] = src[i];
        }
        __syncthreads();

        #pragma unroll
        for (int ks = 0; ks < 4; ks++) {
            uint32_t aoff = kc * 128 + ks * 32;
            uint32_t aH[2][4];
            LDSM4(aH[0][0], aH[0][1], aH[0][2], aH[0][3], adA0 + aoff);
            LDSM4(aH[1][0], aH[1][1], aH[1][2], aH[1][3], adA1 + aoff);
            uint32_t woff = ks * 32;
            uint32_t b0, b1, b2, b3;
            #define XAGG_PAIR(ADDR, NT) \
                LDSM4(b0, b1, b2, b3, (ADDR) + woff); \
                { uint32_t bb[2] = { b0, b1 }; mma16816h(acc[0][NT], aH[0], bb); mma16816h(acc[1][NT], aH[1], bb); } \
                { uint32_t bb[2] = { b2, b3 }; mma16816h(acc[0][(NT)+1], aH[0], bb); mma16816h(acc[1][(NT)+1], aH[1], bb); }
            XAGG_PAIR(adW0, 0)
            XAGG_PAIR(adW1, 2)
            XAGG_PAIR(adW2, 4)
            XAGG_PAIR(adW3, 6)
            #undef XAGG_PAIR
        }
    }

    __syncthreads();
    #pragma unroll
    for (int mt = 0; mt < 2; mt++)
        #pragma unroll
        for (int nt = 0; nt < 8; nt++) {
            int rl = mrow + mt * 16 + g;
            int col = ncol + nt * 8 + tg * 2;
            float* a = acc[mt][nt];
            pA[rl * 132 + (col >> 1)]       = pack2h(fast_tanh(a[0]), fast_tanh(a[1]));
            pA[(rl + 8) * 132 + (col >> 1)] = pack2h(fast_tanh(a[2]), fast_tanh(a[3]));
        }
    __syncthreads();

    // ---- segmented per-node reduction; boundary -> deterministic staging ----
    {
        int c = tid;
        int blk = blockIdx.x;
        float wv = sf[XG_WV + c];
        float accH = 0.f, a0 = 0.f, a1 = 0.f, a2 = 0.f;
        int segStart = 0;
        for (int sl = 0; sl < 64; sl++) {
            int n = sN[sl];
            if (n >= 0) {
                float A32 = sf[XG_HM + sl * 67 + (c >> 2)] * sf[XG_ATT + sl * 4 + (c & 3)];
                accH += A32;
                uint32_t cp = pA[sl * 132 + (c >> 1)];
                __half2 h2 = *(__half2*)&cp;
                float cf = (c & 1) ? __high2float(h2) : __low2float(h2);
                a0 += cf * sf[XG_XH + sl * 3];
                a1 += cf * sf[XG_XH + sl * 3 + 1];
                a2 += cf * sf[XG_XH + sl * 3 + 2];
            }
            bool segEnd = (sl == 63) || (sN[sl + 1] != n);
            if (segEnd) {
                if (n >= 0) {
                    int beg = g_off[n], end = g_off[n + 1];
                    bool full = (beg == p0 + segStart) && (end == p0 + sl + 1);
                    if (full) {
                        float invc = 1.f / ((float)(end - beg) + 1.f);
                        g_he[n * 256 + c] = accH;
                        float s0 = a0 * invc, s1 = a1 * invc, s2 = a2 * invc;
                        g_cnorm[n * 256 + c] = s0 * s0 + s1 * s1 + s2 * s2;
                        float r0 = wv * s0, r1 = wv * s1, r2 = wv * s2;
                        #pragma unroll
                        for (int o = 16; o > 0; o >>= 1) {
                            r0 += __shfl_xor_sync(0xFFFFFFFFu, r0, o);
                            r1 += __shfl_xor_sync(0xFFFFFFFFu, r1, o);
                            r2 += __shfl_xor_sync(0xFFFFFFFFu, r2, o);
                        }
                        if (lid == 0) {
                            sf[XG_RED + wid * 3]     = r0;
                            sf[XG_RED + wid * 3 + 1] = r1;
                            sf[XG_RED + wid * 3 + 2] = r2;
                        }
                        __syncthreads();
                        if (c < 3) {
                            float s = 0.f;
                            #pragma unroll
                            for (int w = 0; w < 8; w++) s += sf[XG_RED + w * 3 + c];
                            g_dv[n * 3 + c] = s;
                        }
                        __syncthreads();
                    } else {
                        int slot = (segStart == 0) ? 0 : 1;
                        g_phe[((size_t)blk * 2 + slot) * 256 + c] = accH;
                        g_pcomb[(((size_t)blk * 2 + slot) * 3 + 0) * 256 + c] = a0;
                        g_pcomb[(((size_t)blk * 2 + slot) * 3 + 1) * 256 + c] = a1;
                        g_pcomb[(((size_t)blk * 2 + slot) * 3 + 2) * 256 + c] = a2;
                    }
                }
                accH = 0.f; a0 = 0.f; a1 = 0.f; a2 = 0.f;
                segStart = sl + 1;
            }
        }
    }
}

// ---------------- K_fin: finish boundary + empty nodes ----------------
__global__ void k_fin(const float* __restrict__ W_vmix, int N) {
    __shared__ float red[24];
    int n = blockIdx.x;
    int c = threadIdx.x, lid = c & 31, wid = c >> 5;
    int beg = g_off[n], end = g_off[n + 1];
    if (end == beg) {   // empty node
        g_he[n * 256 + c] = 0.f;
        g_cnorm[n * 256 + c] = 0.f;
        if (c < 3) g_dv[n * 3 + c] = 0.f;
        return;
    }
    int b0 = beg >> 6, b1 = (end - 1) >> 6;
    if (b0 == b1) return;   // fully handled in k_xagg

    float accH = 0.f, a0 = 0.f, a1 = 0.f, a2 = 0.f;
    for (int b = b0; b <= b1; b++) {
        int slot = (b == b0 && (beg & 63) != 0) ? 1 : 0;
        size_t base = ((size_t)b * 2 + slot);
        accH += g_phe[base * 256 + c];
        a0 += g_pcomb[(base * 3 + 0) * 256 + c];
        a1 += g_pcomb[(base * 3 + 1) * 256 + c];
        a2 += g_pcomb[(base * 3 + 2) * 256 + c];
    }
    g_he[n * 256 + c] = accH;
    float invc = 1.f / ((float)(end - beg) + 1.f);
    float s0 = a0 * invc, s1 = a1 * invc, s2 = a2 * invc;
    g_cnorm[n * 256 + c] = s0 * s0 + s1 * s1 + s2 * s2;
    float wv = W_vmix[c];
    float r0 = wv * s0, r1 = wv * s1, r2 = wv * s2;
    #pragma unroll
    for (int o = 16; o > 0; o >>= 1) {
        r0 += __shfl_xor_sync(0xFFFFFFFFu, r0, o);
        r1 += __shfl_xor_sync(0xFFFFFFFFu, r1, o);
        r2 += __shfl_xor_sync(0xFFFFFFFFu, r2, o);
    }
    if (lid == 0) { red[wid * 3] = r0; red[wid * 3 + 1] = r1; red[wid * 3 + 2] = r2; }
    __syncthreads();
    if (c < 3) {
        float s = 0.f;
        #pragma unroll
        for (int w = 0; w < 8; w++) s += red[w * 3 + c];
        g_dv[n * 3 + c] = s;
    }
}

// ---------------- K7: node MLPs (2-row x 4-col register blocking) ----------------
__global__ void k_node(const float* __restrict__ h, const float* __restrict__ x,
                       const float* __restrict__ v,
                       const float* __restrict__ W_post1, const float* __restrict__ b_post1,
                       const float* __restrict__ W_post2, const float* __restrict__ b_post2,
                       const float* __restrict__ W_node1, const float* __restrict__ b_node1,
                       const float* __restrict__ W_node2, const float* __restrict__ b_node2,
                       const float* __restrict__ W_vel1,  const float* __restrict__ b_vel1,
                       const float* __restrict__ W_vel2,
                       float* __restrict__ out_h, float* __restrict__ out_x,
                       float* __restrict__ out_v, int N)
{
    extern __shared__ float sm[];
    float* sCN = sm;
    float* sHE = sCN + 8192;
    float* sH  = sHE + 8192;
    float* sT  = sH  + 2048;
    float* sHC = sT  + 2048;
    float* sHN = sHC + 2048;
    float* sBp1 = sHN + 2048;
    float* sBp2 = sBp1 + 64;
    float* sBn1 = sBp2 + 64;
    float* sBn2 = sBn1 + 64;
    float* sBv1 = sBn2 + 64;
    float* sWv2 = sBv1 + 64;
    float* sWbuf = sWv2 + 64;

    int tid = threadIdx.x;
    int n0 = blockIdx.x * 32;
    int nn = min(32, N - n0);

    for (int i = tid; i < 8192; i += 256) {
        sCN[i] = (i < nn * 256) ? g_cnorm[n0 * 256 + i] : 0.f;
        sHE[i] = (i < nn * 256) ? g_he[n0 * 256 + i] : 0.f;
    }
    for (int i = tid; i < 2048; i += 256) sH[i] = (i < nn * 64) ? h[n0 * 64 + i] : 0.f;
    if (tid < 64) {
        sBp1[tid] = b_post1[tid]; sBp2[tid] = b_post2[tid];
        sBn1[tid] = b_node1[tid]; sBn2[tid] = b_node2[tid];
        sBv1[tid] = b_vel1[tid];  sWv2[tid] = W_vel2[tid];
    }
    __syncthreads();

    int gq = tid >> 4;          // node pair 0..15
    int j0 = (tid & 15) * 4;
    int ln0 = gq * 2, ln1 = ln0 + 1;

    // stage 1: t1 = silu(cnorm @ W_post1 + b)  K=256
    for (int i = tid; i < 16384; i += 256) sWbuf[i] = W_post1[i];
    __syncthreads();
    {
        float A0[4] = { sBp1[j0], sBp1[j0+1], sBp1[j0+2], sBp1[j0+3] };
        float A1[4] = { A0[0], A0[1], A0[2], A0[3] };
        const float* c0p = &sCN[ln0 * 256];
        const float* c1p = &sCN[ln1 * 256];
        #pragma unroll 4
        for (int c = 0; c < 256; c++) {
            float4 w = *(const float4*)&sWbuf[c * 64 + j0];
            float h0 = c0p[c], h1 = c1p[c];
            A0[0] += h0 * w.x; A0[1] += h0 * w.y; A0[2] += h0 * w.z; A0[3] += h0 * w.w;
            A1[0] += h1 * w.x; A1[1] += h1 * w.y; A1[2] += h1 * w.z; A1[3] += h1 * w.w;
        }
        float* o0 = &sT[ln0 * 64 + j0];
        float* o1 = &sT[ln1 * 64 + j0];
        o0[0] = siluf(A0[0]); o0[1] = siluf(A0[1]); o0[2] = siluf(A0[2]); o0[3] = siluf(A0[3]);
        o1[0] = siluf(A1[0]); o1[1] = siluf(A1[1]); o1[2] = siluf(A1[2]); o1[3] = siluf(A1[3]);
    }
    __syncthreads();

    // stage 2: h_comb = silu(t1 @ W_post2 + b)  K=64
    for (int i = tid; i < 4096; i += 256) sWbuf[i] = W_post2[i];
    __syncthreads();
    {
        float A0[4] = { sBp2[j0], sBp2[j0+1], sBp2[j0+2], sBp2[j0+3] };
        float A1[4] = { A0[0], A0[1], A0[2], A0[3] };
        const float* t0p = &sT[ln0 * 64];
        const float* t1p = &sT[ln1 * 64];
        #pragma unroll 4
        for (int c = 0; c < 64; c++) {
            float4 w = *(const float4*)&sWbuf[c * 64 + j0];
            float h0 = t0p[c], h1 = t1p[c];
            A0[0] += h0 * w.x; A0[1] += h0 * w.y; A0[2] += h0 * w.z; A0[3] += h0 * w.w;
            A1[0] += h1 * w.x; A1[1] += h1 * w.y; A1[2] += h1 * w.z; A1[3] += h1 * w.w;
        }
        float* o0 = &sHC[ln0 * 64 + j0];
        float* o1 = &sHC[ln1 * 64 + j0];
        o0[0] = siluf(A0[0]); o0[1] = siluf(A0[1]); o0[2] = siluf(A0[2]); o0[3] = siluf(A0[3]);
        o1[0] = siluf(A1[0]); o1[1] = siluf(A1[1]); o1[2] = siluf(A1[2]); o1[3] = siluf(A1[3]);
    }
    __syncthreads();

    // stage 3: t2 = silu([h, h_e, h_comb] @ W_node1 + b)  K=384
    for (int i = tid; i < 24576; i += 256) sWbuf[i] = W_node1[i];
    __syncthreads();
    {
        float A0[4] = { sBn1[j0], sBn1[j0+1], sBn1[j0+2], sBn1[j0+3] };
        float A1[4] = { A0[0], A0[1], A0[2], A0[3] };
        const float* h0p = &sH[ln0 * 64];
        const float* h1p = &sH[ln1 * 64];
        #pragma unroll 4
        for (int c = 0; c < 64; c++) {
            float4 w = *(const float4*)&sWbuf[c * 64 + j0];
            float h0 = h0p[c], h1 = h1p[c];
            A0[0] += h0 * w.x; A0[1] += h0 * w.y; A0[2] += h0 * w.z; A0[3] += h0 * w.w;
            A1[0] += h1 * w.x; A1[1] += h1 * w.y; A1[2] += h1 * w.z; A1[3] += h1 * w.w;
        }
        const float* e0p = &sHE[ln0 * 256];
        const float* e1p = &sHE[ln1 * 256];
        #pragma unroll 4
        for (int c = 0; c < 256; c++) {
            float4 w = *(const float4*)&sWbuf[(64 + c) * 64 + j0];
            float h0 = e0p[c], h1 = e1p[c];
            A0[0] += h0 * w.x; A0[1] += h0 * w.y; A0[2] += h0 * w.z; A0[3] += h0 * w.w;
            A1[0] += h1 * w.x; A1[1] += h1 * w.y; A1[2] += h1 * w.z; A1[3] += h1 * w.w;
        }
        const float* q0p = &sHC[ln0 * 64];
        const float* q1p = &sHC[ln1 * 64];
        #pragma unroll 4
        for (int c = 0; c < 64; c++) {
            float4 w = *(const float4*)&sWbuf[(320 + c) * 64 + j0];
            float h0 = q0p[c], h1 = q1p[c];
            A0[0] += h0 * w.x; A0[1] += h0 * w.y; A0[2] += h0 * w.z; A0[3] += h0 * w.w;
            A1[0] += h1 * w.x; A1[1] += h1 * w.y; A1[2] += h1 * w.z; A1[3] += h1 * w.w;
        }
        float* o0 = &sT[ln0 * 64 + j0];
        float* o1 = &sT[ln1 * 64 + j0];
        o0[0] = siluf(A0[0]); o0[1] = siluf(A0[1]); o0[2] = siluf(A0[2]); o0[3] = siluf(A0[3]);
        o1[0] = siluf(A1[0]); o1[1] = siluf(A1[1]); o1[2] = siluf(A1[2]); o1[3] = siluf(A1[3]);
    }
    __syncthreads();

    // stage 4: h_new = h + silu(t2 @ W_node2 + b)  K=64
    for (int i = tid; i < 4096; i += 256) sWbuf[i] = W_node2[i];
    __syncthreads();
    {
        float A0[4] = { sBn2[j0], sBn2[j0+1], sBn2[j0+2], sBn2[j0+3] };
        float A1[4] = { A0[0], A0[1], A0[2], A0[3] };
        const float* t0p = &sT[ln0 * 64];
        const float* t1p = &sT[ln1 * 64];
        #pragma unroll 4
        for (int c = 0; c < 64; c++) {
            float4 w = *(const float4*)&sWbuf[c * 64 + j0];
            float h0 = t0p[c], h1 = t1p[c];
            A0[0] += h0 * w.x; A0[1] += h0 * w.y; A0[2] += h0 * w.z; A0[3] += h0 * w.w;
            A1[0] += h1 * w.x; A1[1] += h1 * w.y; A1[2] += h1 * w.z; A1[3] += h1 * w.w;
        }
        float r0[4], r1[4];
        #pragma unroll
        for (int q = 0; q < 4; q++) {
            r0[q] = sH[ln0 * 64 + j0 + q] + siluf(A0[q]);
            r1[q] = sH[ln1 * 64 + j0 + q] + siluf(A1[q]);
        }
        float* o0 = &sHN[ln0 * 64 + j0];
        float* o1 = &sHN[ln1 * 64 + j0];
        #pragma unroll
        for (int q = 0; q < 4; q++) { o0[q] = r0[q]; o1[q] = r1[q]; }
        if (ln0 < nn) *(float4*)&out_h[(n0 + ln0) * 64 + j0] = make_float4(r0[0], r0[1], r0[2], r0[3]);
        if (ln1 < nn) *(float4*)&out_h[(n0 + ln1) * 64 + j0] = make_float4(r1[0], r1[1], r1[2], r1[3]);
    }
    __syncthreads();

    // stage 5: t3 = silu(h_new @ W_vel1 + b) * W_vel2
    for (int i = tid; i < 4096; i += 256) sWbuf[i] = W_vel1[i];
    __syncthreads();
    {
        float A0[4] = { sBv1[j0], sBv1[j0+1], sBv1[j0+2], sBv1[j0+3] };
        float A1[4] = { A0[0], A0[1], A0[2], A0[3] };
        const float* n0p = &sHN[ln0 * 64];
        const float* n1p = &sHN[ln1 * 64];
        #pragma unroll 4
        for (int c = 0; c < 64; c++) {
            float4 w = *(const float4*)&sWbuf[c * 64 + j0];
            float h0 = n0p[c], h1 = n1p[c];
            A0[0] += h0 * w.x; A0[1] += h0 * w.y; A0[2] += h0 * w.z; A0[3] += h0 * w.w;
            A1[0] += h1 * w.x; A1[1] += h1 * w.y; A1[2] += h1 * w.z; A1[3] += h1 * w.w;
        }
        float* o0 = &sT[ln0 * 64 + j0];
        float* o1 = &sT[ln1 * 64 + j0];
        #pragma unroll
        for (int q = 0; q < 4; q++) {
            o0[q] = siluf(A0[q]) * sWv2[j0 + q];
            o1[q] = siluf(A1[q]) * sWv2[j0 + q];
        }
    }
    __syncthreads();

    if (tid < nn) {
        int ln = tid;
        float s = 0.f;
        #pragma unroll 8
        for (int k = 0; k < 64; k++) s += sT[ln * 64 + k];
        float scale = 2.f / (1.f + __expf(-s));
        int n = n0 + ln;
        #pragma unroll
        for (int d = 0; d < 3; d++) {
            float vn = g_dv[n * 3 + d] + scale * v[n * 3 + d];
            out_v[n * 3 + d] = vn;
            out_x[n * 3 + d] = x[n * 3 + d] + vn;
        }
    }
}

// ---------------- launch ----------------
extern "C" void kernel_launch(void* const* d_in, const int* in_sizes, int n_in,
                              void* d_out, int out_size)
{
    const float* h        = (const float*)d_in[0];
    const float* x        = (const float*)d_in[1];
    const float* v        = (const float*)d_in[2];
    const int*   idxs     = (const int*)  d_in[3];
    const float* rbf_mean = (const float*)d_in[4];
    const float* rbf_beta = (const float*)d_in[5];
    const float* W_in     = (const float*)d_in[6];
    const float* b_in     = (const float*)d_in[7];
    const float* W_out1   = (const float*)d_in[8];
    const float* b_out1   = (const float*)d_in[9];
    const float* W_out2   = (const float*)d_in[10];
    const float* b_out2   = (const float*)d_in[11];
    const float* W_att    = (const float*)d_in[12];
    const float* b_att    = (const float*)d_in[13];
    const float* W_xmix   = (const float*)d_in[14];
    const float* W_post1  = (const float*)d_in[15];
    const float* b_post1  = (const float*)d_in[16];
    const float* W_post2  = (const float*)d_in[17];
    const float* b_post2  = (const float*)d_in[18];
    const float* W_node1  = (const float*)d_in[19];
    const float* b_node1  = (const float*)d_in[20];
    const float* W_node2  = (const float*)d_in[21];
    const float* b_node2  = (const float*)d_in[22];
    const float* W_vmix   = (const float*)d_in[23];
    const float* W_vel1   = (const float*)d_in[24];
    const float* b_vel1   = (const float*)d_in[25];
    const float* W_vel2   = (const float*)d_in[26];

    int N = in_sizes[0] / 64;
    int E = in_sizes[3] / 2;

    float* out  = (float*)d_out;
    float* outh = out;
    float* outx = out + (size_t)N * 64;
    float* outv = out + (size_t)N * 67;

    const int SM_NODE = (8192 * 2 + 2048 * 4 + 64 * 6 + 24576) * 4;

    cudaFuncSetAttribute(k_edge_mma, cudaFuncAttributeMaxDynamicSharedMemorySize, E_SMEM);
    cudaFuncSetAttribute(k_xagg,     cudaFuncAttributeMaxDynamicSharedMemorySize, XG_SMEM);
    cudaFuncSetAttribute(k_node,     cudaFuncAttributeMaxDynamicSharedMemorySize, SM_NODE);

    k_init<<<256, 256>>>(N, W_xmix, W_in, W_out1, W_out2);
    k_edge_mma<<<296, 256, E_SMEM>>>(h, x, idxs, rbf_mean, rbf_beta,
                                     b_in, b_out1, b_out2, W_att, b_att, E);
    k_scan<<<1, 1024>>>(N);
    k_fillexp<<<(E + 255) / 256, 256>>>(idxs, E);
    k_xagg<<<(E + 63) / 64, 256, XG_SMEM>>>(idxs, W_vmix, E);
    k_fin<<<N, 256>>>(W_vmix, N);
    k_node<<<(N + 31) / 32, 256, SM_NODE>>>(h, x, v,
                                            W_post1, b_post1, W_post2, b_post2,
                                            W_node1, b_node1, W_node2, b_node2,
                                            W_vel1, b_vel1, W_vel2,
                                            outh, outx, outv, N);
}